// round 1
// baseline (speedup 1.0000x reference)
#include <cuda_runtime.h>

#define DEV_INLINE __device__ __forceinline__

// Problem constants
constexpr int cB  = 8;
constexpr int cNW = 1024;
constexpr int cWL = 8;
constexpr int cCH = 4;
constexpr int cD  = 512;
constexpr int cH  = 8;
constexpr int cL  = 4;
constexpr int cFF = 2048;
constexpr int cK  = 512;
constexpr int cT  = cB * cNW;        // 8192 tokens
constexpr int cDH = cD / cH;         // 64
constexpr float cSCALE = 0.125f;     // (D/H)^-0.5

// ---------------------------------------------------------------------------
// Scratch (device globals: allocation-free per harness rules)
// ---------------------------------------------------------------------------
__device__ float g_x   [cT * cD];          // residual stream (16 MB)
__device__ float g_h   [cT * cD];          // LN output       (16 MB)
__device__ float g_qkv [cT * 3 * cD];      // qkv             (48 MB)
__device__ float g_sc  [67108864];         // attn scores 8*8*1024*1024 (256 MB)
__device__ float g_ao  [cT * cD];          // attn out        (16 MB)
__device__ float g_ff  [cT * cFF];         // ffn hidden      (64 MB)
__device__ int   g_mflag[cT];

// ---------------------------------------------------------------------------
// Helpers
// ---------------------------------------------------------------------------
DEV_INLINE float gelu_f(float x) {
    return 0.5f * x * (1.0f + tanhf(0.7978845608028654f * (x + 0.044715f * x * x * x)));
}

template<int NWARPS>
DEV_INLINE void block_sum2(float& s, float& s2) {
    #pragma unroll
    for (int o = 16; o > 0; o >>= 1) {
        s  += __shfl_down_sync(0xffffffffu, s,  o);
        s2 += __shfl_down_sync(0xffffffffu, s2, o);
    }
    __shared__ float sh_a[NWARPS], sh_b[NWARPS];
    int w = threadIdx.x >> 5;
    if ((threadIdx.x & 31) == 0) { sh_a[w] = s; sh_b[w] = s2; }
    __syncthreads();
    if (threadIdx.x == 0) {
        float a = sh_a[0], b = sh_b[0];
        #pragma unroll
        for (int i = 1; i < NWARPS; i++) { a += sh_a[i]; b += sh_b[i]; }
        sh_a[0] = a; sh_b[0] = b;
    }
    __syncthreads();
    s = sh_a[0]; s2 = sh_b[0];
}

template<int NWARPS>
DEV_INLINE float block_max(float v) {
    #pragma unroll
    for (int o = 16; o > 0; o >>= 1)
        v = fmaxf(v, __shfl_down_sync(0xffffffffu, v, o));
    __shared__ float sh_m[NWARPS];
    int w = threadIdx.x >> 5;
    if ((threadIdx.x & 31) == 0) sh_m[w] = v;
    __syncthreads();
    if (threadIdx.x == 0) {
        float a = sh_m[0];
        #pragma unroll
        for (int i = 1; i < NWARPS; i++) a = fmaxf(a, sh_m[i]);
        sh_m[0] = a;
    }
    __syncthreads();
    return sh_m[0];
}

template<int NWARPS>
DEV_INLINE float block_sum1(float v) {
    #pragma unroll
    for (int o = 16; o > 0; o >>= 1)
        v += __shfl_down_sync(0xffffffffu, v, o);
    __shared__ float sh_s[NWARPS];
    int w = threadIdx.x >> 5;
    if ((threadIdx.x & 31) == 0) sh_s[w] = v;
    __syncthreads();
    if (threadIdx.x == 0) {
        float a = sh_s[0];
        #pragma unroll
        for (int i = 1; i < NWARPS; i++) a += sh_s[i];
        sh_s[0] = a;
    }
    __syncthreads();
    return sh_s[0];
}

#define ACC44(aa, bb, acc) do {                                                          \
    acc[0][0] += aa.x*bb.x; acc[0][1] += aa.x*bb.y; acc[0][2] += aa.x*bb.z; acc[0][3] += aa.x*bb.w; \
    acc[1][0] += aa.y*bb.x; acc[1][1] += aa.y*bb.y; acc[1][2] += aa.y*bb.z; acc[1][3] += aa.y*bb.w; \
    acc[2][0] += aa.z*bb.x; acc[2][1] += aa.z*bb.y; acc[2][2] += aa.z*bb.z; acc[2][3] += aa.z*bb.w; \
    acc[3][0] += aa.w*bb.x; acc[3][1] += aa.w*bb.y; acc[3][2] += aa.w*bb.z; acc[3][3] += aa.w*bb.w; \
} while (0)

// ---------------------------------------------------------------------------
// Mask flags
// ---------------------------------------------------------------------------
__global__ void k_zeroflags() {
    int i = blockIdx.x * blockDim.x + threadIdx.x;
    if (i < cT) g_mflag[i] = 0;
}

__global__ void k_setflags(const int* __restrict__ mask_idx) {
    int i = blockIdx.x * blockDim.x + threadIdx.x;
    if (i < cB * cK) {
        int b = i / cK;
        int w = mask_idx[i];
        g_mflag[b * cNW + w] = 1;
    }
}

// ---------------------------------------------------------------------------
// Embedding: words -> tokens (LN1, W_emb, LN2, +pos, mask replace)
// 1 block / token, 128 threads
// ---------------------------------------------------------------------------
__global__ void __launch_bounds__(128) k_embed(
    const float* __restrict__ seq, const float* __restrict__ pos_emb,
    const float* __restrict__ mtok,
    const float* __restrict__ p1g, const float* __restrict__ p1b,
    const float* __restrict__ W_emb, const float* __restrict__ b_emb,
    const float* __restrict__ p2g, const float* __restrict__ p2b)
{
    int tok = blockIdx.x;
    int w = tok & (cNW - 1);
    int t = threadIdx.x;
    const float* pos = pos_emb + (size_t)(w + 1) * cD;
    float* out = g_x + (size_t)tok * cD;

    if (g_mflag[tok]) {
        #pragma unroll
        for (int j = 0; j < 4; j++) {
            int d = t + j * 128;
            out[d] = mtok[d] + pos[d];
        }
        return;
    }

    __shared__ float wsm[32];
    __shared__ float lnw[32];
    const float* wrow = seq + (size_t)tok * 32;
    if (t < 32) wsm[t] = wrow[t];
    __syncthreads();

    float m = 0.f;
    #pragma unroll
    for (int c = 0; c < 32; c++) m += wsm[c];
    m *= (1.f / 32.f);
    float v = 0.f;
    #pragma unroll
    for (int c = 0; c < 32; c++) { float d0 = wsm[c] - m; v += d0 * d0; }
    v *= (1.f / 32.f);
    float rs = rsqrtf(v + 1e-5f);
    if (t < 32) lnw[t] = (wsm[t] - m) * rs * p1g[t] + p1b[t];
    __syncthreads();

    float acc[4];
    #pragma unroll
    for (int j = 0; j < 4; j++) {
        int d = t + j * 128;
        float a = b_emb[d];
        #pragma unroll
        for (int c = 0; c < 32; c++) a += lnw[c] * W_emb[c * cD + d];
        acc[j] = a;
    }
    float s = 0.f, s2 = 0.f;
    #pragma unroll
    for (int j = 0; j < 4; j++) { s += acc[j]; s2 += acc[j] * acc[j]; }
    block_sum2<4>(s, s2);
    float mean = s * (1.f / cD);
    float var  = s2 * (1.f / cD) - mean * mean;
    float rstd = rsqrtf(var + 1e-5f);
    #pragma unroll
    for (int j = 0; j < 4; j++) {
        int d = t + j * 128;
        out[d] = (acc[j] - mean) * rstd * p2g[d] + p2b[d] + pos[d];
    }
}

// ---------------------------------------------------------------------------
// LayerNorm over D=512: 1 block / row, 128 threads
// ---------------------------------------------------------------------------
__global__ void __launch_bounds__(128) k_ln(
    const float* __restrict__ x, const float* __restrict__ g,
    const float* __restrict__ bt, float* __restrict__ y)
{
    int row = blockIdx.x;
    int t = threadIdx.x;
    const float4* xr = (const float4*)(x + (size_t)row * cD);
    float4 a = xr[t];
    float s  = a.x + a.y + a.z + a.w;
    float s2 = a.x*a.x + a.y*a.y + a.z*a.z + a.w*a.w;
    block_sum2<4>(s, s2);
    float mean = s * (1.f / cD);
    float var  = s2 * (1.f / cD) - mean * mean;
    float rstd = rsqrtf(var + 1e-5f);
    float4 gg = ((const float4*)g)[t];
    float4 bb = ((const float4*)bt)[t];
    float4 o;
    o.x = (a.x - mean) * rstd * gg.x + bb.x;
    o.y = (a.y - mean) * rstd * gg.y + bb.y;
    o.z = (a.z - mean) * rstd * gg.z + bb.z;
    o.w = (a.w - mean) * rstd * gg.w + bb.w;
    ((float4*)(y + (size_t)row * cD))[t] = o;
}

// ---------------------------------------------------------------------------
// Generic tiled SGEMM: C[M,N] = act(A[M,K] @ B[K,N] + bias) + Res
// BM=BN=64, BK=16, 256 threads, 4x4 per thread
// ---------------------------------------------------------------------------
template<bool BIAS, bool RES, bool GELU_>
__global__ void __launch_bounds__(256) k_gemm(
    const float* __restrict__ A, const float* __restrict__ Bw,
    const float* __restrict__ bias, const float* __restrict__ Res,
    float* __restrict__ C, int M, int N, int Kd)
{
    __shared__ float As[16][64];
    __shared__ float Bs[16][68];
    int bm = blockIdx.y * 64, bn = blockIdx.x * 64;
    int tid = threadIdx.x;
    int tx = tid & 15, ty = tid >> 4;
    int ar = tid >> 2, ac4 = tid & 3;
    int br = tid >> 4, bc4 = tid & 15;
    const float* Aptr = A + (size_t)(bm + ar) * Kd + ac4 * 4;
    const float* Bptr = Bw + (size_t)br * N + bn + bc4 * 4;
    float acc[4][4] = {};

    for (int k0 = 0; k0 < Kd; k0 += 16) {
        float4 av = *(const float4*)(Aptr + k0);
        float4 bv = *(const float4*)(Bptr + (size_t)k0 * N);
        __syncthreads();
        As[ac4*4+0][ar] = av.x; As[ac4*4+1][ar] = av.y;
        As[ac4*4+2][ar] = av.z; As[ac4*4+3][ar] = av.w;
        *(float4*)&Bs[br][bc4*4] = bv;
        __syncthreads();
        #pragma unroll
        for (int k = 0; k < 16; k++) {
            float4 aa = *(const float4*)&As[k][ty*4];
            float4 bb = *(const float4*)&Bs[k][tx*4];
            ACC44(aa, bb, acc);
        }
    }

    #pragma unroll
    for (int i = 0; i < 4; i++) {
        int row = bm + ty*4 + i;
        int col = bn + tx*4;
        float4 v = make_float4(acc[i][0], acc[i][1], acc[i][2], acc[i][3]);
        if (BIAS) {
            float4 b4 = *(const float4*)(bias + col);
            v.x += b4.x; v.y += b4.y; v.z += b4.z; v.w += b4.w;
        }
        if (GELU_) { v.x = gelu_f(v.x); v.y = gelu_f(v.y); v.z = gelu_f(v.z); v.w = gelu_f(v.w); }
        if (RES) {
            float4 r = *(const float4*)(Res + (size_t)row * N + col);
            v.x += r.x; v.y += r.y; v.z += r.z; v.w += r.w;
        }
        *(float4*)(C + (size_t)row * N + col) = v;
    }
}

// ---------------------------------------------------------------------------
// Attention scores: S[bh][i][j] = SCALE * sum_d Q[i][d]*K[j][d]
// grid (16 jtile, 16 itile, 64 bh), 256 threads
// ---------------------------------------------------------------------------
__global__ void __launch_bounds__(256) k_scores()
{
    int bh = blockIdx.z;
    int b = bh >> 3, h = bh & 7;
    int i0 = blockIdx.y * 64, j0 = blockIdx.x * 64;
    __shared__ float Qs[64][68];
    __shared__ float Ks[64][68];
    int tid = threadIdx.x;
    int lr = tid >> 4, lc4 = tid & 15;
    const float* qbase = g_qkv + (size_t)b * cNW * (3*cD) + h * cDH;
    const float* kbase = qbase + cD;

    #pragma unroll
    for (int p = 0; p < 4; p++) {
        int r = lr + p * 16;
        float4 q  = *(const float4*)(qbase + (size_t)(i0 + r) * (3*cD) + lc4*4);
        float4 kk = *(const float4*)(kbase + (size_t)(j0 + r) * (3*cD) + lc4*4);
        Qs[lc4*4+0][r] = q.x;  Qs[lc4*4+1][r] = q.y;  Qs[lc4*4+2][r] = q.z;  Qs[lc4*4+3][r] = q.w;
        Ks[lc4*4+0][r] = kk.x; Ks[lc4*4+1][r] = kk.y; Ks[lc4*4+2][r] = kk.z; Ks[lc4*4+3][r] = kk.w;
    }
    __syncthreads();

    int tx = tid & 15, ty = tid >> 4;
    float acc[4][4] = {};
    #pragma unroll
    for (int d = 0; d < 64; d++) {
        float4 aa = *(const float4*)&Qs[d][ty*4];
        float4 bb = *(const float4*)&Ks[d][tx*4];
        ACC44(aa, bb, acc);
    }
    float* out = g_sc + ((size_t)bh * cNW + i0) * cNW + j0;
    #pragma unroll
    for (int i = 0; i < 4; i++) {
        float4 v = make_float4(acc[i][0]*cSCALE, acc[i][1]*cSCALE, acc[i][2]*cSCALE, acc[i][3]*cSCALE);
        *(float4*)(out + (size_t)(ty*4 + i) * cNW + tx*4) = v;
    }
}

// ---------------------------------------------------------------------------
// Row softmax over 1024, in-place on g_sc. 1 block / row, 256 threads.
// ---------------------------------------------------------------------------
__global__ void __launch_bounds__(256) k_softmax()
{
    size_t row = blockIdx.x;
    float4* p = (float4*)(g_sc + row * cNW);
    int t = threadIdx.x;
    float4 v = p[t];
    float mx = fmaxf(fmaxf(v.x, v.y), fmaxf(v.z, v.w));
    mx = block_max<8>(mx);
    v.x = __expf(v.x - mx); v.y = __expf(v.y - mx);
    v.z = __expf(v.z - mx); v.w = __expf(v.w - mx);
    float s = v.x + v.y + v.z + v.w;
    s = block_sum1<8>(s);
    float inv = 1.f / s;
    v.x *= inv; v.y *= inv; v.z *= inv; v.w *= inv;
    p[t] = v;
}

// ---------------------------------------------------------------------------
// Attn output: O[bh][i][d] = sum_j P[i][j] * V[j][d]  (M=1024,N=64,K=1024)
// grid (16 itile, 64 bh), 256 threads
// ---------------------------------------------------------------------------
__global__ void __launch_bounds__(256) k_attnout()
{
    int bh = blockIdx.y;
    int b = bh >> 3, h = bh & 7;
    int i0 = blockIdx.x * 64;
    __shared__ float Ps[32][68];
    __shared__ float Vs[32][68];
    int tid = threadIdx.x;
    const float* vbase = g_qkv + (size_t)b * cNW * (3*cD) + 2*cD + h * cDH;
    const float* prow  = g_sc + ((size_t)bh * cNW + i0) * cNW;
    int ppr = tid >> 3, ppc = tid & 7;
    int vr  = tid >> 4, vc  = tid & 15;
    int tx = tid & 15, ty = tid >> 4;
    float acc[4][4] = {};

    for (int j0 = 0; j0 < cNW; j0 += 32) {
        float4 p0 = *(const float4*)(prow + (size_t)ppr        * cNW + j0 + ppc*4);
        float4 p1 = *(const float4*)(prow + (size_t)(ppr + 32) * cNW + j0 + ppc*4);
        float4 v0 = *(const float4*)(vbase + (size_t)(j0 + vr)      * (3*cD) + vc*4);
        float4 v1 = *(const float4*)(vbase + (size_t)(j0 + vr + 16) * (3*cD) + vc*4);
        __syncthreads();
        Ps[ppc*4+0][ppr] = p0.x; Ps[ppc*4+1][ppr] = p0.y;
        Ps[ppc*4+2][ppr] = p0.z; Ps[ppc*4+3][ppr] = p0.w;
        Ps[ppc*4+0][ppr+32] = p1.x; Ps[ppc*4+1][ppr+32] = p1.y;
        Ps[ppc*4+2][ppr+32] = p1.z; Ps[ppc*4+3][ppr+32] = p1.w;
        *(float4*)&Vs[vr][vc*4]      = v0;
        *(float4*)&Vs[vr + 16][vc*4] = v1;
        __syncthreads();
        #pragma unroll
        for (int k = 0; k < 32; k++) {
            float4 aa = *(const float4*)&Ps[k][ty*4];
            float4 bb = *(const float4*)&Vs[k][tx*4];
            ACC44(aa, bb, acc);
        }
    }
    float* obase = g_ao + ((size_t)b * cNW + i0) * cD + h * cDH;
    #pragma unroll
    for (int i = 0; i < 4; i++) {
        float4 v = make_float4(acc[i][0], acc[i][1], acc[i][2], acc[i][3]);
        *(float4*)(obase + (size_t)(ty*4 + i) * cD + tx*4) = v;
    }
}

// ---------------------------------------------------------------------------
// Output head: gather masked tokens from final LN (g_h), project W_words,
// softmax over CH=4 groups, plus labels gather.
// grid (K=512, B=8), 256 threads
// ---------------------------------------------------------------------------
__global__ void __launch_bounds__(256) k_output(
    const float* __restrict__ seq, const int* __restrict__ mask_idx,
    const float* __restrict__ Ww, const float* __restrict__ bw,
    float* __restrict__ out, long long out_size)
{
    int b = blockIdx.y, k = blockIdx.x;
    int idx = mask_idx[b * cK + k];
    const float* enc = g_h + ((size_t)b * cNW + idx) * cD;
    __shared__ float es[cD];
    __shared__ float lgt[32];
    int t = threadIdx.x;
    ((float2*)es)[t] = ((const float2*)enc)[t];
    __syncthreads();

    int lg = t >> 3, sg = t & 7;
    float part = 0.f;
    #pragma unroll
    for (int c = 0; c < 64; c++) {
        int cc = sg * 64 + c;
        part += es[cc] * Ww[cc * 32 + lg];
    }
    part += __shfl_down_sync(0xffffffffu, part, 4);
    part += __shfl_down_sync(0xffffffffu, part, 2);
    part += __shfl_down_sync(0xffffffffu, part, 1);
    if (sg == 0) lgt[lg] = part + bw[lg];
    __syncthreads();

    size_t base = (size_t)b * cK + k;
    if (t < 8) {
        float l0 = lgt[t*4+0], l1 = lgt[t*4+1], l2 = lgt[t*4+2], l3 = lgt[t*4+3];
        float mx = fmaxf(fmaxf(l0, l1), fmaxf(l2, l3));
        float e0 = expf(l0 - mx), e1 = expf(l1 - mx), e2 = expf(l2 - mx), e3 = expf(l3 - mx);
        float inv = 1.f / (e0 + e1 + e2 + e3);
        size_t off = base * 32 + t * 4;
        if ((long long)(off + 3) < out_size) {
            out[off+0] = e0*inv; out[off+1] = e1*inv; out[off+2] = e2*inv; out[off+3] = e3*inv;
        }
    }
    if (t < 32) {
        size_t off = (size_t)cB * cK * 32 + base * 32 + t;
        if ((long long)off < out_size)
            out[off] = seq[((size_t)b * cNW + idx) * 32 + t];
    }
}

// ---------------------------------------------------------------------------
// Launch
// ---------------------------------------------------------------------------
extern "C" void kernel_launch(void* const* d_in, const int* in_sizes, int n_in,
                              void* d_out, int out_size)
{
    const float* seq      = (const float*)d_in[0];
    const int*   mask_idx = (const int*)  d_in[1];
    const float* pos_emb  = (const float*)d_in[2];
    const float* mtok     = (const float*)d_in[3];
    const float* p1g      = (const float*)d_in[4];
    const float* p1b      = (const float*)d_in[5];
    const float* W_emb    = (const float*)d_in[6];
    const float* b_emb    = (const float*)d_in[7];
    const float* p2g      = (const float*)d_in[8];
    const float* p2b      = (const float*)d_in[9];
    const float* alng     = (const float*)d_in[10];
    const float* alnb     = (const float*)d_in[11];
    const float* Wqkv     = (const float*)d_in[12];
    const float* Wo       = (const float*)d_in[13];
    const float* flng     = (const float*)d_in[14];
    const float* flnb     = (const float*)d_in[15];
    const float* W1       = (const float*)d_in[16];
    const float* b1       = (const float*)d_in[17];
    const float* W2       = (const float*)d_in[18];
    const float* b2       = (const float*)d_in[19];
    const float* olng     = (const float*)d_in[20];
    const float* olnb     = (const float*)d_in[21];
    const float* Ww       = (const float*)d_in[22];
    const float* bw       = (const float*)d_in[23];
    float* out = (float*)d_out;
    (void)in_sizes; (void)n_in;

    float *px, *ph, *pqkv, *pao, *pff;
    cudaGetSymbolAddress((void**)&px,   g_x);
    cudaGetSymbolAddress((void**)&ph,   g_h);
    cudaGetSymbolAddress((void**)&pqkv, g_qkv);
    cudaGetSymbolAddress((void**)&pao,  g_ao);
    cudaGetSymbolAddress((void**)&pff,  g_ff);

    k_zeroflags<<<cT / 256, 256>>>();
    k_setflags<<<(cB * cK) / 256, 256>>>(mask_idx);
    k_embed<<<cT, 128>>>(seq, pos_emb, mtok, p1g, p1b, W_emb, b_emb, p2g, p2b);

    for (int l = 0; l < cL; l++) {
        const float* Wqkv_l = Wqkv + (size_t)l * cD * 3 * cD;
        const float* Wo_l   = Wo   + (size_t)l * cD * cD;
        const float* W1_l   = W1   + (size_t)l * cD * cFF;
        const float* W2_l   = W2   + (size_t)l * cFF * cD;

        // attention
        k_ln<<<cT, 128>>>(px, alng + l*cD, alnb + l*cD, ph);
        k_gemm<false,false,false><<<dim3(3*cD/64, cT/64), 256>>>(
            ph, Wqkv_l, nullptr, nullptr, pqkv, cT, 3*cD, cD);
        k_scores<<<dim3(16, 16, 64), 256>>>();
        k_softmax<<<cB * cH * cNW, 256>>>();
        k_attnout<<<dim3(16, 64), 256>>>();
        k_gemm<false,true,false><<<dim3(cD/64, cT/64), 256>>>(
            pao, Wo_l, nullptr, px, px, cT, cD, cD);

        // ffn
        k_ln<<<cT, 128>>>(px, flng + l*cD, flnb + l*cD, ph);
        k_gemm<true,false,true><<<dim3(cFF/64, cT/64), 256>>>(
            ph, W1_l, b1 + (size_t)l*cFF, nullptr, pff, cT, cFF, cD);
        k_gemm<true,true,false><<<dim3(cD/64, cT/64), 256>>>(
            pff, W2_l, b2 + (size_t)l*cD, px, px, cT, cD, cFF);
    }

    k_ln<<<cT, 128>>>(px, olng, olnb, ph);
    k_output<<<dim3(cK, cB), 256>>>(seq, mask_idx, Ww, bw, out, (long long)out_size);
}

// round 3
// speedup vs baseline: 2.4734x; 2.4734x over previous
#include <cuda_runtime.h>

#define DEV_INLINE __device__ __forceinline__

// Problem constants
constexpr int cB  = 8;
constexpr int cNW = 1024;
constexpr int cD  = 512;
constexpr int cH  = 8;
constexpr int cL  = 4;
constexpr int cFF = 2048;
constexpr int cK  = 512;
constexpr int cT  = cB * cNW;        // 8192 tokens
constexpr float cSCALE = 0.125f;

// ---------------------------------------------------------------------------
// Scratch
// ---------------------------------------------------------------------------
__device__ float g_x   [cT * cD];
__device__ float g_h   [cT * cD];
__device__ float g_qkv [cT * 3 * cD];
__device__ float g_sc  [67108864];         // 8*8*1024*1024
__device__ float g_ao  [cT * cD];
__device__ float g_ff  [cT * cFF];
__device__ float g_wT  [12582912];         // transposed weights (all layers)
__device__ float g_vt  [4194304];          // V^T per (b,h): [64][1024]
__device__ int   g_mflag[cT];

// ---------------------------------------------------------------------------
// Helpers
// ---------------------------------------------------------------------------
DEV_INLINE float gelu_f(float x) {
    return 0.5f * x * (1.0f + tanhf(0.7978845608028654f * (x + 0.044715f * x * x * x)));
}

DEV_INLINE unsigned tf32r(float x) {
    unsigned u;
    asm("cvt.rna.tf32.f32 %0, %1;" : "=r"(u) : "f"(x));
    return u;
}

DEV_INLINE void mma_tf32(float* d, const unsigned* a, const unsigned* b) {
    asm volatile(
        "mma.sync.aligned.m16n8k8.row.col.f32.tf32.tf32.f32 "
        "{%0,%1,%2,%3}, {%4,%5,%6,%7}, {%8,%9}, {%0,%1,%2,%3};"
        : "+f"(d[0]), "+f"(d[1]), "+f"(d[2]), "+f"(d[3])
        : "r"(a[0]), "r"(a[1]), "r"(a[2]), "r"(a[3]), "r"(b[0]), "r"(b[1]));
}

// ---------------------------------------------------------------------------
// Tensor-core tf32 GEMM:  C[M,N] = alpha*(A[M,K] @ B[N,K]^T) (+bias)(gelu)(+Res)
// BM=128, BN in {128,64}, BK=32, 256 threads (8 warps: 2m x 4n).
// Each warp: 64 x (BN/4), atoms m16n8k8: 4 x NATOM.
// SMEM row-major pad 36 -> bank = (4m+k)%32, conflict-free fragment loads.
// z-dim: zb = z>>3, zh = z&7 offsets for batched attention GEMMs.
// ---------------------------------------------------------------------------
template<int BN, bool BIAS, bool RES, bool GELU_>
__global__ void __launch_bounds__(256)
k_tgemm(const float* __restrict__ A, const float* __restrict__ B,
        const float* __restrict__ bias, const float* __restrict__ Res,
        float* __restrict__ C, int K, int sA, int sB, int sC,
        long long bA, long long hA, long long bB, long long hB,
        long long bC, long long hC, float alpha)
{
    extern __shared__ __align__(16) unsigned dsm[];
    constexpr int NATOM = BN / 32;        // n-atoms per warp
    constexpr int WN    = BN / 4;         // warp n-tile
    constexpr int NB4   = BN * 8 / 256;   // B float4 loads per thread per chunk
    constexpr int ASZ   = 128 * 36;       // A buffer (elems)
    constexpr int BSZ   = BN * 36;        // B buffer (elems)

    int tid = threadIdx.x;
    int wid = tid >> 5, lane = tid & 31;
    int wm = wid & 1, wn = wid >> 1;
    int lg = lane >> 2, lt = lane & 3;

    int z = blockIdx.z, zb = z >> 3, zh = z & 7;
    A += (size_t)zb * bA + (size_t)zh * hA;
    B += (size_t)zb * bB + (size_t)zh * hB;
    C += (size_t)zb * bC + (size_t)zh * hC;
    int bm = blockIdx.y * 128, bn = blockIdx.x * BN;

    const int NC = K >> 5;
    float4 ra[4], rb[NB4];
    float acc[4][NATOM][4] = {};

#define LDG_CHUNK(c) do { int k0 = (c) << 5;                                               \
    _Pragma("unroll")                                                                      \
    for (int i = 0; i < 4; i++) { int idx = tid + i * 256; int r = idx >> 3, f = idx & 7;  \
        ra[i] = __ldg((const float4*)(A + (size_t)(bm + r) * sA + k0 + f * 4)); }          \
    _Pragma("unroll")                                                                      \
    for (int i = 0; i < NB4; i++) { int idx = tid + i * 256; int r = idx >> 3, f = idx & 7;\
        rb[i] = __ldg((const float4*)(B + (size_t)(bn + r) * sB + k0 + f * 4)); } } while (0)

#define STS_CHUNK(bf) do {                                                                 \
    unsigned* Aw = dsm + (bf) * ASZ;                                                       \
    unsigned* Bw = dsm + 2 * ASZ + (bf) * BSZ;                                             \
    _Pragma("unroll")                                                                      \
    for (int i = 0; i < 4; i++) { int idx = tid + i * 256; int r = idx >> 3, f = idx & 7;  \
        uint4 u = make_uint4(tf32r(ra[i].x), tf32r(ra[i].y), tf32r(ra[i].z), tf32r(ra[i].w)); \
        *(uint4*)&Aw[r * 36 + f * 4] = u; }                                                \
    _Pragma("unroll")                                                                      \
    for (int i = 0; i < NB4; i++) { int idx = tid + i * 256; int r = idx >> 3, f = idx & 7;\
        uint4 u = make_uint4(tf32r(rb[i].x), tf32r(rb[i].y), tf32r(rb[i].z), tf32r(rb[i].w)); \
        *(uint4*)&Bw[r * 36 + f * 4] = u; } } while (0)

    LDG_CHUNK(0);
    STS_CHUNK(0);
    __syncthreads();

    for (int c = 0; c < NC; c++) {
        int buf = c & 1;
        if (c + 1 < NC) LDG_CHUNK(c + 1);

        const unsigned* Ab = dsm + buf * ASZ;
        const unsigned* Bb = dsm + 2 * ASZ + buf * BSZ;
        #pragma unroll
        for (int ks = 0; ks < 4; ks++) {
            int kk = ks * 8 + lt;
            unsigned af[4][4], bf[NATOM][2];
            #pragma unroll
            for (int ma = 0; ma < 4; ma++) {
                int r = wm * 64 + ma * 16 + lg;
                af[ma][0] = Ab[r * 36 + kk];
                af[ma][1] = Ab[(r + 8) * 36 + kk];
                af[ma][2] = Ab[r * 36 + kk + 4];
                af[ma][3] = Ab[(r + 8) * 36 + kk + 4];
            }
            #pragma unroll
            for (int na = 0; na < NATOM; na++) {
                int n = wn * WN + na * 8 + lg;
                bf[na][0] = Bb[n * 36 + kk];
                bf[na][1] = Bb[n * 36 + kk + 4];
            }
            #pragma unroll
            for (int ma = 0; ma < 4; ma++)
                #pragma unroll
                for (int na = 0; na < NATOM; na++)
                    mma_tf32(acc[ma][na], af[ma], bf[na]);
        }

        if (c + 1 < NC) {
            STS_CHUNK(buf ^ 1);
            __syncthreads();
        }
    }

    // Epilogue: direct STG (float2 per row-half)
    #pragma unroll
    for (int ma = 0; ma < 4; ma++) {
        #pragma unroll
        for (int na = 0; na < NATOM; na++) {
            int row = bm + wm * 64 + ma * 16 + lg;
            int col = bn + wn * WN + na * 8 + 2 * lt;
            #pragma unroll
            for (int half = 0; half < 2; half++) {
                int r = row + half * 8;
                float v0 = acc[ma][na][half * 2 + 0] * alpha;
                float v1 = acc[ma][na][half * 2 + 1] * alpha;
                if (BIAS) { v0 += bias[col]; v1 += bias[col + 1]; }
                if (GELU_) { v0 = gelu_f(v0); v1 = gelu_f(v1); }
                if (RES) {
                    const float* rp = Res + (size_t)r * sC + col;
                    v0 += rp[0]; v1 += rp[1];
                }
                *(float2*)(C + (size_t)r * sC + col) = make_float2(v0, v1);
            }
        }
    }
#undef LDG_CHUNK
#undef STS_CHUNK
}

// ---------------------------------------------------------------------------
// Transposes
// ---------------------------------------------------------------------------
__global__ void k_wt(const float* __restrict__ in, float* __restrict__ out, int R, int Cc) {
    __shared__ float t[32][33];
    int c0 = blockIdx.x * 32, r0 = blockIdx.y * 32;
    #pragma unroll
    for (int i = 0; i < 4; i++)
        t[threadIdx.y + i * 8][threadIdx.x] = in[(size_t)(r0 + threadIdx.y + i * 8) * Cc + c0 + threadIdx.x];
    __syncthreads();
    #pragma unroll
    for (int i = 0; i < 4; i++)
        out[(size_t)(c0 + threadIdx.y + i * 8) * R + r0 + threadIdx.x] = t[threadIdx.x][threadIdx.y + i * 8];
}

__global__ void k_vtrans() {
    __shared__ float t[32][33];
    int bh = blockIdx.z, b = bh >> 3, h = bh & 7;
    const float* src = g_qkv + (size_t)b * cNW * (3 * cD) + 2 * cD + h * 64;
    int j0 = blockIdx.x * 32, d0 = blockIdx.y * 32;
    #pragma unroll
    for (int i = 0; i < 4; i++)
        t[threadIdx.y + i * 8][threadIdx.x] = src[(size_t)(j0 + threadIdx.y + i * 8) * (3 * cD) + d0 + threadIdx.x];
    __syncthreads();
    float* dst = g_vt + ((size_t)bh * 64 + d0) * cNW + j0;
    #pragma unroll
    for (int i = 0; i < 4; i++)
        dst[(size_t)(threadIdx.y + i * 8) * cNW + threadIdx.x] = t[threadIdx.x][threadIdx.y + i * 8];
}

// ---------------------------------------------------------------------------
// Reductions
// ---------------------------------------------------------------------------
template<int NWARPS>
DEV_INLINE void block_sum2(float& s, float& s2) {
    #pragma unroll
    for (int o = 16; o > 0; o >>= 1) {
        s  += __shfl_down_sync(0xffffffffu, s,  o);
        s2 += __shfl_down_sync(0xffffffffu, s2, o);
    }
    __shared__ float sh_a[NWARPS], sh_b[NWARPS];
    int w = threadIdx.x >> 5;
    if ((threadIdx.x & 31) == 0) { sh_a[w] = s; sh_b[w] = s2; }
    __syncthreads();
    if (threadIdx.x == 0) {
        float a = sh_a[0], b = sh_b[0];
        #pragma unroll
        for (int i = 1; i < NWARPS; i++) { a += sh_a[i]; b += sh_b[i]; }
        sh_a[0] = a; sh_b[0] = b;
    }
    __syncthreads();
    s = sh_a[0]; s2 = sh_b[0];
}

template<int NWARPS>
DEV_INLINE float block_max(float v) {
    #pragma unroll
    for (int o = 16; o > 0; o >>= 1)
        v = fmaxf(v, __shfl_down_sync(0xffffffffu, v, o));
    __shared__ float sh_m[NWARPS];
    int w = threadIdx.x >> 5;
    if ((threadIdx.x & 31) == 0) sh_m[w] = v;
    __syncthreads();
    if (threadIdx.x == 0) {
        float a = sh_m[0];
        #pragma unroll
        for (int i = 1; i < NWARPS; i++) a = fmaxf(a, sh_m[i]);
        sh_m[0] = a;
    }
    __syncthreads();
    return sh_m[0];
}

template<int NWARPS>
DEV_INLINE float block_sum1(float v) {
    #pragma unroll
    for (int o = 16; o > 0; o >>= 1)
        v += __shfl_down_sync(0xffffffffu, v, o);
    __shared__ float sh_s[NWARPS];
    int w = threadIdx.x >> 5;
    if ((threadIdx.x & 31) == 0) sh_s[w] = v;
    __syncthreads();
    if (threadIdx.x == 0) {
        float a = sh_s[0];
        #pragma unroll
        for (int i = 1; i < NWARPS; i++) a += sh_s[i];
        sh_s[0] = a;
    }
    __syncthreads();
    return sh_s[0];
}

// ---------------------------------------------------------------------------
// Flags / embed / ln / softmax / output
// ---------------------------------------------------------------------------
__global__ void k_zeroflags() {
    int i = blockIdx.x * blockDim.x + threadIdx.x;
    if (i < cT) g_mflag[i] = 0;
}
__global__ void k_setflags(const int* __restrict__ mask_idx) {
    int i = blockIdx.x * blockDim.x + threadIdx.x;
    if (i < cB * cK) g_mflag[(i / cK) * cNW + mask_idx[i]] = 1;
}

__global__ void __launch_bounds__(128) k_embed(
    const float* __restrict__ seq, const float* __restrict__ pos_emb,
    const float* __restrict__ mtok,
    const float* __restrict__ p1g, const float* __restrict__ p1b,
    const float* __restrict__ W_emb, const float* __restrict__ b_emb,
    const float* __restrict__ p2g, const float* __restrict__ p2b)
{
    int tok = blockIdx.x;
    int w = tok & (cNW - 1);
    int t = threadIdx.x;
    const float* pos = pos_emb + (size_t)(w + 1) * cD;
    float* out = g_x + (size_t)tok * cD;

    if (g_mflag[tok]) {
        #pragma unroll
        for (int j = 0; j < 4; j++) { int d = t + j * 128; out[d] = mtok[d] + pos[d]; }
        return;
    }
    __shared__ float wsm[32];
    __shared__ float lnw[32];
    const float* wrow = seq + (size_t)tok * 32;
    if (t < 32) wsm[t] = wrow[t];
    __syncthreads();
    float m = 0.f;
    #pragma unroll
    for (int c = 0; c < 32; c++) m += wsm[c];
    m *= (1.f / 32.f);
    float v = 0.f;
    #pragma unroll
    for (int c = 0; c < 32; c++) { float d0 = wsm[c] - m; v += d0 * d0; }
    v *= (1.f / 32.f);
    float rs = rsqrtf(v + 1e-5f);
    if (t < 32) lnw[t] = (wsm[t] - m) * rs * p1g[t] + p1b[t];
    __syncthreads();
    float acc[4];
    #pragma unroll
    for (int j = 0; j < 4; j++) {
        int d = t + j * 128;
        float a = b_emb[d];
        #pragma unroll
        for (int c = 0; c < 32; c++) a += lnw[c] * W_emb[c * cD + d];
        acc[j] = a;
    }
    float s = 0.f, s2 = 0.f;
    #pragma unroll
    for (int j = 0; j < 4; j++) { s += acc[j]; s2 += acc[j] * acc[j]; }
    block_sum2<4>(s, s2);
    float mean = s * (1.f / cD);
    float var  = s2 * (1.f / cD) - mean * mean;
    float rstd = rsqrtf(var + 1e-5f);
    #pragma unroll
    for (int j = 0; j < 4; j++) {
        int d = t + j * 128;
        out[d] = (acc[j] - mean) * rstd * p2g[d] + p2b[d] + pos[d];
    }
}

__global__ void __launch_bounds__(128) k_ln(
    const float* __restrict__ x, const float* __restrict__ g,
    const float* __restrict__ bt, float* __restrict__ y)
{
    int row = blockIdx.x;
    int t = threadIdx.x;
    const float4* xr = (const float4*)(x + (size_t)row * cD);
    float4 a = xr[t];
    float s  = a.x + a.y + a.z + a.w;
    float s2 = a.x*a.x + a.y*a.y + a.z*a.z + a.w*a.w;
    block_sum2<4>(s, s2);
    float mean = s * (1.f / cD);
    float var  = s2 * (1.f / cD) - mean * mean;
    float rstd = rsqrtf(var + 1e-5f);
    float4 gg = ((const float4*)g)[t];
    float4 bb = ((const float4*)bt)[t];
    float4 o;
    o.x = (a.x - mean) * rstd * gg.x + bb.x;
    o.y = (a.y - mean) * rstd * gg.y + bb.y;
    o.z = (a.z - mean) * rstd * gg.z + bb.z;
    o.w = (a.w - mean) * rstd * gg.w + bb.w;
    ((float4*)(y + (size_t)row * cD))[t] = o;
}

__global__ void __launch_bounds__(256) k_softmax()
{
    size_t row = blockIdx.x;
    float4* p = (float4*)(g_sc + row * cNW);
    int t = threadIdx.x;
    float4 v = p[t];
    float mx = fmaxf(fmaxf(v.x, v.y), fmaxf(v.z, v.w));
    mx = block_max<8>(mx);
    v.x = __expf(v.x - mx); v.y = __expf(v.y - mx);
    v.z = __expf(v.z - mx); v.w = __expf(v.w - mx);
    float s = v.x + v.y + v.z + v.w;
    s = block_sum1<8>(s);
    float inv = 1.f / s;
    v.x *= inv; v.y *= inv; v.z *= inv; v.w *= inv;
    p[t] = v;
}

__global__ void __launch_bounds__(256) k_output(
    const float* __restrict__ seq, const int* __restrict__ mask_idx,
    const float* __restrict__ Ww, const float* __restrict__ bw,
    float* __restrict__ out, long long out_size)
{
    int b = blockIdx.y, k = blockIdx.x;
    int idx = mask_idx[b * cK + k];
    const float* enc = g_h + ((size_t)b * cNW + idx) * cD;
    __shared__ float es[cD];
    __shared__ float lgt[32];
    int t = threadIdx.x;
    ((float2*)es)[t] = ((const float2*)enc)[t];
    __syncthreads();
    int lg = t >> 3, sg = t & 7;
    float part = 0.f;
    #pragma unroll
    for (int c = 0; c < 64; c++) {
        int cc = sg * 64 + c;
        part += es[cc] * Ww[cc * 32 + lg];
    }
    part += __shfl_down_sync(0xffffffffu, part, 4);
    part += __shfl_down_sync(0xffffffffu, part, 2);
    part += __shfl_down_sync(0xffffffffu, part, 1);
    if (sg == 0) lgt[lg] = part + bw[lg];
    __syncthreads();
    size_t base = (size_t)b * cK + k;
    if (t < 8) {
        float l0 = lgt[t*4+0], l1 = lgt[t*4+1], l2 = lgt[t*4+2], l3 = lgt[t*4+3];
        float mx = fmaxf(fmaxf(l0, l1), fmaxf(l2, l3));
        float e0 = expf(l0 - mx), e1 = expf(l1 - mx), e2 = expf(l2 - mx), e3 = expf(l3 - mx);
        float inv = 1.f / (e0 + e1 + e2 + e3);
        size_t off = base * 32 + t * 4;
        if ((long long)(off + 3) < out_size) {
            out[off+0] = e0*inv; out[off+1] = e1*inv; out[off+2] = e2*inv; out[off+3] = e3*inv;
        }
    }
    if (t < 32) {
        size_t off = (size_t)cB * cK * 32 + base * 32 + t;
        if ((long long)off < out_size)
            out[off] = seq[((size_t)b * cNW + idx) * 32 + t];
    }
}

// ---------------------------------------------------------------------------
// Launch
// ---------------------------------------------------------------------------
extern "C" void kernel_launch(void* const* d_in, const int* in_sizes, int n_in,
                              void* d_out, int out_size)
{
    const float* seq      = (const float*)d_in[0];
    const int*   mask_idx = (const int*)  d_in[1];
    const float* pos_emb  = (const float*)d_in[2];
    const float* mtok     = (const float*)d_in[3];
    const float* p1g      = (const float*)d_in[4];
    const float* p1b      = (const float*)d_in[5];
    const float* W_emb    = (const float*)d_in[6];
    const float* b_emb    = (const float*)d_in[7];
    const float* p2g      = (const float*)d_in[8];
    const float* p2b      = (const float*)d_in[9];
    const float* alng     = (const float*)d_in[10];
    const float* alnb     = (const float*)d_in[11];
    const float* Wqkv     = (const float*)d_in[12];
    const float* Wo       = (const float*)d_in[13];
    const float* flng     = (const float*)d_in[14];
    const float* flnb     = (const float*)d_in[15];
    const float* W1       = (const float*)d_in[16];
    const float* b1       = (const float*)d_in[17];
    const float* W2       = (const float*)d_in[18];
    const float* b2       = (const float*)d_in[19];
    const float* olng     = (const float*)d_in[20];
    const float* olnb     = (const float*)d_in[21];
    const float* Ww       = (const float*)d_in[22];
    const float* bw       = (const float*)d_in[23];
    float* out = (float*)d_out;
    (void)in_sizes; (void)n_in;

    float *px, *ph, *pqkv, *pao, *pff, *pwT, *psc, *pvt;
    cudaGetSymbolAddress((void**)&px,   g_x);
    cudaGetSymbolAddress((void**)&ph,   g_h);
    cudaGetSymbolAddress((void**)&pqkv, g_qkv);
    cudaGetSymbolAddress((void**)&pao,  g_ao);
    cudaGetSymbolAddress((void**)&pff,  g_ff);
    cudaGetSymbolAddress((void**)&pwT,  g_wT);
    cudaGetSymbolAddress((void**)&psc,  g_sc);
    cudaGetSymbolAddress((void**)&pvt,  g_vt);

    const int DYN128 = (2 * 128 * 36 + 2 * 128 * 36) * 4;  // 73728
    const int DYN64  = (2 * 128 * 36 + 2 * 64  * 36) * 4;  // 55296
    cudaFuncSetAttribute(k_tgemm<128,false,false,false>, cudaFuncAttributeMaxDynamicSharedMemorySize, DYN128);
    cudaFuncSetAttribute(k_tgemm<128,false,true, false>, cudaFuncAttributeMaxDynamicSharedMemorySize, DYN128);
    cudaFuncSetAttribute(k_tgemm<128,true, false,true >, cudaFuncAttributeMaxDynamicSharedMemorySize, DYN128);
    cudaFuncSetAttribute(k_tgemm<128,true, true, false>, cudaFuncAttributeMaxDynamicSharedMemorySize, DYN128);
    cudaFuncSetAttribute(k_tgemm<64, false,false,false>, cudaFuncAttributeMaxDynamicSharedMemorySize, DYN64);

    k_zeroflags<<<cT / 256, 256>>>();
    k_setflags<<<(cB * cK) / 256, 256>>>(mask_idx);
    k_embed<<<cT, 128>>>(seq, pos_emb, mtok, p1g, p1b, W_emb, b_emb, p2g, p2b);

    // transpose all weights to [N][K]
    for (int l = 0; l < cL; l++) {
        float* baseT = pwT + (size_t)l * 3145728;
        k_wt<<<dim3(1536/32, 512/32), dim3(32,8)>>>(Wqkv + (size_t)l*512*1536, baseT,           512, 1536);
        k_wt<<<dim3( 512/32, 512/32), dim3(32,8)>>>(Wo   + (size_t)l*512*512,  baseT + 786432,  512,  512);
        k_wt<<<dim3(2048/32, 512/32), dim3(32,8)>>>(W1   + (size_t)l*512*2048, baseT + 1048576, 512, 2048);
        k_wt<<<dim3( 512/32,2048/32), dim3(32,8)>>>(W2   + (size_t)l*2048*512, baseT + 2097152,2048,  512);
    }

    for (int l = 0; l < cL; l++) {
        float* baseT = pwT + (size_t)l * 3145728;
        float* WqkvT = baseT;
        float* WoT   = baseT + 786432;
        float* W1T   = baseT + 1048576;
        float* W2T   = baseT + 2097152;

        // attention
        k_ln<<<cT, 128>>>(px, alng + l*cD, alnb + l*cD, ph);
        k_tgemm<128,false,false,false><<<dim3(12, 64, 1), 256, DYN128>>>(
            ph, WqkvT, nullptr, nullptr, pqkv, 512, 512, 512, 1536,
            0,0, 0,0, 0,0, 1.0f);
        k_vtrans<<<dim3(32, 2, 64), dim3(32,8)>>>();
        // scores = Q @ K^T * SCALE
        k_tgemm<128,false,false,false><<<dim3(8, 8, 64), 256, DYN128>>>(
            pqkv, pqkv + 512, nullptr, nullptr, psc, 64, 1536, 1536, 1024,
            (long long)1024*1536, 64, (long long)1024*1536, 64,
            (long long)8*1048576, 1048576, cSCALE);
        k_softmax<<<cB * cH * cNW, 256>>>();
        // attn out = P @ V^T(d-major)
        k_tgemm<64,false,false,false><<<dim3(1, 8, 64), 256, DYN64>>>(
            psc, pvt, nullptr, nullptr, pao, 1024, 1024, 1024, 512,
            (long long)8*1048576, 1048576, (long long)8*65536, 65536,
            (long long)524288, 64, 1.0f);
        k_tgemm<128,false,true,false><<<dim3(4, 64, 1), 256, DYN128>>>(
            pao, WoT, nullptr, px, px, 512, 512, 512, 512,
            0,0, 0,0, 0,0, 1.0f);

        // ffn
        k_ln<<<cT, 128>>>(px, flng + l*cD, flnb + l*cD, ph);
        k_tgemm<128,true,false,true><<<dim3(16, 64, 1), 256, DYN128>>>(
            ph, W1T, b1 + (size_t)l*cFF, nullptr, pff, 512, 512, 512, 2048,
            0,0, 0,0, 0,0, 1.0f);
        k_tgemm<128,true,true,false><<<dim3(4, 64, 1), 256, DYN128>>>(
            pff, W2T, b2 + (size_t)l*cD, px, px, 2048, 2048, 2048, 512,
            0,0, 0,0, 0,0, 1.0f);
    }

    k_ln<<<cT, 128>>>(px, olng, olnb, ph);
    k_output<<<dim3(cK, cB), 256>>>(seq, mask_idx, Ww, bw, out, (long long)out_size);
}

// round 4
// speedup vs baseline: 3.0396x; 1.2289x over previous
#include <cuda_runtime.h>

#define DEV_INLINE __device__ __forceinline__

// Problem constants
constexpr int cB  = 8;
constexpr int cNW = 1024;
constexpr int cD  = 512;
constexpr int cH  = 8;
constexpr int cL  = 4;
constexpr int cFF = 2048;
constexpr int cK  = 512;
constexpr int cT  = cB * cNW;        // 8192 tokens
constexpr float cSCALE = 0.125f;

// ---------------------------------------------------------------------------
// Scratch
// ---------------------------------------------------------------------------
__device__ float g_x   [cT * cD];
__device__ float g_h   [cT * cD];
__device__ float g_qkv [cT * 3 * cD];
__device__ float g_sc  [67108864];         // 8*8*1024*1024
__device__ float g_ao  [cT * cD];
__device__ float g_ff  [cT * cFF];
__device__ float g_wT  [12582912];         // transposed weights (all layers)
__device__ float g_vt  [4194304];          // V^T per (b,h): [64][1024]
__device__ int   g_mflag[cT];

// ---------------------------------------------------------------------------
// Helpers
// ---------------------------------------------------------------------------
DEV_INLINE float gelu_f(float x) {
    float z = 0.7978845608028654f * (x + 0.044715f * x * x * x);
    float t = __expf(2.0f * z);
    float th = 1.0f - 2.0f / (t + 1.0f);
    return 0.5f * x * (1.0f + th);
}

DEV_INLINE unsigned pk2(float lo, float hi) {
    unsigned u;
    asm("cvt.rn.bf16x2.f32 %0, %1, %2;" : "=r"(u) : "f"(hi), "f"(lo));
    return u;
}

DEV_INLINE void mma_bf16(float* d, const unsigned* a, const unsigned* b) {
    asm volatile(
        "mma.sync.aligned.m16n8k16.row.col.f32.bf16.bf16.f32 "
        "{%0,%1,%2,%3}, {%4,%5,%6,%7}, {%8,%9}, {%0,%1,%2,%3};"
        : "+f"(d[0]), "+f"(d[1]), "+f"(d[2]), "+f"(d[3])
        : "r"(a[0]), "r"(a[1]), "r"(a[2]), "r"(a[3]), "r"(b[0]), "r"(b[1]));
}

// ---------------------------------------------------------------------------
// Tensor-core bf16 GEMM:  C[M,N] = alpha*(A[M,K] @ B[N,K]^T) (+bias)(gelu)(+Res)
// BM=128, BN in {128,64}, BK=32, 256 threads (8 warps: 2m x 4n).
// Each warp: 64 x (BN/4), atoms m16n8k16: 4 x NATOM, 2 k-steps per chunk.
// SMEM: u32 = bf16x2 pairs, row stride 20 u32 (16 data + 4 pad) ->
// fragment loads provably conflict-free.
// z-dim: zb = z>>3, zh = z&7 offsets for batched attention GEMMs.
// ---------------------------------------------------------------------------
template<int BN, bool BIAS, bool RES, bool GELU_>
__global__ void __launch_bounds__(256)
k_tgemm(const float* __restrict__ A, const float* __restrict__ B,
        const float* __restrict__ bias, const float* __restrict__ Res,
        float* __restrict__ C, int K, int sA, int sB, int sC,
        long long bA, long long hA, long long bB, long long hB,
        long long bC, long long hC, float alpha)
{
    extern __shared__ __align__(16) unsigned dsm[];
    constexpr int NATOM = BN / 32;        // n-atoms per warp
    constexpr int WN    = BN / 4;         // warp n-tile
    constexpr int NB4   = BN * 8 / 256;   // B float4 loads per thread per chunk
    constexpr int ASZ   = 128 * 20;       // A buffer (u32)
    constexpr int BSZ   = BN * 20;        // B buffer (u32)

    int tid = threadIdx.x;
    int wid = tid >> 5, lane = tid & 31;
    int wm = wid & 1, wn = wid >> 1;
    int lg = lane >> 2, lt = lane & 3;

    int z = blockIdx.z, zb = z >> 3, zh = z & 7;
    A += (size_t)zb * bA + (size_t)zh * hA;
    B += (size_t)zb * bB + (size_t)zh * hB;
    C += (size_t)zb * bC + (size_t)zh * hC;
    int bm = blockIdx.y * 128, bn = blockIdx.x * BN;

    const int NC = K >> 5;
    float4 ra[4], rb[NB4];
    float acc[4][NATOM][4] = {};

#define LDG_CHUNK(c) do { int k0 = (c) << 5;                                               \
    _Pragma("unroll")                                                                      \
    for (int i = 0; i < 4; i++) { int idx = tid + i * 256; int r = idx >> 3, f = idx & 7;  \
        ra[i] = __ldg((const float4*)(A + (size_t)(bm + r) * sA + k0 + f * 4)); }          \
    _Pragma("unroll")                                                                      \
    for (int i = 0; i < NB4; i++) { int idx = tid + i * 256; int r = idx >> 3, f = idx & 7;\
        rb[i] = __ldg((const float4*)(B + (size_t)(bn + r) * sB + k0 + f * 4)); } } while (0)

#define STS_CHUNK(bf_) do {                                                                \
    unsigned* Aw = dsm + (bf_) * ASZ;                                                      \
    unsigned* Bw = dsm + 2 * ASZ + (bf_) * BSZ;                                            \
    _Pragma("unroll")                                                                      \
    for (int i = 0; i < 4; i++) { int idx = tid + i * 256; int r = idx >> 3, f = idx & 7;  \
        uint2 u = make_uint2(pk2(ra[i].x, ra[i].y), pk2(ra[i].z, ra[i].w));                \
        *(uint2*)&Aw[r * 20 + f * 2] = u; }                                                \
    _Pragma("unroll")                                                                      \
    for (int i = 0; i < NB4; i++) { int idx = tid + i * 256; int r = idx >> 3, f = idx & 7;\
        uint2 u = make_uint2(pk2(rb[i].x, rb[i].y), pk2(rb[i].z, rb[i].w));                \
        *(uint2*)&Bw[r * 20 + f * 2] = u; } } while (0)

    LDG_CHUNK(0);
    STS_CHUNK(0);
    __syncthreads();

    for (int c = 0; c < NC; c++) {
        int buf = c & 1;
        if (c + 1 < NC) LDG_CHUNK(c + 1);

        const unsigned* Ab = dsm + buf * ASZ;
        const unsigned* Bb = dsm + 2 * ASZ + buf * BSZ;
        #pragma unroll
        for (int ks = 0; ks < 2; ks++) {
            int kk = ks * 8 + lt;                 // u32 (bf16-pair) column
            unsigned af[4][4], bfr[NATOM][2];
            #pragma unroll
            for (int ma = 0; ma < 4; ma++) {
                int r = wm * 64 + ma * 16 + lg;
                af[ma][0] = Ab[r * 20 + kk];
                af[ma][1] = Ab[(r + 8) * 20 + kk];
                af[ma][2] = Ab[r * 20 + kk + 4];
                af[ma][3] = Ab[(r + 8) * 20 + kk + 4];
            }
            #pragma unroll
            for (int na = 0; na < NATOM; na++) {
                int n = wn * WN + na * 8 + lg;
                bfr[na][0] = Bb[n * 20 + kk];
                bfr[na][1] = Bb[n * 20 + kk + 4];
            }
            #pragma unroll
            for (int ma = 0; ma < 4; ma++)
                #pragma unroll
                for (int na = 0; na < NATOM; na++)
                    mma_bf16(acc[ma][na], af[ma], bfr[na]);
        }

        if (c + 1 < NC) {
            STS_CHUNK(buf ^ 1);
            __syncthreads();
        }
    }

    // Epilogue: direct STG (float2 per row-half)
    #pragma unroll
    for (int ma = 0; ma < 4; ma++) {
        #pragma unroll
        for (int na = 0; na < NATOM; na++) {
            int row = bm + wm * 64 + ma * 16 + lg;
            int col = bn + wn * WN + na * 8 + 2 * lt;
            #pragma unroll
            for (int half = 0; half < 2; half++) {
                int r = row + half * 8;
                float v0 = acc[ma][na][half * 2 + 0] * alpha;
                float v1 = acc[ma][na][half * 2 + 1] * alpha;
                if (BIAS) { v0 += bias[col]; v1 += bias[col + 1]; }
                if (GELU_) { v0 = gelu_f(v0); v1 = gelu_f(v1); }
                if (RES) {
                    const float* rp = Res + (size_t)r * sC + col;
                    v0 += rp[0]; v1 += rp[1];
                }
                *(float2*)(C + (size_t)r * sC + col) = make_float2(v0, v1);
            }
        }
    }
#undef LDG_CHUNK
#undef STS_CHUNK
}

// ---------------------------------------------------------------------------
// Transposes
// ---------------------------------------------------------------------------
__global__ void k_wt(const float* __restrict__ in, float* __restrict__ out, int R, int Cc) {
    __shared__ float t[32][33];
    int c0 = blockIdx.x * 32, r0 = blockIdx.y * 32;
    #pragma unroll
    for (int i = 0; i < 4; i++)
        t[threadIdx.y + i * 8][threadIdx.x] = in[(size_t)(r0 + threadIdx.y + i * 8) * Cc + c0 + threadIdx.x];
    __syncthreads();
    #pragma unroll
    for (int i = 0; i < 4; i++)
        out[(size_t)(c0 + threadIdx.y + i * 8) * R + r0 + threadIdx.x] = t[threadIdx.x][threadIdx.y + i * 8];
}

__global__ void k_vtrans() {
    __shared__ float t[32][33];
    int bh = blockIdx.z, b = bh >> 3, h = bh & 7;
    const float* src = g_qkv + (size_t)b * cNW * (3 * cD) + 2 * cD + h * 64;
    int j0 = blockIdx.x * 32, d0 = blockIdx.y * 32;
    #pragma unroll
    for (int i = 0; i < 4; i++)
        t[threadIdx.y + i * 8][threadIdx.x] = src[(size_t)(j0 + threadIdx.y + i * 8) * (3 * cD) + d0 + threadIdx.x];
    __syncthreads();
    float* dst = g_vt + ((size_t)bh * 64 + d0) * cNW + j0;
    #pragma unroll
    for (int i = 0; i < 4; i++)
        dst[(size_t)(threadIdx.y + i * 8) * cNW + threadIdx.x] = t[threadIdx.x][threadIdx.y + i * 8];
}

// ---------------------------------------------------------------------------
// Reductions
// ---------------------------------------------------------------------------
template<int NWARPS>
DEV_INLINE void block_sum2(float& s, float& s2) {
    #pragma unroll
    for (int o = 16; o > 0; o >>= 1) {
        s  += __shfl_down_sync(0xffffffffu, s,  o);
        s2 += __shfl_down_sync(0xffffffffu, s2, o);
    }
    __shared__ float sh_a[NWARPS], sh_b[NWARPS];
    int w = threadIdx.x >> 5;
    if ((threadIdx.x & 31) == 0) { sh_a[w] = s; sh_b[w] = s2; }
    __syncthreads();
    if (threadIdx.x == 0) {
        float a = sh_a[0], b = sh_b[0];
        #pragma unroll
        for (int i = 1; i < NWARPS; i++) { a += sh_a[i]; b += sh_b[i]; }
        sh_a[0] = a; sh_b[0] = b;
    }
    __syncthreads();
    s = sh_a[0]; s2 = sh_b[0];
}

template<int NWARPS>
DEV_INLINE float block_max(float v) {
    #pragma unroll
    for (int o = 16; o > 0; o >>= 1)
        v = fmaxf(v, __shfl_down_sync(0xffffffffu, v, o));
    __shared__ float sh_m[NWARPS];
    int w = threadIdx.x >> 5;
    if ((threadIdx.x & 31) == 0) sh_m[w] = v;
    __syncthreads();
    if (threadIdx.x == 0) {
        float a = sh_m[0];
        #pragma unroll
        for (int i = 1; i < NWARPS; i++) a = fmaxf(a, sh_m[i]);
        sh_m[0] = a;
    }
    __syncthreads();
    return sh_m[0];
}

template<int NWARPS>
DEV_INLINE float block_sum1(float v) {
    #pragma unroll
    for (int o = 16; o > 0; o >>= 1)
        v += __shfl_down_sync(0xffffffffu, v, o);
    __shared__ float sh_s[NWARPS];
    int w = threadIdx.x >> 5;
    if ((threadIdx.x & 31) == 0) sh_s[w] = v;
    __syncthreads();
    if (threadIdx.x == 0) {
        float a = sh_s[0];
        #pragma unroll
        for (int i = 1; i < NWARPS; i++) a += sh_s[i];
        sh_s[0] = a;
    }
    __syncthreads();
    return sh_s[0];
}

// ---------------------------------------------------------------------------
// Flags / embed / ln / softmax / output
// ---------------------------------------------------------------------------
__global__ void k_zeroflags() {
    int i = blockIdx.x * blockDim.x + threadIdx.x;
    if (i < cT) g_mflag[i] = 0;
}
__global__ void k_setflags(const int* __restrict__ mask_idx) {
    int i = blockIdx.x * blockDim.x + threadIdx.x;
    if (i < cB * cK) g_mflag[(i / cK) * cNW + mask_idx[i]] = 1;
}

__global__ void __launch_bounds__(128) k_embed(
    const float* __restrict__ seq, const float* __restrict__ pos_emb,
    const float* __restrict__ mtok,
    const float* __restrict__ p1g, const float* __restrict__ p1b,
    const float* __restrict__ W_emb, const float* __restrict__ b_emb,
    const float* __restrict__ p2g, const float* __restrict__ p2b)
{
    int tok = blockIdx.x;
    int w = tok & (cNW - 1);
    int t = threadIdx.x;
    const float* pos = pos_emb + (size_t)(w + 1) * cD;
    float* out = g_x + (size_t)tok * cD;

    if (g_mflag[tok]) {
        #pragma unroll
        for (int j = 0; j < 4; j++) { int d = t + j * 128; out[d] = mtok[d] + pos[d]; }
        return;
    }
    __shared__ float wsm[32];
    __shared__ float lnw[32];
    const float* wrow = seq + (size_t)tok * 32;
    if (t < 32) wsm[t] = wrow[t];
    __syncthreads();
    float m = 0.f;
    #pragma unroll
    for (int c = 0; c < 32; c++) m += wsm[c];
    m *= (1.f / 32.f);
    float v = 0.f;
    #pragma unroll
    for (int c = 0; c < 32; c++) { float d0 = wsm[c] - m; v += d0 * d0; }
    v *= (1.f / 32.f);
    float rs = rsqrtf(v + 1e-5f);
    if (t < 32) lnw[t] = (wsm[t] - m) * rs * p1g[t] + p1b[t];
    __syncthreads();
    float acc[4];
    #pragma unroll
    for (int j = 0; j < 4; j++) {
        int d = t + j * 128;
        float a = b_emb[d];
        #pragma unroll
        for (int c = 0; c < 32; c++) a += lnw[c] * W_emb[c * cD + d];
        acc[j] = a;
    }
    float s = 0.f, s2 = 0.f;
    #pragma unroll
    for (int j = 0; j < 4; j++) { s += acc[j]; s2 += acc[j] * acc[j]; }
    block_sum2<4>(s, s2);
    float mean = s * (1.f / cD);
    float var  = s2 * (1.f / cD) - mean * mean;
    float rstd = rsqrtf(var + 1e-5f);
    #pragma unroll
    for (int j = 0; j < 4; j++) {
        int d = t + j * 128;
        out[d] = (acc[j] - mean) * rstd * p2g[d] + p2b[d] + pos[d];
    }
}

__global__ void __launch_bounds__(128) k_ln(
    const float* __restrict__ x, const float* __restrict__ g,
    const float* __restrict__ bt, float* __restrict__ y)
{
    int row = blockIdx.x;
    int t = threadIdx.x;
    const float4* xr = (const float4*)(x + (size_t)row * cD);
    float4 a = xr[t];
    float s  = a.x + a.y + a.z + a.w;
    float s2 = a.x*a.x + a.y*a.y + a.z*a.z + a.w*a.w;
    block_sum2<4>(s, s2);
    float mean = s * (1.f / cD);
    float var  = s2 * (1.f / cD) - mean * mean;
    float rstd = rsqrtf(var + 1e-5f);
    float4 gg = ((const float4*)g)[t];
    float4 bb = ((const float4*)bt)[t];
    float4 o;
    o.x = (a.x - mean) * rstd * gg.x + bb.x;
    o.y = (a.y - mean) * rstd * gg.y + bb.y;
    o.z = (a.z - mean) * rstd * gg.z + bb.z;
    o.w = (a.w - mean) * rstd * gg.w + bb.w;
    ((float4*)(y + (size_t)row * cD))[t] = o;
}

__global__ void __launch_bounds__(256) k_softmax()
{
    size_t row = blockIdx.x;
    float4* p = (float4*)(g_sc + row * cNW);
    int t = threadIdx.x;
    float4 v = p[t];
    float mx = fmaxf(fmaxf(v.x, v.y), fmaxf(v.z, v.w));
    mx = block_max<8>(mx);
    v.x = __expf(v.x - mx); v.y = __expf(v.y - mx);
    v.z = __expf(v.z - mx); v.w = __expf(v.w - mx);
    float s = v.x + v.y + v.z + v.w;
    s = block_sum1<8>(s);
    float inv = 1.f / s;
    v.x *= inv; v.y *= inv; v.z *= inv; v.w *= inv;
    p[t] = v;
}

__global__ void __launch_bounds__(256) k_output(
    const float* __restrict__ seq, const int* __restrict__ mask_idx,
    const float* __restrict__ Ww, const float* __restrict__ bw,
    float* __restrict__ out, long long out_size)
{
    int b = blockIdx.y, k = blockIdx.x;
    int idx = mask_idx[b * cK + k];
    const float* enc = g_h + ((size_t)b * cNW + idx) * cD;
    __shared__ float es[cD];
    __shared__ float lgt[32];
    int t = threadIdx.x;
    ((float2*)es)[t] = ((const float2*)enc)[t];
    __syncthreads();
    int lg = t >> 3, sg = t & 7;
    float part = 0.f;
    #pragma unroll
    for (int c = 0; c < 64; c++) {
        int cc = sg * 64 + c;
        part += es[cc] * Ww[cc * 32 + lg];
    }
    part += __shfl_down_sync(0xffffffffu, part, 4);
    part += __shfl_down_sync(0xffffffffu, part, 2);
    part += __shfl_down_sync(0xffffffffu, part, 1);
    if (sg == 0) lgt[lg] = part + bw[lg];
    __syncthreads();
    size_t base = (size_t)b * cK + k;
    if (t < 8) {
        float l0 = lgt[t*4+0], l1 = lgt[t*4+1], l2 = lgt[t*4+2], l3 = lgt[t*4+3];
        float mx = fmaxf(fmaxf(l0, l1), fmaxf(l2, l3));
        float e0 = expf(l0 - mx), e1 = expf(l1 - mx), e2 = expf(l2 - mx), e3 = expf(l3 - mx);
        float inv = 1.f / (e0 + e1 + e2 + e3);
        size_t off = base * 32 + t * 4;
        if ((long long)(off + 3) < out_size) {
            out[off+0] = e0*inv; out[off+1] = e1*inv; out[off+2] = e2*inv; out[off+3] = e3*inv;
        }
    }
    if (t < 32) {
        size_t off = (size_t)cB * cK * 32 + base * 32 + t;
        if ((long long)off < out_size)
            out[off] = seq[((size_t)b * cNW + idx) * 32 + t];
    }
}

// ---------------------------------------------------------------------------
// Launch
// ---------------------------------------------------------------------------
extern "C" void kernel_launch(void* const* d_in, const int* in_sizes, int n_in,
                              void* d_out, int out_size)
{
    const float* seq      = (const float*)d_in[0];
    const int*   mask_idx = (const int*)  d_in[1];
    const float* pos_emb  = (const float*)d_in[2];
    const float* mtok     = (const float*)d_in[3];
    const float* p1g      = (const float*)d_in[4];
    const float* p1b      = (const float*)d_in[5];
    const float* W_emb    = (const float*)d_in[6];
    const float* b_emb    = (const float*)d_in[7];
    const float* p2g      = (const float*)d_in[8];
    const float* p2b      = (const float*)d_in[9];
    const float* alng     = (const float*)d_in[10];
    const float* alnb     = (const float*)d_in[11];
    const float* Wqkv     = (const float*)d_in[12];
    const float* Wo       = (const float*)d_in[13];
    const float* flng     = (const float*)d_in[14];
    const float* flnb     = (const float*)d_in[15];
    const float* W1       = (const float*)d_in[16];
    const float* b1       = (const float*)d_in[17];
    const float* W2       = (const float*)d_in[18];
    const float* b2       = (const float*)d_in[19];
    const float* olng     = (const float*)d_in[20];
    const float* olnb     = (const float*)d_in[21];
    const float* Ww       = (const float*)d_in[22];
    const float* bw       = (const float*)d_in[23];
    float* out = (float*)d_out;
    (void)in_sizes; (void)n_in;

    float *px, *ph, *pqkv, *pao, *pff, *pwT, *psc, *pvt;
    cudaGetSymbolAddress((void**)&px,   g_x);
    cudaGetSymbolAddress((void**)&ph,   g_h);
    cudaGetSymbolAddress((void**)&pqkv, g_qkv);
    cudaGetSymbolAddress((void**)&pao,  g_ao);
    cudaGetSymbolAddress((void**)&pff,  g_ff);
    cudaGetSymbolAddress((void**)&pwT,  g_wT);
    cudaGetSymbolAddress((void**)&psc,  g_sc);
    cudaGetSymbolAddress((void**)&pvt,  g_vt);

    const int DYN128 = (2 * 128 * 20 + 2 * 128 * 20) * 4;  // 40960
    const int DYN64  = (2 * 128 * 20 + 2 * 64  * 20) * 4;  // 30720
    cudaFuncSetAttribute(k_tgemm<128,false,false,false>, cudaFuncAttributeMaxDynamicSharedMemorySize, DYN128);
    cudaFuncSetAttribute(k_tgemm<128,false,true, false>, cudaFuncAttributeMaxDynamicSharedMemorySize, DYN128);
    cudaFuncSetAttribute(k_tgemm<128,true, false,true >, cudaFuncAttributeMaxDynamicSharedMemorySize, DYN128);
    cudaFuncSetAttribute(k_tgemm<128,true, true, false>, cudaFuncAttributeMaxDynamicSharedMemorySize, DYN128);
    cudaFuncSetAttribute(k_tgemm<64, false,false,false>, cudaFuncAttributeMaxDynamicSharedMemorySize, DYN64);

    k_zeroflags<<<cT / 256, 256>>>();
    k_setflags<<<(cB * cK) / 256, 256>>>(mask_idx);
    k_embed<<<cT, 128>>>(seq, pos_emb, mtok, p1g, p1b, W_emb, b_emb, p2g, p2b);

    // transpose all weights to [N][K]
    for (int l = 0; l < cL; l++) {
        float* baseT = pwT + (size_t)l * 3145728;
        k_wt<<<dim3(1536/32, 512/32), dim3(32,8)>>>(Wqkv + (size_t)l*512*1536, baseT,           512, 1536);
        k_wt<<<dim3( 512/32, 512/32), dim3(32,8)>>>(Wo   + (size_t)l*512*512,  baseT + 786432,  512,  512);
        k_wt<<<dim3(2048/32, 512/32), dim3(32,8)>>>(W1   + (size_t)l*512*2048, baseT + 1048576, 512, 2048);
        k_wt<<<dim3( 512/32,2048/32), dim3(32,8)>>>(W2   + (size_t)l*2048*512, baseT + 2097152,2048,  512);
    }

    for (int l = 0; l < cL; l++) {
        float* baseT = pwT + (size_t)l * 3145728;
        float* WqkvT = baseT;
        float* WoT   = baseT + 786432;
        float* W1T   = baseT + 1048576;
        float* W2T   = baseT + 2097152;

        // attention
        k_ln<<<cT, 128>>>(px, alng + l*cD, alnb + l*cD, ph);
        k_tgemm<128,false,false,false><<<dim3(12, 64, 1), 256, DYN128>>>(
            ph, WqkvT, nullptr, nullptr, pqkv, 512, 512, 512, 1536,
            0,0, 0,0, 0,0, 1.0f);
        k_vtrans<<<dim3(32, 2, 64), dim3(32,8)>>>();
        // scores = Q @ K^T * SCALE
        k_tgemm<128,false,false,false><<<dim3(8, 8, 64), 256, DYN128>>>(
            pqkv, pqkv + 512, nullptr, nullptr, psc, 64, 1536, 1536, 1024,
            (long long)1024*1536, 64, (long long)1024*1536, 64,
            (long long)8*1048576, 1048576, cSCALE);
        k_softmax<<<cB * cH * cNW, 256>>>();
        // attn out = P @ V^T(d-major)
        k_tgemm<64,false,false,false><<<dim3(1, 8, 64), 256, DYN64>>>(
            psc, pvt, nullptr, nullptr, pao, 1024, 1024, 1024, 512,
            (long long)8*1048576, 1048576, (long long)8*65536, 65536,
            (long long)524288, 64, 1.0f);
        k_tgemm<128,false,true,false><<<dim3(4, 64, 1), 256, DYN128>>>(
            pao, WoT, nullptr, px, px, 512, 512, 512, 512,
            0,0, 0,0, 0,0, 1.0f);

        // ffn
        k_ln<<<cT, 128>>>(px, flng + l*cD, flnb + l*cD, ph);
        k_tgemm<128,true,false,true><<<dim3(16, 64, 1), 256, DYN128>>>(
            ph, W1T, b1 + (size_t)l*cFF, nullptr, pff, 512, 512, 512, 2048,
            0,0, 0,0, 0,0, 1.0f);
        k_tgemm<128,true,true,false><<<dim3(4, 64, 1), 256, DYN128>>>(
            pff, W2T, b2 + (size_t)l*cD, px, px, 2048, 2048, 2048, 512,
            0,0, 0,0, 0,0, 1.0f);
    }

    k_ln<<<cT, 128>>>(px, olng, olnb, ph);
    k_output<<<dim3(cK, cB), 256>>>(seq, mask_idx, Ww, bw, out, (long long)out_size);
}

// round 5
// speedup vs baseline: 4.9573x; 1.6309x over previous
#include <cuda_runtime.h>
#include <cuda_bf16.h>

#define DEV_INLINE __device__ __forceinline__

// Problem constants
constexpr int cB  = 8;
constexpr int cNW = 1024;
constexpr int cD  = 512;
constexpr int cH  = 8;
constexpr int cL  = 4;
constexpr int cFF = 2048;
constexpr int cK  = 512;
constexpr int cT  = cB * cNW;        // 8192 tokens
constexpr float cSCALE = 0.125f;

typedef __nv_bfloat16 bf16;

// ---------------------------------------------------------------------------
// Scratch
// ---------------------------------------------------------------------------
__device__ float g_x   [cT * cD];           // residual (fp32)
__device__ float g_h   [cT * cD];           // final LN out (fp32)
__device__ bf16  g_hh  [cT * cD];           // LN out bf16
__device__ bf16  g_qkvh[cT * 3 * cD];       // qkv bf16
__device__ bf16  g_aoh [cT * cD];           // attn out bf16
__device__ bf16  g_ffh [cT * cFF];          // ffn hidden bf16
__device__ bf16  g_wTh [12582912];          // transposed weights bf16
__device__ int   g_mflag[cT];

// ---------------------------------------------------------------------------
// Helpers
// ---------------------------------------------------------------------------
DEV_INLINE float gelu_f(float x) {
    float z = 0.7978845608028654f * (x + 0.044715f * x * x * x);
    float t = __expf(2.0f * z);
    float th = 1.0f - 2.0f / (t + 1.0f);
    return 0.5f * x * (1.0f + th);
}

DEV_INLINE unsigned pk2(float lo, float hi) {
    unsigned u;
    asm("cvt.rn.bf16x2.f32 %0, %1, %2;" : "=r"(u) : "f"(hi), "f"(lo));
    return u;
}

DEV_INLINE void mma_bf16(float* d, const unsigned* a, const unsigned* b) {
    asm volatile(
        "mma.sync.aligned.m16n8k16.row.col.f32.bf16.bf16.f32 "
        "{%0,%1,%2,%3}, {%4,%5,%6,%7}, {%8,%9}, {%0,%1,%2,%3};"
        : "+f"(d[0]), "+f"(d[1]), "+f"(d[2]), "+f"(d[3])
        : "r"(a[0]), "r"(a[1]), "r"(a[2]), "r"(a[3]), "r"(b[0]), "r"(b[1]));
}

// ---------------------------------------------------------------------------
// bf16 tensor-core GEMM: C[M,N] = A[M,K] @ B[N,K]^T (+bias)(gelu)(+Res)
// BM=128, BN=128, BK=32, 256 threads (8 warps: 2m x 4n), warp 64x32.
// A,B bf16 row-major. C fp32 or bf16 (OBF). Static SMEM 40KB, double-buffered.
// ---------------------------------------------------------------------------
template<bool BIAS, bool RES, bool GELU_, bool OBF>
__global__ void __launch_bounds__(256)
k_tgemm(const bf16* __restrict__ A, const bf16* __restrict__ B,
        const float* __restrict__ bias, const float* __restrict__ Res,
        void* __restrict__ Cv, int K, int sA, int sB, int sC)
{
    __shared__ __align__(16) unsigned dsm[2 * 2560 * 2];   // 2 bufs x (A 2560 + B 2560) u32
    constexpr int ASZ = 128 * 20;
    constexpr int BSZ = 128 * 20;

    int tid = threadIdx.x;
    int wid = tid >> 5, lane = tid & 31;
    int wm = wid & 1, wn = wid >> 1;
    int lg = lane >> 2, lt = lane & 3;

    int bm = blockIdx.y * 128, bn = blockIdx.x * 128;

    const int NC = K >> 5;
    uint4 ra[2], rb[2];
    float acc[4][4][4] = {};

#define LDG_CHUNK(c) do { int k0 = (c) << 5;                                               \
    _Pragma("unroll")                                                                      \
    for (int i = 0; i < 2; i++) { int idx = tid + i * 256; int r = idx >> 2, f = idx & 3;  \
        ra[i] = __ldg((const uint4*)(A + (size_t)(bm + r) * sA + k0 + f * 8)); }           \
    _Pragma("unroll")                                                                      \
    for (int i = 0; i < 2; i++) { int idx = tid + i * 256; int r = idx >> 2, f = idx & 3;  \
        rb[i] = __ldg((const uint4*)(B + (size_t)(bn + r) * sB + k0 + f * 8)); } } while (0)

#define STS_CHUNK(bf_) do {                                                                \
    unsigned* Aw = dsm + (bf_) * ASZ;                                                      \
    unsigned* Bw = dsm + 2 * ASZ + (bf_) * BSZ;                                            \
    _Pragma("unroll")                                                                      \
    for (int i = 0; i < 2; i++) { int idx = tid + i * 256; int r = idx >> 2, f = idx & 3;  \
        *(uint4*)&Aw[r * 20 + f * 4] = ra[i]; }                                            \
    _Pragma("unroll")                                                                      \
    for (int i = 0; i < 2; i++) { int idx = tid + i * 256; int r = idx >> 2, f = idx & 3;  \
        *(uint4*)&Bw[r * 20 + f * 4] = rb[i]; } } while (0)

    LDG_CHUNK(0);
    STS_CHUNK(0);
    __syncthreads();

    for (int c = 0; c < NC; c++) {
        int buf = c & 1;
        if (c + 1 < NC) LDG_CHUNK(c + 1);

        const unsigned* Ab = dsm + buf * ASZ;
        const unsigned* Bb = dsm + 2 * ASZ + buf * BSZ;
        #pragma unroll
        for (int ks = 0; ks < 2; ks++) {
            int kk = ks * 8 + lt;
            unsigned af[4][4], bfr[4][2];
            #pragma unroll
            for (int ma = 0; ma < 4; ma++) {
                int r = wm * 64 + ma * 16 + lg;
                af[ma][0] = Ab[r * 20 + kk];
                af[ma][1] = Ab[(r + 8) * 20 + kk];
                af[ma][2] = Ab[r * 20 + kk + 4];
                af[ma][3] = Ab[(r + 8) * 20 + kk + 4];
            }
            #pragma unroll
            for (int na = 0; na < 4; na++) {
                int n = wn * 32 + na * 8 + lg;
                bfr[na][0] = Bb[n * 20 + kk];
                bfr[na][1] = Bb[n * 20 + kk + 4];
            }
            #pragma unroll
            for (int ma = 0; ma < 4; ma++)
                #pragma unroll
                for (int na = 0; na < 4; na++)
                    mma_bf16(acc[ma][na], af[ma], bfr[na]);
        }

        if (c + 1 < NC) {
            STS_CHUNK(buf ^ 1);
            __syncthreads();
        }
    }

    // Epilogue
    #pragma unroll
    for (int ma = 0; ma < 4; ma++) {
        #pragma unroll
        for (int na = 0; na < 4; na++) {
            int row = bm + wm * 64 + ma * 16 + lg;
            int col = bn + wn * 32 + na * 8 + 2 * lt;
            #pragma unroll
            for (int half = 0; half < 2; half++) {
                int r = row + half * 8;
                float v0 = acc[ma][na][half * 2 + 0];
                float v1 = acc[ma][na][half * 2 + 1];
                if (BIAS) { v0 += bias[col]; v1 += bias[col + 1]; }
                if (GELU_) { v0 = gelu_f(v0); v1 = gelu_f(v1); }
                if (RES) {
                    const float* rp = Res + (size_t)r * sC + col;
                    v0 += rp[0]; v1 += rp[1];
                }
                if (OBF) {
                    *(unsigned*)((bf16*)Cv + (size_t)r * sC + col) = pk2(v0, v1);
                } else {
                    *(float2*)((float*)Cv + (size_t)r * sC + col) = make_float2(v0, v1);
                }
            }
        }
    }
#undef LDG_CHUNK
#undef STS_CHUNK
}

// ---------------------------------------------------------------------------
// Flash attention: per (b,h), i-tile of 128 rows, online softmax over 16
// j-tiles of 64. 256 threads, 8 warps x 16 rows. bf16 in, bf16 out.
// ---------------------------------------------------------------------------
__global__ void __launch_bounds__(256)
k_flash(const bf16* __restrict__ qkv, bf16* __restrict__ ao)
{
    __shared__ __align__(16) unsigned Qs[128 * 36];
    __shared__ __align__(16) unsigned Ks[64 * 36];
    __shared__ __align__(16) unsigned Vt[64 * 36];

    int tid = threadIdx.x;
    int wid = tid >> 5, lane = tid & 31;
    int lg = lane >> 2, lt = lane & 3;
    int bh = blockIdx.y, b = bh >> 3, h = bh & 7;
    int i0 = blockIdx.x * 128;

    const bf16* base = qkv + (size_t)b * cNW * 1536;
    const bf16* Qg = base + h * 64;
    const bf16* Kg = base + 512 + h * 64;
    const bf16* Vg = base + 1024 + h * 64;

    // Load Q tile (128 x 64 bf16)
    #pragma unroll
    for (int i = 0; i < 4; i++) {
        int idx = tid + i * 256;
        int r = idx >> 3, f = idx & 7;
        uint4 v = __ldg((const uint4*)(Qg + (size_t)(i0 + r) * 1536 + f * 8));
        *(uint4*)&Qs[r * 36 + f * 4] = v;
    }

    float m0 = -1e30f, m1 = -1e30f, l0 = 0.f, l1 = 0.f;
    float o[8][4] = {};
    int qrow = wid * 16 + lg;

    for (int jt = 0; jt < 16; jt++) {
        int j0 = jt * 64;
        __syncthreads();   // previous Ks/Vt consumed; Q ready (first iter)
        #pragma unroll
        for (int i = 0; i < 2; i++) {
            int idx = tid + i * 256;
            int r = idx >> 3, f = idx & 7;
            uint4 v = __ldg((const uint4*)(Kg + (size_t)(j0 + r) * 1536 + f * 8));
            *(uint4*)&Ks[r * 36 + f * 4] = v;
        }
        unsigned short* vt16 = (unsigned short*)Vt;
        #pragma unroll
        for (int i = 0; i < 2; i++) {
            int idx = tid + i * 256;
            int r = idx >> 3, f = idx & 7;      // r = j local, f = d group
            uint4 v = __ldg((const uint4*)(Vg + (size_t)(j0 + r) * 1536 + f * 8));
            unsigned short* ve = (unsigned short*)&v;
            #pragma unroll
            for (int e = 0; e < 8; e++)
                vt16[(f * 8 + e) * 72 + r] = ve[e];
        }
        __syncthreads();

        // S = Q @ K^T
        float sacc[8][4] = {};
        #pragma unroll
        for (int ks = 0; ks < 4; ks++) {
            int kk = ks * 8 + lt;
            unsigned af[4];
            af[0] = Qs[qrow * 36 + kk];
            af[1] = Qs[(qrow + 8) * 36 + kk];
            af[2] = Qs[qrow * 36 + kk + 4];
            af[3] = Qs[(qrow + 8) * 36 + kk + 4];
            #pragma unroll
            for (int na = 0; na < 8; na++) {
                int n = na * 8 + lg;
                unsigned bfr[2] = { Ks[n * 36 + kk], Ks[n * 36 + kk + 4] };
                mma_bf16(sacc[na], af, bfr);
            }
        }

        // scale + row stats
        float mx0 = -1e30f, mx1 = -1e30f;
        #pragma unroll
        for (int na = 0; na < 8; na++) {
            #pragma unroll
            for (int c2 = 0; c2 < 4; c2++) sacc[na][c2] *= cSCALE;
            mx0 = fmaxf(mx0, fmaxf(sacc[na][0], sacc[na][1]));
            mx1 = fmaxf(mx1, fmaxf(sacc[na][2], sacc[na][3]));
        }
        #pragma unroll
        for (int o2 = 1; o2 < 4; o2 <<= 1) {
            mx0 = fmaxf(mx0, __shfl_xor_sync(0xffffffffu, mx0, o2));
            mx1 = fmaxf(mx1, __shfl_xor_sync(0xffffffffu, mx1, o2));
        }
        float nm0 = fmaxf(m0, mx0), nm1 = fmaxf(m1, mx1);
        float cr0 = __expf(m0 - nm0), cr1 = __expf(m1 - nm1);
        m0 = nm0; m1 = nm1;

        float sum0 = 0.f, sum1 = 0.f;
        #pragma unroll
        for (int na = 0; na < 8; na++) {
            sacc[na][0] = __expf(sacc[na][0] - nm0);
            sacc[na][1] = __expf(sacc[na][1] - nm0);
            sacc[na][2] = __expf(sacc[na][2] - nm1);
            sacc[na][3] = __expf(sacc[na][3] - nm1);
            sum0 += sacc[na][0] + sacc[na][1];
            sum1 += sacc[na][2] + sacc[na][3];
        }
        #pragma unroll
        for (int o2 = 1; o2 < 4; o2 <<= 1) {
            sum0 += __shfl_xor_sync(0xffffffffu, sum0, o2);
            sum1 += __shfl_xor_sync(0xffffffffu, sum1, o2);
        }
        l0 = l0 * cr0 + sum0;
        l1 = l1 * cr1 + sum1;
        #pragma unroll
        for (int na = 0; na < 8; na++) {
            o[na][0] *= cr0; o[na][1] *= cr0;
            o[na][2] *= cr1; o[na][3] *= cr1;
        }

        // O += P @ V  (P acc-layout -> A-fragment repack)
        #pragma unroll
        for (int ks = 0; ks < 4; ks++) {
            unsigned pa[4];
            pa[0] = pk2(sacc[2*ks][0],   sacc[2*ks][1]);
            pa[1] = pk2(sacc[2*ks][2],   sacc[2*ks][3]);
            pa[2] = pk2(sacc[2*ks+1][0], sacc[2*ks+1][1]);
            pa[3] = pk2(sacc[2*ks+1][2], sacc[2*ks+1][3]);
            int kk = ks * 8 + lt;
            #pragma unroll
            for (int na = 0; na < 8; na++) {
                int n = na * 8 + lg;
                unsigned bfr[2] = { Vt[n * 36 + kk], Vt[n * 36 + kk + 4] };
                mma_bf16(o[na], pa, bfr);
            }
        }
    }

    float inv0 = 1.f / l0, inv1 = 1.f / l1;
    bf16* aoG = ao + ((size_t)b * cNW + i0) * cD + h * 64;
    #pragma unroll
    for (int na = 0; na < 8; na++) {
        int col = na * 8 + 2 * lt;
        *(unsigned*)(aoG + (size_t)qrow * cD + col)       = pk2(o[na][0] * inv0, o[na][1] * inv0);
        *(unsigned*)(aoG + (size_t)(qrow + 8) * cD + col) = pk2(o[na][2] * inv1, o[na][3] * inv1);
    }
}

// ---------------------------------------------------------------------------
// Weight transpose fp32 -> bf16 [N][K], grid.z = layer
// ---------------------------------------------------------------------------
__global__ void k_wt(const float* __restrict__ in, bf16* __restrict__ out,
                     int R, int Cc, long long inL, long long outL) {
    __shared__ float t[32][33];
    in  += (size_t)blockIdx.z * inL;
    out += (size_t)blockIdx.z * outL;
    int c0 = blockIdx.x * 32, r0 = blockIdx.y * 32;
    #pragma unroll
    for (int i = 0; i < 4; i++)
        t[threadIdx.y + i * 8][threadIdx.x] = in[(size_t)(r0 + threadIdx.y + i * 8) * Cc + c0 + threadIdx.x];
    __syncthreads();
    #pragma unroll
    for (int i = 0; i < 4; i++)
        out[(size_t)(c0 + threadIdx.y + i * 8) * R + r0 + threadIdx.x] =
            __float2bfloat16(t[threadIdx.x][threadIdx.y + i * 8]);
}

// ---------------------------------------------------------------------------
// Reductions
// ---------------------------------------------------------------------------
template<int NWARPS>
DEV_INLINE void block_sum2(float& s, float& s2) {
    #pragma unroll
    for (int o = 16; o > 0; o >>= 1) {
        s  += __shfl_down_sync(0xffffffffu, s,  o);
        s2 += __shfl_down_sync(0xffffffffu, s2, o);
    }
    __shared__ float sh_a[NWARPS], sh_b[NWARPS];
    int w = threadIdx.x >> 5;
    if ((threadIdx.x & 31) == 0) { sh_a[w] = s; sh_b[w] = s2; }
    __syncthreads();
    if (threadIdx.x == 0) {
        float a = sh_a[0], b = sh_b[0];
        #pragma unroll
        for (int i = 1; i < NWARPS; i++) { a += sh_a[i]; b += sh_b[i]; }
        sh_a[0] = a; sh_b[0] = b;
    }
    __syncthreads();
    s = sh_a[0]; s2 = sh_b[0];
}

// ---------------------------------------------------------------------------
// Flags / embed / ln / output
// ---------------------------------------------------------------------------
__global__ void k_zeroflags() {
    int i = blockIdx.x * blockDim.x + threadIdx.x;
    if (i < cT) g_mflag[i] = 0;
}
__global__ void k_setflags(const int* __restrict__ mask_idx) {
    int i = blockIdx.x * blockDim.x + threadIdx.x;
    if (i < cB * cK) g_mflag[(i / cK) * cNW + mask_idx[i]] = 1;
}

__global__ void __launch_bounds__(128) k_embed(
    const float* __restrict__ seq, const float* __restrict__ pos_emb,
    const float* __restrict__ mtok,
    const float* __restrict__ p1g, const float* __restrict__ p1b,
    const float* __restrict__ W_emb, const float* __restrict__ b_emb,
    const float* __restrict__ p2g, const float* __restrict__ p2b)
{
    int tok = blockIdx.x;
    int w = tok & (cNW - 1);
    int t = threadIdx.x;
    const float* pos = pos_emb + (size_t)(w + 1) * cD;
    float* out = g_x + (size_t)tok * cD;

    if (g_mflag[tok]) {
        #pragma unroll
        for (int j = 0; j < 4; j++) { int d = t + j * 128; out[d] = mtok[d] + pos[d]; }
        return;
    }
    __shared__ float wsm[32];
    __shared__ float lnw[32];
    const float* wrow = seq + (size_t)tok * 32;
    if (t < 32) wsm[t] = wrow[t];
    __syncthreads();
    float m = 0.f;
    #pragma unroll
    for (int c = 0; c < 32; c++) m += wsm[c];
    m *= (1.f / 32.f);
    float v = 0.f;
    #pragma unroll
    for (int c = 0; c < 32; c++) { float d0 = wsm[c] - m; v += d0 * d0; }
    v *= (1.f / 32.f);
    float rs = rsqrtf(v + 1e-5f);
    if (t < 32) lnw[t] = (wsm[t] - m) * rs * p1g[t] + p1b[t];
    __syncthreads();
    float acc[4];
    #pragma unroll
    for (int j = 0; j < 4; j++) {
        int d = t + j * 128;
        float a = b_emb[d];
        #pragma unroll
        for (int c = 0; c < 32; c++) a += lnw[c] * W_emb[c * cD + d];
        acc[j] = a;
    }
    float s = 0.f, s2 = 0.f;
    #pragma unroll
    for (int j = 0; j < 4; j++) { s += acc[j]; s2 += acc[j] * acc[j]; }
    block_sum2<4>(s, s2);
    float mean = s * (1.f / cD);
    float var  = s2 * (1.f / cD) - mean * mean;
    float rstd = rsqrtf(var + 1e-5f);
    #pragma unroll
    for (int j = 0; j < 4; j++) {
        int d = t + j * 128;
        out[d] = (acc[j] - mean) * rstd * p2g[d] + p2b[d] + pos[d];
    }
}

template<bool OBF>
__global__ void __launch_bounds__(128) k_ln(
    const float* __restrict__ x, const float* __restrict__ g,
    const float* __restrict__ bt, void* __restrict__ y)
{
    int row = blockIdx.x;
    int t = threadIdx.x;
    const float4* xr = (const float4*)(x + (size_t)row * cD);
    float4 a = xr[t];
    float s  = a.x + a.y + a.z + a.w;
    float s2 = a.x*a.x + a.y*a.y + a.z*a.z + a.w*a.w;
    block_sum2<4>(s, s2);
    float mean = s * (1.f / cD);
    float var  = s2 * (1.f / cD) - mean * mean;
    float rstd = rsqrtf(var + 1e-5f);
    float4 gg = ((const float4*)g)[t];
    float4 bb = ((const float4*)bt)[t];
    float4 o;
    o.x = (a.x - mean) * rstd * gg.x + bb.x;
    o.y = (a.y - mean) * rstd * gg.y + bb.y;
    o.z = (a.z - mean) * rstd * gg.z + bb.z;
    o.w = (a.w - mean) * rstd * gg.w + bb.w;
    if (OBF) {
        uint2 u = make_uint2(pk2(o.x, o.y), pk2(o.z, o.w));
        *(uint2*)((bf16*)y + (size_t)row * cD + t * 4) = u;
    } else {
        ((float4*)((float*)y + (size_t)row * cD))[t] = o;
    }
}

__global__ void __launch_bounds__(256) k_output(
    const float* __restrict__ seq, const int* __restrict__ mask_idx,
    const float* __restrict__ Ww, const float* __restrict__ bw,
    float* __restrict__ out, long long out_size)
{
    int b = blockIdx.y, k = blockIdx.x;
    int idx = mask_idx[b * cK + k];
    const float* enc = g_h + ((size_t)b * cNW + idx) * cD;
    __shared__ float es[cD];
    __shared__ float lgt[32];
    int t = threadIdx.x;
    ((float2*)es)[t] = ((const float2*)enc)[t];
    __syncthreads();
    int lg = t >> 3, sg = t & 7;
    float part = 0.f;
    #pragma unroll
    for (int c = 0; c < 64; c++) {
        int cc = sg * 64 + c;
        part += es[cc] * Ww[cc * 32 + lg];
    }
    part += __shfl_down_sync(0xffffffffu, part, 4);
    part += __shfl_down_sync(0xffffffffu, part, 2);
    part += __shfl_down_sync(0xffffffffu, part, 1);
    if (sg == 0) lgt[lg] = part + bw[lg];
    __syncthreads();
    size_t base = (size_t)b * cK + k;
    if (t < 8) {
        float l0 = lgt[t*4+0], l1 = lgt[t*4+1], l2 = lgt[t*4+2], l3 = lgt[t*4+3];
        float mx = fmaxf(fmaxf(l0, l1), fmaxf(l2, l3));
        float e0 = expf(l0 - mx), e1 = expf(l1 - mx), e2 = expf(l2 - mx), e3 = expf(l3 - mx);
        float inv = 1.f / (e0 + e1 + e2 + e3);
        size_t off = base * 32 + t * 4;
        if ((long long)(off + 3) < out_size) {
            out[off+0] = e0*inv; out[off+1] = e1*inv; out[off+2] = e2*inv; out[off+3] = e3*inv;
        }
    }
    if (t < 32) {
        size_t off = (size_t)cB * cK * 32 + base * 32 + t;
        if ((long long)off < out_size)
            out[off] = seq[((size_t)b * cNW + idx) * 32 + t];
    }
}

// ---------------------------------------------------------------------------
// Launch
// ---------------------------------------------------------------------------
extern "C" void kernel_launch(void* const* d_in, const int* in_sizes, int n_in,
                              void* d_out, int out_size)
{
    const float* seq      = (const float*)d_in[0];
    const int*   mask_idx = (const int*)  d_in[1];
    const float* pos_emb  = (const float*)d_in[2];
    const float* mtok     = (const float*)d_in[3];
    const float* p1g      = (const float*)d_in[4];
    const float* p1b      = (const float*)d_in[5];
    const float* W_emb    = (const float*)d_in[6];
    const float* b_emb    = (const float*)d_in[7];
    const float* p2g      = (const float*)d_in[8];
    const float* p2b      = (const float*)d_in[9];
    const float* alng     = (const float*)d_in[10];
    const float* alnb     = (const float*)d_in[11];
    const float* Wqkv     = (const float*)d_in[12];
    const float* Wo       = (const float*)d_in[13];
    const float* flng     = (const float*)d_in[14];
    const float* flnb     = (const float*)d_in[15];
    const float* W1       = (const float*)d_in[16];
    const float* b1       = (const float*)d_in[17];
    const float* W2       = (const float*)d_in[18];
    const float* b2       = (const float*)d_in[19];
    const float* olng     = (const float*)d_in[20];
    const float* olnb     = (const float*)d_in[21];
    const float* Ww       = (const float*)d_in[22];
    const float* bw       = (const float*)d_in[23];
    float* out = (float*)d_out;
    (void)in_sizes; (void)n_in;

    float *px, *ph;
    bf16 *phh, *pqkvh, *paoh, *pffh, *pwTh;
    cudaGetSymbolAddress((void**)&px,    g_x);
    cudaGetSymbolAddress((void**)&ph,    g_h);
    cudaGetSymbolAddress((void**)&phh,   g_hh);
    cudaGetSymbolAddress((void**)&pqkvh, g_qkvh);
    cudaGetSymbolAddress((void**)&paoh,  g_aoh);
    cudaGetSymbolAddress((void**)&pffh,  g_ffh);
    cudaGetSymbolAddress((void**)&pwTh,  g_wTh);

    k_zeroflags<<<cT / 256, 256>>>();
    k_setflags<<<(cB * cK) / 256, 256>>>(mask_idx);
    k_embed<<<cT, 128>>>(seq, pos_emb, mtok, p1g, p1b, W_emb, b_emb, p2g, p2b);

    // transpose all weights to bf16 [N][K], all layers at once (grid.z)
    const long long LSTR = 3145728;
    k_wt<<<dim3(1536/32, 512/32, cL), dim3(32,8)>>>(Wqkv, pwTh,            512, 1536, 786432,  LSTR);
    k_wt<<<dim3( 512/32, 512/32, cL), dim3(32,8)>>>(Wo,   pwTh + 786432,   512,  512, 262144,  LSTR);
    k_wt<<<dim3(2048/32, 512/32, cL), dim3(32,8)>>>(W1,   pwTh + 1048576,  512, 2048, 1048576, LSTR);
    k_wt<<<dim3( 512/32,2048/32, cL), dim3(32,8)>>>(W2,   pwTh + 2097152, 2048,  512, 1048576, LSTR);

    for (int l = 0; l < cL; l++) {
        bf16* baseT = pwTh + (size_t)l * LSTR;
        bf16* WqkvT = baseT;
        bf16* WoT   = baseT + 786432;
        bf16* W1T   = baseT + 1048576;
        bf16* W2T   = baseT + 2097152;

        // attention
        k_ln<true><<<cT, 128>>>(px, alng + l*cD, alnb + l*cD, phh);
        k_tgemm<false,false,false,true><<<dim3(12, 64), 256>>>(
            phh, WqkvT, nullptr, nullptr, pqkvh, 512, 512, 512, 1536);
        k_flash<<<dim3(8, 64), 256>>>(pqkvh, paoh);
        k_tgemm<false,true,false,false><<<dim3(4, 64), 256>>>(
            paoh, WoT, nullptr, px, px, 512, 512, 512, 512);

        // ffn
        k_ln<true><<<cT, 128>>>(px, flng + l*cD, flnb + l*cD, phh);
        k_tgemm<true,false,true,true><<<dim3(16, 64), 256>>>(
            phh, W1T, b1 + (size_t)l*cFF, nullptr, pffh, 512, 512, 512, 2048);
        k_tgemm<true,true,false,false><<<dim3(4, 64), 256>>>(
            pffh, W2T, b2 + (size_t)l*cD, px, px, 2048, 2048, 2048, 512);
    }

    k_ln<false><<<cT, 128>>>(px, olng, olnb, ph);
    k_output<<<dim3(cK, cB), 256>>>(seq, mask_idx, Ww, bw, out, (long long)out_size);
}

// round 6
// speedup vs baseline: 5.0585x; 1.0204x over previous
#include <cuda_runtime.h>
#include <cuda_bf16.h>

#define DEV_INLINE __device__ __forceinline__

// Problem constants
constexpr int cB  = 8;
constexpr int cNW = 1024;
constexpr int cD  = 512;
constexpr int cH  = 8;
constexpr int cL  = 4;
constexpr int cFF = 2048;
constexpr int cK  = 512;
constexpr int cT  = cB * cNW;        // 8192 tokens
constexpr float cSCALE = 0.125f;

typedef __nv_bfloat16 bf16;

// ---------------------------------------------------------------------------
// Scratch
// ---------------------------------------------------------------------------
__device__ float g_x   [cT * cD];           // residual (fp32)
__device__ float g_h   [cT * cD];           // final LN out (fp32)
__device__ bf16  g_hh  [cT * cD];           // LN out bf16
__device__ bf16  g_qkvh[cT * 3 * cD];       // qkv bf16
__device__ bf16  g_aoh [cT * cD];           // attn out bf16
__device__ bf16  g_ffh [cT * cFF];          // ffn hidden bf16
__device__ bf16  g_wTh [12582912];          // transposed weights bf16
__device__ int   g_mflag[cT];

// ---------------------------------------------------------------------------
// Helpers
// ---------------------------------------------------------------------------
DEV_INLINE float gelu_f(float x) {
    float z = 0.7978845608028654f * (x + 0.044715f * x * x * x);
    float t = __expf(2.0f * z);
    float th = 1.0f - 2.0f / (t + 1.0f);
    return 0.5f * x * (1.0f + th);
}

DEV_INLINE unsigned pk2(float lo, float hi) {
    unsigned u;
    asm("cvt.rn.bf16x2.f32 %0, %1, %2;" : "=r"(u) : "f"(hi), "f"(lo));
    return u;
}

DEV_INLINE void mma_bf16(float* d, const unsigned* a, const unsigned* b) {
    asm volatile(
        "mma.sync.aligned.m16n8k16.row.col.f32.bf16.bf16.f32 "
        "{%0,%1,%2,%3}, {%4,%5,%6,%7}, {%8,%9}, {%0,%1,%2,%3};"
        : "+f"(d[0]), "+f"(d[1]), "+f"(d[2]), "+f"(d[3])
        : "r"(a[0]), "r"(a[1]), "r"(a[2]), "r"(a[3]), "r"(b[0]), "r"(b[1]));
}

DEV_INLINE void cp16(unsigned dst, const void* src) {
    asm volatile("cp.async.cg.shared.global [%0], [%1], 16;" :: "r"(dst), "l"(src));
}
#define CP_COMMIT() asm volatile("cp.async.commit_group;" ::: "memory")
#define CP_WAIT1()  asm volatile("cp.async.wait_group 1;" ::: "memory")

// ---------------------------------------------------------------------------
// bf16 tensor-core GEMM with 3-stage cp.async pipeline.
// C[M,N] = A[M,K] @ B[N,K]^T (+bias)(gelu)(+Res)
// BM=128, BN=128, BK=32, 256 threads (8 warps: 2m x 4n), warp 64x32.
// SMEM rows of 20 u32 (16 data + 4 pad) -> conflict-free fragment loads.
// ---------------------------------------------------------------------------
template<bool BIAS, bool RES, bool GELU_, bool OBF>
__global__ void __launch_bounds__(256)
k_tgemm(const bf16* __restrict__ A, const bf16* __restrict__ B,
        const float* __restrict__ bias, const float* __restrict__ Res,
        void* __restrict__ Cv, int K, int sA, int sB, int sC)
{
    extern __shared__ __align__(16) unsigned dsm[];
    constexpr int ASZ = 128 * 20;
    constexpr int BSZ = 128 * 20;

    int tid = threadIdx.x;
    int wid = tid >> 5, lane = tid & 31;
    int wm = wid & 1, wn = wid >> 1;
    int lg = lane >> 2, lt = lane & 3;

    int bm = blockIdx.y * 128, bn = blockIdx.x * 128;
    unsigned smemU = (unsigned)__cvta_generic_to_shared(dsm);

    const int NC = K >> 5;
    float acc[4][4][4] = {};

    int pr = tid >> 2, pf = tid & 3;                 // prefetch row/frag
    const bf16* Apre = A + (size_t)(bm + pr) * sA + pf * 8;
    const bf16* Bpre = B + (size_t)(bn + pr) * sB + pf * 8;
    unsigned adst = smemU + (pr * 20 + pf * 4) * 4;
    unsigned bdst = smemU + (3 * ASZ + pr * 20 + pf * 4) * 4;

#define PRE(s, c) do { int k0 = (c) << 5;                                     \
    cp16(adst + (s) * ASZ * 4, Apre + k0);                                    \
    cp16(adst + (s) * ASZ * 4 + 64 * 20 * 4, Apre + (size_t)64 * sA + k0);    \
    cp16(bdst + (s) * BSZ * 4, Bpre + k0);                                    \
    cp16(bdst + (s) * BSZ * 4 + 64 * 20 * 4, Bpre + (size_t)64 * sB + k0);    \
    CP_COMMIT(); } while (0)

    PRE(0, 0);
    PRE(1, 1);

    for (int c = 0; c < NC; c++) {
        CP_WAIT1();
        __syncthreads();

        int st = c % 3;
        const unsigned* Ab = dsm + st * ASZ;
        const unsigned* Bb = dsm + 3 * ASZ + st * BSZ;
        #pragma unroll
        for (int ks = 0; ks < 2; ks++) {
            int kk = ks * 8 + lt;
            unsigned af[4][4], bfr[4][2];
            #pragma unroll
            for (int ma = 0; ma < 4; ma++) {
                int r = wm * 64 + ma * 16 + lg;
                af[ma][0] = Ab[r * 20 + kk];
                af[ma][1] = Ab[(r + 8) * 20 + kk];
                af[ma][2] = Ab[r * 20 + kk + 4];
                af[ma][3] = Ab[(r + 8) * 20 + kk + 4];
            }
            #pragma unroll
            for (int na = 0; na < 4; na++) {
                int n = wn * 32 + na * 8 + lg;
                bfr[na][0] = Bb[n * 20 + kk];
                bfr[na][1] = Bb[n * 20 + kk + 4];
            }
            #pragma unroll
            for (int ma = 0; ma < 4; ma++)
                #pragma unroll
                for (int na = 0; na < 4; na++)
                    mma_bf16(acc[ma][na], af[ma], bfr[na]);
        }
        __syncthreads();
        if (c + 2 < NC) PRE((c + 2) % 3, c + 2);
    }

    // Epilogue
    #pragma unroll
    for (int ma = 0; ma < 4; ma++) {
        #pragma unroll
        for (int na = 0; na < 4; na++) {
            int row = bm + wm * 64 + ma * 16 + lg;
            int col = bn + wn * 32 + na * 8 + 2 * lt;
            #pragma unroll
            for (int half = 0; half < 2; half++) {
                int r = row + half * 8;
                float v0 = acc[ma][na][half * 2 + 0];
                float v1 = acc[ma][na][half * 2 + 1];
                if (BIAS) { v0 += bias[col]; v1 += bias[col + 1]; }
                if (GELU_) { v0 = gelu_f(v0); v1 = gelu_f(v1); }
                if (RES) {
                    const float* rp = Res + (size_t)r * sC + col;
                    v0 += rp[0]; v1 += rp[1];
                }
                if (OBF) {
                    *(unsigned*)((bf16*)Cv + (size_t)r * sC + col) = pk2(v0, v1);
                } else {
                    *(float2*)((float*)Cv + (size_t)r * sC + col) = make_float2(v0, v1);
                }
            }
        }
    }
#undef PRE
}

// ---------------------------------------------------------------------------
// Flash attention: per (b,h), i-tile of 128 rows, online softmax over 16
// j-tiles of 64. 256 threads, 8 warps x 16 rows. Double-buffered K/V with
// register prefetch (LDG overlapped with compute). bf16 in/out.
// ---------------------------------------------------------------------------
__global__ void __launch_bounds__(256)
k_flash(const bf16* __restrict__ qkv, bf16* __restrict__ ao)
{
    extern __shared__ __align__(16) unsigned fsm[];
    unsigned* Qs = fsm;                   // 128*36
    unsigned* Ks = fsm + 4608;            // 2 x 64*36
    unsigned* Vt = fsm + 4608 + 4608;     // 2 x 64*36

    int tid = threadIdx.x;
    int wid = tid >> 5, lane = tid & 31;
    int lg = lane >> 2, lt = lane & 3;
    int bh = blockIdx.y, b = bh >> 3, h = bh & 7;
    int i0 = blockIdx.x * 128;

    const bf16* base = qkv + (size_t)b * cNW * 1536;
    const bf16* Qg = base + h * 64;
    const bf16* Kg = base + 512 + h * 64;
    const bf16* Vg = base + 1024 + h * 64;

    // Load Q tile (128 x 64 bf16)
    #pragma unroll
    for (int i = 0; i < 4; i++) {
        int idx = tid + i * 256;
        int r = idx >> 3, f = idx & 7;
        uint4 v = __ldg((const uint4*)(Qg + (size_t)(i0 + r) * 1536 + f * 8));
        *(uint4*)&Qs[r * 36 + f * 4] = v;
    }

    int pr = tid >> 3, pf = tid & 7;      // prefetch row (0..31), frag (0..7)
    uint4 kr[2], vr[2];

#define LDGKV(jt) do { int j0 = (jt) * 64;                                               \
    kr[0] = __ldg((const uint4*)(Kg + (size_t)(j0 + pr) * 1536 + pf * 8));               \
    kr[1] = __ldg((const uint4*)(Kg + (size_t)(j0 + pr + 32) * 1536 + pf * 8));          \
    vr[0] = __ldg((const uint4*)(Vg + (size_t)(j0 + pr) * 1536 + pf * 8));               \
    vr[1] = __ldg((const uint4*)(Vg + (size_t)(j0 + pr + 32) * 1536 + pf * 8)); } while (0)

#define STSKV(bf_) do {                                                                  \
    unsigned* Kb = Ks + (bf_) * 2304;                                                    \
    unsigned short* vt16 = (unsigned short*)(Vt + (bf_) * 2304);                         \
    *(uint4*)&Kb[pr * 36 + pf * 4]        = kr[0];                                       \
    *(uint4*)&Kb[(pr + 32) * 36 + pf * 4] = kr[1];                                       \
    _Pragma("unroll")                                                                    \
    for (int e = 0; e < 8; e++) {                                                        \
        vt16[(pf * 8 + e) * 72 + pr]      = ((unsigned short*)&vr[0])[e];                \
        vt16[(pf * 8 + e) * 72 + pr + 32] = ((unsigned short*)&vr[1])[e];                \
    } } while (0)

    LDGKV(0);
    STSKV(0);
    __syncthreads();

    float m0 = -1e30f, m1 = -1e30f, l0 = 0.f, l1 = 0.f;
    float o[8][4] = {};
    int qrow = wid * 16 + lg;

    for (int jt = 0; jt < 16; jt++) {
        int buf = jt & 1;
        if (jt + 1 < 16) LDGKV(jt + 1);

        const unsigned* Kb = Ks + buf * 2304;
        const unsigned* Vb = Vt + buf * 2304;

        // S = Q @ K^T
        float sacc[8][4] = {};
        #pragma unroll
        for (int ks = 0; ks < 4; ks++) {
            int kk = ks * 8 + lt;
            unsigned af[4];
            af[0] = Qs[qrow * 36 + kk];
            af[1] = Qs[(qrow + 8) * 36 + kk];
            af[2] = Qs[qrow * 36 + kk + 4];
            af[3] = Qs[(qrow + 8) * 36 + kk + 4];
            #pragma unroll
            for (int na = 0; na < 8; na++) {
                int n = na * 8 + lg;
                unsigned bfr[2] = { Kb[n * 36 + kk], Kb[n * 36 + kk + 4] };
                mma_bf16(sacc[na], af, bfr);
            }
        }

        // scale + row stats
        float mx0 = -1e30f, mx1 = -1e30f;
        #pragma unroll
        for (int na = 0; na < 8; na++) {
            #pragma unroll
            for (int c2 = 0; c2 < 4; c2++) sacc[na][c2] *= cSCALE;
            mx0 = fmaxf(mx0, fmaxf(sacc[na][0], sacc[na][1]));
            mx1 = fmaxf(mx1, fmaxf(sacc[na][2], sacc[na][3]));
        }
        #pragma unroll
        for (int o2 = 1; o2 < 4; o2 <<= 1) {
            mx0 = fmaxf(mx0, __shfl_xor_sync(0xffffffffu, mx0, o2));
            mx1 = fmaxf(mx1, __shfl_xor_sync(0xffffffffu, mx1, o2));
        }
        float nm0 = fmaxf(m0, mx0), nm1 = fmaxf(m1, mx1);
        float cr0 = __expf(m0 - nm0), cr1 = __expf(m1 - nm1);
        m0 = nm0; m1 = nm1;

        float sum0 = 0.f, sum1 = 0.f;
        #pragma unroll
        for (int na = 0; na < 8; na++) {
            sacc[na][0] = __expf(sacc[na][0] - nm0);
            sacc[na][1] = __expf(sacc[na][1] - nm0);
            sacc[na][2] = __expf(sacc[na][2] - nm1);
            sacc[na][3] = __expf(sacc[na][3] - nm1);
            sum0 += sacc[na][0] + sacc[na][1];
            sum1 += sacc[na][2] + sacc[na][3];
        }
        #pragma unroll
        for (int o2 = 1; o2 < 4; o2 <<= 1) {
            sum0 += __shfl_xor_sync(0xffffffffu, sum0, o2);
            sum1 += __shfl_xor_sync(0xffffffffu, sum1, o2);
        }
        l0 = l0 * cr0 + sum0;
        l1 = l1 * cr1 + sum1;
        #pragma unroll
        for (int na = 0; na < 8; na++) {
            o[na][0] *= cr0; o[na][1] *= cr0;
            o[na][2] *= cr1; o[na][3] *= cr1;
        }

        // O += P @ V
        #pragma unroll
        for (int ks = 0; ks < 4; ks++) {
            unsigned pa[4];
            pa[0] = pk2(sacc[2*ks][0],   sacc[2*ks][1]);
            pa[1] = pk2(sacc[2*ks][2],   sacc[2*ks][3]);
            pa[2] = pk2(sacc[2*ks+1][0], sacc[2*ks+1][1]);
            pa[3] = pk2(sacc[2*ks+1][2], sacc[2*ks+1][3]);
            int kk = ks * 8 + lt;
            #pragma unroll
            for (int na = 0; na < 8; na++) {
                int n = na * 8 + lg;
                unsigned bfr[2] = { Vb[n * 36 + kk], Vb[n * 36 + kk + 4] };
                mma_bf16(o[na], pa, bfr);
            }
        }

        if (jt + 1 < 16) {
            __syncthreads();
            STSKV(buf ^ 1);
            __syncthreads();
        }
    }

    float inv0 = 1.f / l0, inv1 = 1.f / l1;
    bf16* aoG = ao + ((size_t)b * cNW + i0) * cD + h * 64;
    #pragma unroll
    for (int na = 0; na < 8; na++) {
        int col = na * 8 + 2 * lt;
        *(unsigned*)(aoG + (size_t)qrow * cD + col)       = pk2(o[na][0] * inv0, o[na][1] * inv0);
        *(unsigned*)(aoG + (size_t)(qrow + 8) * cD + col) = pk2(o[na][2] * inv1, o[na][3] * inv1);
    }
#undef LDGKV
#undef STSKV
}

// ---------------------------------------------------------------------------
// Weight transpose fp32 -> bf16 [N][K], grid.z = layer
// ---------------------------------------------------------------------------
__global__ void k_wt(const float* __restrict__ in, bf16* __restrict__ out,
                     int R, int Cc, long long inL, long long outL) {
    __shared__ float t[32][33];
    in  += (size_t)blockIdx.z * inL;
    out += (size_t)blockIdx.z * outL;
    int c0 = blockIdx.x * 32, r0 = blockIdx.y * 32;
    #pragma unroll
    for (int i = 0; i < 4; i++)
        t[threadIdx.y + i * 8][threadIdx.x] = in[(size_t)(r0 + threadIdx.y + i * 8) * Cc + c0 + threadIdx.x];
    __syncthreads();
    #pragma unroll
    for (int i = 0; i < 4; i++)
        out[(size_t)(c0 + threadIdx.y + i * 8) * R + r0 + threadIdx.x] =
            __float2bfloat16(t[threadIdx.x][threadIdx.y + i * 8]);
}

// ---------------------------------------------------------------------------
// Reductions
// ---------------------------------------------------------------------------
template<int NWARPS>
DEV_INLINE void block_sum2(float& s, float& s2) {
    #pragma unroll
    for (int o = 16; o > 0; o >>= 1) {
        s  += __shfl_down_sync(0xffffffffu, s,  o);
        s2 += __shfl_down_sync(0xffffffffu, s2, o);
    }
    __shared__ float sh_a[NWARPS], sh_b[NWARPS];
    int w = threadIdx.x >> 5;
    if ((threadIdx.x & 31) == 0) { sh_a[w] = s; sh_b[w] = s2; }
    __syncthreads();
    if (threadIdx.x == 0) {
        float a = sh_a[0], b = sh_b[0];
        #pragma unroll
        for (int i = 1; i < NWARPS; i++) { a += sh_a[i]; b += sh_b[i]; }
        sh_a[0] = a; sh_b[0] = b;
    }
    __syncthreads();
    s = sh_a[0]; s2 = sh_b[0];
}

// ---------------------------------------------------------------------------
// Flags / embed / ln / output
// ---------------------------------------------------------------------------
__global__ void k_zeroflags() {
    int i = blockIdx.x * blockDim.x + threadIdx.x;
    if (i < cT) g_mflag[i] = 0;
}
__global__ void k_setflags(const int* __restrict__ mask_idx) {
    int i = blockIdx.x * blockDim.x + threadIdx.x;
    if (i < cB * cK) g_mflag[(i / cK) * cNW + mask_idx[i]] = 1;
}

__global__ void __launch_bounds__(128) k_embed(
    const float* __restrict__ seq, const float* __restrict__ pos_emb,
    const float* __restrict__ mtok,
    const float* __restrict__ p1g, const float* __restrict__ p1b,
    const float* __restrict__ W_emb, const float* __restrict__ b_emb,
    const float* __restrict__ p2g, const float* __restrict__ p2b)
{
    int tok = blockIdx.x;
    int w = tok & (cNW - 1);
    int t = threadIdx.x;
    const float* pos = pos_emb + (size_t)(w + 1) * cD;
    float* out = g_x + (size_t)tok * cD;

    if (g_mflag[tok]) {
        #pragma unroll
        for (int j = 0; j < 4; j++) { int d = t + j * 128; out[d] = mtok[d] + pos[d]; }
        return;
    }
    __shared__ float wsm[32];
    __shared__ float lnw[32];
    const float* wrow = seq + (size_t)tok * 32;
    if (t < 32) wsm[t] = wrow[t];
    __syncthreads();
    float m = 0.f;
    #pragma unroll
    for (int c = 0; c < 32; c++) m += wsm[c];
    m *= (1.f / 32.f);
    float v = 0.f;
    #pragma unroll
    for (int c = 0; c < 32; c++) { float d0 = wsm[c] - m; v += d0 * d0; }
    v *= (1.f / 32.f);
    float rs = rsqrtf(v + 1e-5f);
    if (t < 32) lnw[t] = (wsm[t] - m) * rs * p1g[t] + p1b[t];
    __syncthreads();
    float acc[4];
    #pragma unroll
    for (int j = 0; j < 4; j++) {
        int d = t + j * 128;
        float a = b_emb[d];
        #pragma unroll
        for (int c = 0; c < 32; c++) a += lnw[c] * W_emb[c * cD + d];
        acc[j] = a;
    }
    float s = 0.f, s2 = 0.f;
    #pragma unroll
    for (int j = 0; j < 4; j++) { s += acc[j]; s2 += acc[j] * acc[j]; }
    block_sum2<4>(s, s2);
    float mean = s * (1.f / cD);
    float var  = s2 * (1.f / cD) - mean * mean;
    float rstd = rsqrtf(var + 1e-5f);
    #pragma unroll
    for (int j = 0; j < 4; j++) {
        int d = t + j * 128;
        out[d] = (acc[j] - mean) * rstd * p2g[d] + p2b[d] + pos[d];
    }
}

template<bool OBF>
__global__ void __launch_bounds__(128) k_ln(
    const float* __restrict__ x, const float* __restrict__ g,
    const float* __restrict__ bt, void* __restrict__ y)
{
    int row = blockIdx.x;
    int t = threadIdx.x;
    const float4* xr = (const float4*)(x + (size_t)row * cD);
    float4 a = xr[t];
    float s  = a.x + a.y + a.z + a.w;
    float s2 = a.x*a.x + a.y*a.y + a.z*a.z + a.w*a.w;
    block_sum2<4>(s, s2);
    float mean = s * (1.f / cD);
    float var  = s2 * (1.f / cD) - mean * mean;
    float rstd = rsqrtf(var + 1e-5f);
    float4 gg = ((const float4*)g)[t];
    float4 bb = ((const float4*)bt)[t];
    float4 o;
    o.x = (a.x - mean) * rstd * gg.x + bb.x;
    o.y = (a.y - mean) * rstd * gg.y + bb.y;
    o.z = (a.z - mean) * rstd * gg.z + bb.z;
    o.w = (a.w - mean) * rstd * gg.w + bb.w;
    if (OBF) {
        uint2 u = make_uint2(pk2(o.x, o.y), pk2(o.z, o.w));
        *(uint2*)((bf16*)y + (size_t)row * cD + t * 4) = u;
    } else {
        ((float4*)((float*)y + (size_t)row * cD))[t] = o;
    }
}

__global__ void __launch_bounds__(256) k_output(
    const float* __restrict__ seq, const int* __restrict__ mask_idx,
    const float* __restrict__ Ww, const float* __restrict__ bw,
    float* __restrict__ out, long long out_size)
{
    int b = blockIdx.y, k = blockIdx.x;
    int idx = mask_idx[b * cK + k];
    const float* enc = g_h + ((size_t)b * cNW + idx) * cD;
    __shared__ float es[cD];
    __shared__ float lgt[32];
    int t = threadIdx.x;
    ((float2*)es)[t] = ((const float2*)enc)[t];
    __syncthreads();
    int lg = t >> 3, sg = t & 7;
    float part = 0.f;
    #pragma unroll
    for (int c = 0; c < 64; c++) {
        int cc = sg * 64 + c;
        part += es[cc] * Ww[cc * 32 + lg];
    }
    part += __shfl_down_sync(0xffffffffu, part, 4);
    part += __shfl_down_sync(0xffffffffu, part, 2);
    part += __shfl_down_sync(0xffffffffu, part, 1);
    if (sg == 0) lgt[lg] = part + bw[lg];
    __syncthreads();
    size_t base = (size_t)b * cK + k;
    if (t < 8) {
        float l0 = lgt[t*4+0], l1 = lgt[t*4+1], l2 = lgt[t*4+2], l3 = lgt[t*4+3];
        float mx = fmaxf(fmaxf(l0, l1), fmaxf(l2, l3));
        float e0 = expf(l0 - mx), e1 = expf(l1 - mx), e2 = expf(l2 - mx), e3 = expf(l3 - mx);
        float inv = 1.f / (e0 + e1 + e2 + e3);
        size_t off = base * 32 + t * 4;
        if ((long long)(off + 3) < out_size) {
            out[off+0] = e0*inv; out[off+1] = e1*inv; out[off+2] = e2*inv; out[off+3] = e3*inv;
        }
    }
    if (t < 32) {
        size_t off = (size_t)cB * cK * 32 + base * 32 + t;
        if ((long long)off < out_size)
            out[off] = seq[((size_t)b * cNW + idx) * 32 + t];
    }
}

// ---------------------------------------------------------------------------
// Launch
// ---------------------------------------------------------------------------
extern "C" void kernel_launch(void* const* d_in, const int* in_sizes, int n_in,
                              void* d_out, int out_size)
{
    const float* seq      = (const float*)d_in[0];
    const int*   mask_idx = (const int*)  d_in[1];
    const float* pos_emb  = (const float*)d_in[2];
    const float* mtok     = (const float*)d_in[3];
    const float* p1g      = (const float*)d_in[4];
    const float* p1b      = (const float*)d_in[5];
    const float* W_emb    = (const float*)d_in[6];
    const float* b_emb    = (const float*)d_in[7];
    const float* p2g      = (const float*)d_in[8];
    const float* p2b      = (const float*)d_in[9];
    const float* alng     = (const float*)d_in[10];
    const float* alnb     = (const float*)d_in[11];
    const float* Wqkv     = (const float*)d_in[12];
    const float* Wo       = (const float*)d_in[13];
    const float* flng     = (const float*)d_in[14];
    const float* flnb     = (const float*)d_in[15];
    const float* W1       = (const float*)d_in[16];
    const float* b1       = (const float*)d_in[17];
    const float* W2       = (const float*)d_in[18];
    const float* b2       = (const float*)d_in[19];
    const float* olng     = (const float*)d_in[20];
    const float* olnb     = (const float*)d_in[21];
    const float* Ww       = (const float*)d_in[22];
    const float* bw       = (const float*)d_in[23];
    float* out = (float*)d_out;
    (void)in_sizes; (void)n_in;

    float *px, *ph;
    bf16 *phh, *pqkvh, *paoh, *pffh, *pwTh;
    cudaGetSymbolAddress((void**)&px,    g_x);
    cudaGetSymbolAddress((void**)&ph,    g_h);
    cudaGetSymbolAddress((void**)&phh,   g_hh);
    cudaGetSymbolAddress((void**)&pqkvh, g_qkvh);
    cudaGetSymbolAddress((void**)&paoh,  g_aoh);
    cudaGetSymbolAddress((void**)&pffh,  g_ffh);
    cudaGetSymbolAddress((void**)&pwTh,  g_wTh);

    const int GSM = 3 * (128 * 20 + 128 * 20) * 4;   // 61440
    const int FSM = (4608 + 2 * 2304 + 2 * 2304) * 4; // 55296
    cudaFuncSetAttribute(k_tgemm<false,false,false,true >, cudaFuncAttributeMaxDynamicSharedMemorySize, GSM);
    cudaFuncSetAttribute(k_tgemm<false,true, false,false>, cudaFuncAttributeMaxDynamicSharedMemorySize, GSM);
    cudaFuncSetAttribute(k_tgemm<true, false,true, true >, cudaFuncAttributeMaxDynamicSharedMemorySize, GSM);
    cudaFuncSetAttribute(k_tgemm<true, true, false,false>, cudaFuncAttributeMaxDynamicSharedMemorySize, GSM);
    cudaFuncSetAttribute(k_flash, cudaFuncAttributeMaxDynamicSharedMemorySize, FSM);

    k_zeroflags<<<cT / 256, 256>>>();
    k_setflags<<<(cB * cK) / 256, 256>>>(mask_idx);
    k_embed<<<cT, 128>>>(seq, pos_emb, mtok, p1g, p1b, W_emb, b_emb, p2g, p2b);

    // transpose all weights to bf16 [N][K], all layers at once (grid.z)
    const long long LSTR = 3145728;
    k_wt<<<dim3(1536/32, 512/32, cL), dim3(32,8)>>>(Wqkv, pwTh,            512, 1536, 786432,  LSTR);
    k_wt<<<dim3( 512/32, 512/32, cL), dim3(32,8)>>>(Wo,   pwTh + 786432,   512,  512, 262144,  LSTR);
    k_wt<<<dim3(2048/32, 512/32, cL), dim3(32,8)>>>(W1,   pwTh + 1048576,  512, 2048, 1048576, LSTR);
    k_wt<<<dim3( 512/32,2048/32, cL), dim3(32,8)>>>(W2,   pwTh + 2097152, 2048,  512, 1048576, LSTR);

    for (int l = 0; l < cL; l++) {
        bf16* baseT = pwTh + (size_t)l * LSTR;
        bf16* WqkvT = baseT;
        bf16* WoT   = baseT + 786432;
        bf16* W1T   = baseT + 1048576;
        bf16* W2T   = baseT + 2097152;

        // attention
        k_ln<true><<<cT, 128>>>(px, alng + l*cD, alnb + l*cD, phh);
        k_tgemm<false,false,false,true><<<dim3(12, 64), 256, GSM>>>(
            phh, WqkvT, nullptr, nullptr, pqkvh, 512, 512, 512, 1536);
        k_flash<<<dim3(8, 64), 256, FSM>>>(pqkvh, paoh);
        k_tgemm<false,true,false,false><<<dim3(4, 64), 256, GSM>>>(
            paoh, WoT, nullptr, px, px, 512, 512, 512, 512);

        // ffn
        k_ln<true><<<cT, 128>>>(px, flng + l*cD, flnb + l*cD, phh);
        k_tgemm<true,false,true,true><<<dim3(16, 64), 256, GSM>>>(
            phh, W1T, b1 + (size_t)l*cFF, nullptr, pffh, 512, 512, 512, 2048);
        k_tgemm<true,true,false,false><<<dim3(4, 64), 256, GSM>>>(
            pffh, W2T, b2 + (size_t)l*cD, px, px, 2048, 2048, 2048, 512);
    }

    k_ln<false><<<cT, 128>>>(px, olng, olnb, ph);
    k_output<<<dim3(cK, cB), 256>>>(seq, mask_idx, Ww, bw, out, (long long)out_size);
}

// round 7
// speedup vs baseline: 5.9312x; 1.1725x over previous
#include <cuda_runtime.h>
#include <cuda_bf16.h>

#define DEV_INLINE __device__ __forceinline__

// Problem constants
constexpr int cB  = 8;
constexpr int cNW = 1024;
constexpr int cD  = 512;
constexpr int cH  = 8;
constexpr int cL  = 4;
constexpr int cFF = 2048;
constexpr int cK  = 512;
constexpr int cT  = cB * cNW;        // 8192 tokens
constexpr float cSCALE = 0.125f;

typedef __nv_bfloat16 bf16;

// ---------------------------------------------------------------------------
// Scratch
// ---------------------------------------------------------------------------
__device__ float g_x   [cT * cD];           // residual (fp32)
__device__ float g_h   [cT * cD];           // final LN out (fp32)
__device__ bf16  g_hh  [cT * cD];           // LN out bf16
__device__ bf16  g_qkvh[cT * 3 * cD];       // qkv bf16
__device__ bf16  g_aoh [cT * cD];           // attn out bf16
__device__ bf16  g_ffh [cT * cFF];          // ffn hidden bf16
__device__ bf16  g_wTh [12582912];          // transposed weights bf16
__device__ int   g_mflag[cT];

// ---------------------------------------------------------------------------
// Helpers
// ---------------------------------------------------------------------------
DEV_INLINE float gelu_f(float x) {
    float z = 0.7978845608028654f * (x + 0.044715f * x * x * x);
    float t = __expf(2.0f * z);
    float th = 1.0f - 2.0f / (t + 1.0f);
    return 0.5f * x * (1.0f + th);
}

DEV_INLINE unsigned pk2(float lo, float hi) {
    unsigned u;
    asm("cvt.rn.bf16x2.f32 %0, %1, %2;" : "=r"(u) : "f"(hi), "f"(lo));
    return u;
}

DEV_INLINE void mma_bf16(float* d, const unsigned* a, const unsigned* b) {
    asm volatile(
        "mma.sync.aligned.m16n8k16.row.col.f32.bf16.bf16.f32 "
        "{%0,%1,%2,%3}, {%4,%5,%6,%7}, {%8,%9}, {%0,%1,%2,%3};"
        : "+f"(d[0]), "+f"(d[1]), "+f"(d[2]), "+f"(d[3])
        : "r"(a[0]), "r"(a[1]), "r"(a[2]), "r"(a[3]), "r"(b[0]), "r"(b[1]));
}

DEV_INLINE void ldsm4(unsigned* r, unsigned addr) {
    asm volatile("ldmatrix.sync.aligned.m8n8.x4.shared.b16 {%0,%1,%2,%3}, [%4];"
        : "=r"(r[0]), "=r"(r[1]), "=r"(r[2]), "=r"(r[3]) : "r"(addr));
}
DEV_INLINE void ldsm4t(unsigned* r, unsigned addr) {
    asm volatile("ldmatrix.sync.aligned.m8n8.x4.trans.shared.b16 {%0,%1,%2,%3}, [%4];"
        : "=r"(r[0]), "=r"(r[1]), "=r"(r[2]), "=r"(r[3]) : "r"(addr));
}

DEV_INLINE void cp16(unsigned dst, const void* src) {
    asm volatile("cp.async.cg.shared.global [%0], [%1], 16;" :: "r"(dst), "l"(src));
}
#define CP_COMMIT() asm volatile("cp.async.commit_group;" ::: "memory")
#define CP_WAIT1()  asm volatile("cp.async.wait_group 1;" ::: "memory")
#define CP_WAIT0()  asm volatile("cp.async.wait_group 0;" ::: "memory")

// ---------------------------------------------------------------------------
// bf16 tensor-core GEMM, 3-stage cp.async pipeline + ldmatrix fragments.
// C[M,N] = A[M,K] @ B[N,K]^T (+bias)(gelu)(+Res)
// BM=128, BN=128, BK=32, 256 threads (8 warps: 2m x 4n), warp 64x32.
// SMEM rows of 20 u32 (16 data + 4 pad); ldmatrix row-starts hit distinct
// 4-bank groups (20r mod 32 = {0,20,8,28,16,4,24,12}) -> conflict-free.
// ---------------------------------------------------------------------------
template<bool BIAS, bool RES, bool GELU_, bool OBF>
__global__ void __launch_bounds__(256)
k_tgemm(const bf16* __restrict__ A, const bf16* __restrict__ B,
        const float* __restrict__ bias, const float* __restrict__ Res,
        void* __restrict__ Cv, int K, int sA, int sB, int sC)
{
    extern __shared__ __align__(16) unsigned dsm[];
    constexpr int ASZ = 128 * 20;
    constexpr int BSZ = 128 * 20;

    int tid = threadIdx.x;
    int wid = tid >> 5, lane = tid & 31;
    int wm = wid & 1, wn = wid >> 1;
    int lrow = lane & 7, q = lane >> 3;
    int lg = lane >> 2, lt = lane & 3;

    int bm = blockIdx.y * 128, bn = blockIdx.x * 128;
    unsigned smemU = (unsigned)__cvta_generic_to_shared(dsm);

    const int NC = K >> 5;
    float acc[4][4][4] = {};

    int pr = tid >> 2, pf = tid & 3;                 // prefetch row/frag
    const bf16* Apre = A + (size_t)(bm + pr) * sA + pf * 8;
    const bf16* Bpre = B + (size_t)(bn + pr) * sB + pf * 8;
    unsigned adst = smemU + (pr * 20 + pf * 4) * 4;
    unsigned bdst = smemU + (3 * ASZ + pr * 20 + pf * 4) * 4;

    // ldmatrix per-thread base addresses
    unsigned aBase = smemU + (((q & 1) * 8 + lrow + wm * 64) * 20 + (q >> 1) * 4) * 4;
    unsigned bBase = smemU + (3 * ASZ + (wn * 32 + (q >> 1) * 8 + lrow) * 20 + (q & 1) * 4) * 4;

#define PRE(s, c) do { int k0 = (c) << 5;                                     \
    cp16(adst + (s) * ASZ * 4, Apre + k0);                                    \
    cp16(adst + (s) * ASZ * 4 + 64 * 20 * 4, Apre + (size_t)64 * sA + k0);    \
    cp16(bdst + (s) * BSZ * 4, Bpre + k0);                                    \
    cp16(bdst + (s) * BSZ * 4 + 64 * 20 * 4, Bpre + (size_t)64 * sB + k0);    \
    CP_COMMIT(); } while (0)

    PRE(0, 0);
    PRE(1, 1);

    for (int c = 0; c < NC; c++) {
        if (c + 1 < NC) CP_WAIT1(); else CP_WAIT0();
        __syncthreads();
        if (c + 2 < NC) PRE((c + 2) % 3, c + 2);

        int st = c % 3;
        unsigned aS = aBase + st * ASZ * 4;
        unsigned bS = bBase + st * BSZ * 4;
        #pragma unroll
        for (int ks = 0; ks < 2; ks++) {
            unsigned af[4][4], bq[2][4];
            #pragma unroll
            for (int ma = 0; ma < 4; ma++) ldsm4(af[ma], aS + (ma * 320 + ks * 8) * 4);
            #pragma unroll
            for (int nb = 0; nb < 2; nb++) ldsm4(bq[nb], bS + (nb * 320 + ks * 8) * 4);
            #pragma unroll
            for (int ma = 0; ma < 4; ma++)
                #pragma unroll
                for (int na = 0; na < 4; na++)
                    mma_bf16(acc[ma][na], af[ma], &bq[na >> 1][(na & 1) * 2]);
        }
    }

    // Epilogue
    #pragma unroll
    for (int ma = 0; ma < 4; ma++) {
        #pragma unroll
        for (int na = 0; na < 4; na++) {
            int row = bm + wm * 64 + ma * 16 + lg;
            int col = bn + wn * 32 + na * 8 + 2 * lt;
            #pragma unroll
            for (int half = 0; half < 2; half++) {
                int r = row + half * 8;
                float v0 = acc[ma][na][half * 2 + 0];
                float v1 = acc[ma][na][half * 2 + 1];
                if (BIAS) { v0 += bias[col]; v1 += bias[col + 1]; }
                if (GELU_) { v0 = gelu_f(v0); v1 = gelu_f(v1); }
                if (RES) {
                    const float* rp = Res + (size_t)r * sC + col;
                    v0 += rp[0]; v1 += rp[1];
                }
                if (OBF) {
                    *(unsigned*)((bf16*)Cv + (size_t)r * sC + col) = pk2(v0, v1);
                } else {
                    *(float2*)((float*)Cv + (size_t)r * sC + col) = make_float2(v0, v1);
                }
            }
        }
    }
#undef PRE
}

// ---------------------------------------------------------------------------
// Flash attention: per (b,h), i-tile of 128 rows, online softmax over 16
// j-tiles of 64. 256 threads, 8 warps x 16 rows. 2-stage cp.async K/V,
// ldmatrix fragments, V via ldmatrix.trans (no explicit transpose).
// ---------------------------------------------------------------------------
__global__ void __launch_bounds__(256)
k_flash(const bf16* __restrict__ qkv, bf16* __restrict__ ao)
{
    extern __shared__ __align__(16) unsigned fsm[];
    // Qs [0,4608), Ks stage s at 4608 + s*2304, Vs stage s at 9216 + s*2304

    int tid = threadIdx.x;
    int wid = tid >> 5, lane = tid & 31;
    int lrow = lane & 7, q = lane >> 3;
    int lg = lane >> 2, lt = lane & 3;
    int bh = blockIdx.y, b = bh >> 3, h = bh & 7;
    int i0 = blockIdx.x * 128;

    unsigned fU = (unsigned)__cvta_generic_to_shared(fsm);

    const bf16* base = qkv + (size_t)b * cNW * 1536;
    const bf16* Qg = base + h * 64;
    const bf16* Kg = base + 512 + h * 64;
    const bf16* Vg = base + 1024 + h * 64;

    // Load Q tile (128 x 64 bf16), plain stores
    #pragma unroll
    for (int i = 0; i < 4; i++) {
        int idx = tid + i * 256;
        int r = idx >> 3, f = idx & 7;
        uint4 v = __ldg((const uint4*)(Qg + (size_t)(i0 + r) * 1536 + f * 8));
        *(uint4*)&fsm[r * 36 + f * 4] = v;
    }

    int pr2 = tid >> 3, pf2 = tid & 7;    // K/V prefetch: row 0..31, frag 0..7
    unsigned kdst = fU + (4608 + pr2 * 36 + pf2 * 4) * 4;
    unsigned vdst = fU + (9216 + pr2 * 36 + pf2 * 4) * 4;

#define PREKV(s, jt) do { int j0 = (jt) * 64;                                  \
    cp16(kdst + (s) * 2304 * 4,              Kg + (size_t)(j0 + pr2) * 1536 + pf2 * 8);      \
    cp16(kdst + (s) * 2304 * 4 + 32 * 36 * 4, Kg + (size_t)(j0 + pr2 + 32) * 1536 + pf2 * 8);\
    cp16(vdst + (s) * 2304 * 4,              Vg + (size_t)(j0 + pr2) * 1536 + pf2 * 8);      \
    cp16(vdst + (s) * 2304 * 4 + 32 * 36 * 4, Vg + (size_t)(j0 + pr2 + 32) * 1536 + pf2 * 8);\
    CP_COMMIT(); } while (0)

    PREKV(0, 0);

    // ldmatrix base addresses
    unsigned qBase = fU + ((wid * 16 + (q & 1) * 8 + lrow) * 36 + (q >> 1) * 4) * 4;
    unsigned kBase = fU + (4608 + ((q >> 1) * 8 + lrow) * 36 + (q & 1) * 4) * 4;
    unsigned vBase = fU + (9216 + ((q & 1) * 8 + lrow) * 36 + (q >> 1) * 4) * 4;

    float m0 = -1e30f, m1 = -1e30f, l0 = 0.f, l1 = 0.f;
    float o[8][4] = {};
    int qrow = wid * 16 + lg;

    for (int jt = 0; jt < 16; jt++) {
        CP_WAIT0();
        __syncthreads();
        if (jt + 1 < 16) PREKV((jt + 1) & 1, jt + 1);

        int buf = jt & 1;
        unsigned kS = kBase + buf * 2304 * 4;
        unsigned vS = vBase + buf * 2304 * 4;

        // S = Q @ K^T
        float sacc[8][4] = {};
        #pragma unroll
        for (int ks = 0; ks < 4; ks++) {
            unsigned aq[4];
            ldsm4(aq, qBase + ks * 8 * 4);
            #pragma unroll
            for (int nb = 0; nb < 4; nb++) {
                unsigned kq[4];
                ldsm4(kq, kS + (nb * 576 + ks * 8) * 4);
                mma_bf16(sacc[2 * nb],     aq, &kq[0]);
                mma_bf16(sacc[2 * nb + 1], aq, &kq[2]);
            }
        }

        // scale + row stats
        float mx0 = -1e30f, mx1 = -1e30f;
        #pragma unroll
        for (int na = 0; na < 8; na++) {
            #pragma unroll
            for (int c2 = 0; c2 < 4; c2++) sacc[na][c2] *= cSCALE;
            mx0 = fmaxf(mx0, fmaxf(sacc[na][0], sacc[na][1]));
            mx1 = fmaxf(mx1, fmaxf(sacc[na][2], sacc[na][3]));
        }
        #pragma unroll
        for (int o2 = 1; o2 < 4; o2 <<= 1) {
            mx0 = fmaxf(mx0, __shfl_xor_sync(0xffffffffu, mx0, o2));
            mx1 = fmaxf(mx1, __shfl_xor_sync(0xffffffffu, mx1, o2));
        }
        float nm0 = fmaxf(m0, mx0), nm1 = fmaxf(m1, mx1);
        float cr0 = __expf(m0 - nm0), cr1 = __expf(m1 - nm1);
        m0 = nm0; m1 = nm1;

        float sum0 = 0.f, sum1 = 0.f;
        #pragma unroll
        for (int na = 0; na < 8; na++) {
            sacc[na][0] = __expf(sacc[na][0] - nm0);
            sacc[na][1] = __expf(sacc[na][1] - nm0);
            sacc[na][2] = __expf(sacc[na][2] - nm1);
            sacc[na][3] = __expf(sacc[na][3] - nm1);
            sum0 += sacc[na][0] + sacc[na][1];
            sum1 += sacc[na][2] + sacc[na][3];
        }
        #pragma unroll
        for (int o2 = 1; o2 < 4; o2 <<= 1) {
            sum0 += __shfl_xor_sync(0xffffffffu, sum0, o2);
            sum1 += __shfl_xor_sync(0xffffffffu, sum1, o2);
        }
        l0 = l0 * cr0 + sum0;
        l1 = l1 * cr1 + sum1;
        #pragma unroll
        for (int na = 0; na < 8; na++) {
            o[na][0] *= cr0; o[na][1] *= cr0;
            o[na][2] *= cr1; o[na][3] *= cr1;
        }

        // O += P @ V   (V fragments via ldmatrix.trans on [j][d] tiles)
        #pragma unroll
        for (int ks = 0; ks < 4; ks++) {
            unsigned pa[4];
            pa[0] = pk2(sacc[2*ks][0],   sacc[2*ks][1]);
            pa[1] = pk2(sacc[2*ks][2],   sacc[2*ks][3]);
            pa[2] = pk2(sacc[2*ks+1][0], sacc[2*ks+1][1]);
            pa[3] = pk2(sacc[2*ks+1][2], sacc[2*ks+1][3]);
            #pragma unroll
            for (int nb = 0; nb < 4; nb++) {
                unsigned vq[4];
                ldsm4t(vq, vS + (ks * 16 * 36 + nb * 8) * 4);
                mma_bf16(o[2 * nb],     pa, &vq[0]);
                mma_bf16(o[2 * nb + 1], pa, &vq[2]);
            }
        }
    }

    float inv0 = 1.f / l0, inv1 = 1.f / l1;
    bf16* aoG = ao + ((size_t)b * cNW + i0) * cD + h * 64;
    #pragma unroll
    for (int na = 0; na < 8; na++) {
        int col = na * 8 + 2 * lt;
        *(unsigned*)(aoG + (size_t)qrow * cD + col)       = pk2(o[na][0] * inv0, o[na][1] * inv0);
        *(unsigned*)(aoG + (size_t)(qrow + 8) * cD + col) = pk2(o[na][2] * inv1, o[na][3] * inv1);
    }
#undef PREKV
}

// ---------------------------------------------------------------------------
// Weight transpose fp32 -> bf16 [N][K], grid.z = layer
// ---------------------------------------------------------------------------
__global__ void k_wt(const float* __restrict__ in, bf16* __restrict__ out,
                     int R, int Cc, long long inL, long long outL) {
    __shared__ float t[32][33];
    in  += (size_t)blockIdx.z * inL;
    out += (size_t)blockIdx.z * outL;
    int c0 = blockIdx.x * 32, r0 = blockIdx.y * 32;
    #pragma unroll
    for (int i = 0; i < 4; i++)
        t[threadIdx.y + i * 8][threadIdx.x] = in[(size_t)(r0 + threadIdx.y + i * 8) * Cc + c0 + threadIdx.x];
    __syncthreads();
    #pragma unroll
    for (int i = 0; i < 4; i++)
        out[(size_t)(c0 + threadIdx.y + i * 8) * R + r0 + threadIdx.x] =
            __float2bfloat16(t[threadIdx.x][threadIdx.y + i * 8]);
}

// ---------------------------------------------------------------------------
// Reductions
// ---------------------------------------------------------------------------
template<int NWARPS>
DEV_INLINE void block_sum2(float& s, float& s2) {
    #pragma unroll
    for (int o = 16; o > 0; o >>= 1) {
        s  += __shfl_down_sync(0xffffffffu, s,  o);
        s2 += __shfl_down_sync(0xffffffffu, s2, o);
    }
    __shared__ float sh_a[NWARPS], sh_b[NWARPS];
    int w = threadIdx.x >> 5;
    if ((threadIdx.x & 31) == 0) { sh_a[w] = s; sh_b[w] = s2; }
    __syncthreads();
    if (threadIdx.x == 0) {
        float a = sh_a[0], b = sh_b[0];
        #pragma unroll
        for (int i = 1; i < NWARPS; i++) { a += sh_a[i]; b += sh_b[i]; }
        sh_a[0] = a; sh_b[0] = b;
    }
    __syncthreads();
    s = sh_a[0]; s2 = sh_b[0];
}

// ---------------------------------------------------------------------------
// Flags / embed / ln / output
// ---------------------------------------------------------------------------
__global__ void k_zeroflags() {
    int i = blockIdx.x * blockDim.x + threadIdx.x;
    if (i < cT) g_mflag[i] = 0;
}
__global__ void k_setflags(const int* __restrict__ mask_idx) {
    int i = blockIdx.x * blockDim.x + threadIdx.x;
    if (i < cB * cK) g_mflag[(i / cK) * cNW + mask_idx[i]] = 1;
}

__global__ void __launch_bounds__(128) k_embed(
    const float* __restrict__ seq, const float* __restrict__ pos_emb,
    const float* __restrict__ mtok,
    const float* __restrict__ p1g, const float* __restrict__ p1b,
    const float* __restrict__ W_emb, const float* __restrict__ b_emb,
    const float* __restrict__ p2g, const float* __restrict__ p2b)
{
    int tok = blockIdx.x;
    int w = tok & (cNW - 1);
    int t = threadIdx.x;
    const float* pos = pos_emb + (size_t)(w + 1) * cD;
    float* out = g_x + (size_t)tok * cD;

    if (g_mflag[tok]) {
        #pragma unroll
        for (int j = 0; j < 4; j++) { int d = t + j * 128; out[d] = mtok[d] + pos[d]; }
        return;
    }
    __shared__ float wsm[32];
    __shared__ float lnw[32];
    const float* wrow = seq + (size_t)tok * 32;
    if (t < 32) wsm[t] = wrow[t];
    __syncthreads();
    float m = 0.f;
    #pragma unroll
    for (int c = 0; c < 32; c++) m += wsm[c];
    m *= (1.f / 32.f);
    float v = 0.f;
    #pragma unroll
    for (int c = 0; c < 32; c++) { float d0 = wsm[c] - m; v += d0 * d0; }
    v *= (1.f / 32.f);
    float rs = rsqrtf(v + 1e-5f);
    if (t < 32) lnw[t] = (wsm[t] - m) * rs * p1g[t] + p1b[t];
    __syncthreads();
    float acc[4];
    #pragma unroll
    for (int j = 0; j < 4; j++) {
        int d = t + j * 128;
        float a = b_emb[d];
        #pragma unroll
        for (int c = 0; c < 32; c++) a += lnw[c] * W_emb[c * cD + d];
        acc[j] = a;
    }
    float s = 0.f, s2 = 0.f;
    #pragma unroll
    for (int j = 0; j < 4; j++) { s += acc[j]; s2 += acc[j] * acc[j]; }
    block_sum2<4>(s, s2);
    float mean = s * (1.f / cD);
    float var  = s2 * (1.f / cD) - mean * mean;
    float rstd = rsqrtf(var + 1e-5f);
    #pragma unroll
    for (int j = 0; j < 4; j++) {
        int d = t + j * 128;
        out[d] = (acc[j] - mean) * rstd * p2g[d] + p2b[d] + pos[d];
    }
}

template<bool OBF>
__global__ void __launch_bounds__(128) k_ln(
    const float* __restrict__ x, const float* __restrict__ g,
    const float* __restrict__ bt, void* __restrict__ y)
{
    int row = blockIdx.x;
    int t = threadIdx.x;
    const float4* xr = (const float4*)(x + (size_t)row * cD);
    float4 a = xr[t];
    float s  = a.x + a.y + a.z + a.w;
    float s2 = a.x*a.x + a.y*a.y + a.z*a.z + a.w*a.w;
    block_sum2<4>(s, s2);
    float mean = s * (1.f / cD);
    float var  = s2 * (1.f / cD) - mean * mean;
    float rstd = rsqrtf(var + 1e-5f);
    float4 gg = ((const float4*)g)[t];
    float4 bb = ((const float4*)bt)[t];
    float4 o;
    o.x = (a.x - mean) * rstd * gg.x + bb.x;
    o.y = (a.y - mean) * rstd * gg.y + bb.y;
    o.z = (a.z - mean) * rstd * gg.z + bb.z;
    o.w = (a.w - mean) * rstd * gg.w + bb.w;
    if (OBF) {
        uint2 u = make_uint2(pk2(o.x, o.y), pk2(o.z, o.w));
        *(uint2*)((bf16*)y + (size_t)row * cD + t * 4) = u;
    } else {
        ((float4*)((float*)y + (size_t)row * cD))[t] = o;
    }
}

__global__ void __launch_bounds__(256) k_output(
    const float* __restrict__ seq, const int* __restrict__ mask_idx,
    const float* __restrict__ Ww, const float* __restrict__ bw,
    float* __restrict__ out, long long out_size)
{
    int b = blockIdx.y, k = blockIdx.x;
    int idx = mask_idx[b * cK + k];
    const float* enc = g_h + ((size_t)b * cNW + idx) * cD;
    __shared__ float es[cD];
    __shared__ float lgt[32];
    int t = threadIdx.x;
    ((float2*)es)[t] = ((const float2*)enc)[t];
    __syncthreads();
    int lg = t >> 3, sg = t & 7;
    float part = 0.f;
    #pragma unroll
    for (int c = 0; c < 64; c++) {
        int cc = sg * 64 + c;
        part += es[cc] * Ww[cc * 32 + lg];
    }
    part += __shfl_down_sync(0xffffffffu, part, 4);
    part += __shfl_down_sync(0xffffffffu, part, 2);
    part += __shfl_down_sync(0xffffffffu, part, 1);
    if (sg == 0) lgt[lg] = part + bw[lg];
    __syncthreads();
    size_t base = (size_t)b * cK + k;
    if (t < 8) {
        float l0 = lgt[t*4+0], l1 = lgt[t*4+1], l2 = lgt[t*4+2], l3 = lgt[t*4+3];
        float mx = fmaxf(fmaxf(l0, l1), fmaxf(l2, l3));
        float e0 = expf(l0 - mx), e1 = expf(l1 - mx), e2 = expf(l2 - mx), e3 = expf(l3 - mx);
        float inv = 1.f / (e0 + e1 + e2 + e3);
        size_t off = base * 32 + t * 4;
        if ((long long)(off + 3) < out_size) {
            out[off+0] = e0*inv; out[off+1] = e1*inv; out[off+2] = e2*inv; out[off+3] = e3*inv;
        }
    }
    if (t < 32) {
        size_t off = (size_t)cB * cK * 32 + base * 32 + t;
        if ((long long)off < out_size)
            out[off] = seq[((size_t)b * cNW + idx) * 32 + t];
    }
}

// ---------------------------------------------------------------------------
// Launch
// ---------------------------------------------------------------------------
extern "C" void kernel_launch(void* const* d_in, const int* in_sizes, int n_in,
                              void* d_out, int out_size)
{
    const float* seq      = (const float*)d_in[0];
    const int*   mask_idx = (const int*)  d_in[1];
    const float* pos_emb  = (const float*)d_in[2];
    const float* mtok     = (const float*)d_in[3];
    const float* p1g      = (const float*)d_in[4];
    const float* p1b      = (const float*)d_in[5];
    const float* W_emb    = (const float*)d_in[6];
    const float* b_emb    = (const float*)d_in[7];
    const float* p2g      = (const float*)d_in[8];
    const float* p2b      = (const float*)d_in[9];
    const float* alng     = (const float*)d_in[10];
    const float* alnb     = (const float*)d_in[11];
    const float* Wqkv     = (const float*)d_in[12];
    const float* Wo       = (const float*)d_in[13];
    const float* flng     = (const float*)d_in[14];
    const float* flnb     = (const float*)d_in[15];
    const float* W1       = (const float*)d_in[16];
    const float* b1       = (const float*)d_in[17];
    const float* W2       = (const float*)d_in[18];
    const float* b2       = (const float*)d_in[19];
    const float* olng     = (const float*)d_in[20];
    const float* olnb     = (const float*)d_in[21];
    const float* Ww       = (const float*)d_in[22];
    const float* bw       = (const float*)d_in[23];
    float* out = (float*)d_out;
    (void)in_sizes; (void)n_in;

    float *px, *ph;
    bf16 *phh, *pqkvh, *paoh, *pffh, *pwTh;
    cudaGetSymbolAddress((void**)&px,    g_x);
    cudaGetSymbolAddress((void**)&ph,    g_h);
    cudaGetSymbolAddress((void**)&phh,   g_hh);
    cudaGetSymbolAddress((void**)&pqkvh, g_qkvh);
    cudaGetSymbolAddress((void**)&paoh,  g_aoh);
    cudaGetSymbolAddress((void**)&pffh,  g_ffh);
    cudaGetSymbolAddress((void**)&pwTh,  g_wTh);

    const int GSM = 3 * (128 * 20 + 128 * 20) * 4;    // 61440
    const int FSM = (4608 + 2 * 2304 + 2 * 2304) * 4; // 55296
    cudaFuncSetAttribute(k_tgemm<false,false,false,true >, cudaFuncAttributeMaxDynamicSharedMemorySize, GSM);
    cudaFuncSetAttribute(k_tgemm<false,true, false,false>, cudaFuncAttributeMaxDynamicSharedMemorySize, GSM);
    cudaFuncSetAttribute(k_tgemm<true, false,true, true >, cudaFuncAttributeMaxDynamicSharedMemorySize, GSM);
    cudaFuncSetAttribute(k_tgemm<true, true, false,false>, cudaFuncAttributeMaxDynamicSharedMemorySize, GSM);
    cudaFuncSetAttribute(k_flash, cudaFuncAttributeMaxDynamicSharedMemorySize, FSM);

    k_zeroflags<<<cT / 256, 256>>>();
    k_setflags<<<(cB * cK) / 256, 256>>>(mask_idx);
    k_embed<<<cT, 128>>>(seq, pos_emb, mtok, p1g, p1b, W_emb, b_emb, p2g, p2b);

    // transpose all weights to bf16 [N][K], all layers at once (grid.z)
    const long long LSTR = 3145728;
    k_wt<<<dim3(1536/32, 512/32, cL), dim3(32,8)>>>(Wqkv, pwTh,            512, 1536, 786432,  LSTR);
    k_wt<<<dim3( 512/32, 512/32, cL), dim3(32,8)>>>(Wo,   pwTh + 786432,   512,  512, 262144,  LSTR);
    k_wt<<<dim3(2048/32, 512/32, cL), dim3(32,8)>>>(W1,   pwTh + 1048576,  512, 2048, 1048576, LSTR);
    k_wt<<<dim3( 512/32,2048/32, cL), dim3(32,8)>>>(W2,   pwTh + 2097152, 2048,  512, 1048576, LSTR);

    for (int l = 0; l < cL; l++) {
        bf16* baseT = pwTh + (size_t)l * LSTR;
        bf16* WqkvT = baseT;
        bf16* WoT   = baseT + 786432;
        bf16* W1T   = baseT + 1048576;
        bf16* W2T   = baseT + 2097152;

        // attention
        k_ln<true><<<cT, 128>>>(px, alng + l*cD, alnb + l*cD, phh);
        k_tgemm<false,false,false,true><<<dim3(12, 64), 256, GSM>>>(
            phh, WqkvT, nullptr, nullptr, pqkvh, 512, 512, 512, 1536);
        k_flash<<<dim3(8, 64), 256, FSM>>>(pqkvh, paoh);
        k_tgemm<false,true,false,false><<<dim3(4, 64), 256, GSM>>>(
            paoh, WoT, nullptr, px, px, 512, 512, 512, 512);

        // ffn
        k_ln<true><<<cT, 128>>>(px, flng + l*cD, flnb + l*cD, phh);
        k_tgemm<true,false,true,true><<<dim3(16, 64), 256, GSM>>>(
            phh, W1T, b1 + (size_t)l*cFF, nullptr, pffh, 512, 512, 512, 2048);
        k_tgemm<true,true,false,false><<<dim3(4, 64), 256, GSM>>>(
            pffh, W2T, b2 + (size_t)l*cD, px, px, 2048, 2048, 2048, 512);
    }

    k_ln<false><<<cT, 128>>>(px, olng, olnb, ph);
    k_output<<<dim3(cK, cB), 256>>>(seq, mask_idx, Ww, bw, out, (long long)out_size);
}

// round 8
// speedup vs baseline: 6.4746x; 1.0916x over previous
#include <cuda_runtime.h>
#include <cuda_bf16.h>

#define DEV_INLINE __device__ __forceinline__

// Problem constants
constexpr int cB  = 8;
constexpr int cNW = 1024;
constexpr int cD  = 512;
constexpr int cH  = 8;
constexpr int cL  = 4;
constexpr int cFF = 2048;
constexpr int cK  = 512;
constexpr int cT  = cB * cNW;        // 8192 tokens
constexpr float cSCALE = 0.125f;

typedef __nv_bfloat16 bf16;

// ---------------------------------------------------------------------------
// Scratch
// ---------------------------------------------------------------------------
__device__ float g_x   [cT * cD];           // residual (fp32)
__device__ float g_h   [cT * cD];           // final LN out (fp32)
__device__ bf16  g_hh  [cT * cD];           // LN out bf16
__device__ bf16  g_qkvh[cT * 3 * cD];       // qkv bf16
__device__ bf16  g_aoh [cT * cD];           // attn out bf16
__device__ bf16  g_ffh [cT * cFF];          // ffn hidden bf16
__device__ bf16  g_wTh [12582912];          // transposed weights bf16
__device__ int   g_mflag[cT];

// ---------------------------------------------------------------------------
// Helpers
// ---------------------------------------------------------------------------
DEV_INLINE float gelu_f(float x) {
    float z = 0.7978845608028654f * (x + 0.044715f * x * x * x);
    float t = __expf(2.0f * z);
    float th = 1.0f - 2.0f / (t + 1.0f);
    return 0.5f * x * (1.0f + th);
}

DEV_INLINE unsigned pk2(float lo, float hi) {
    unsigned u;
    asm("cvt.rn.bf16x2.f32 %0, %1, %2;" : "=r"(u) : "f"(hi), "f"(lo));
    return u;
}

DEV_INLINE void mma_bf16(float* d, const unsigned* a, const unsigned* b) {
    asm volatile(
        "mma.sync.aligned.m16n8k16.row.col.f32.bf16.bf16.f32 "
        "{%0,%1,%2,%3}, {%4,%5,%6,%7}, {%8,%9}, {%0,%1,%2,%3};"
        : "+f"(d[0]), "+f"(d[1]), "+f"(d[2]), "+f"(d[3])
        : "r"(a[0]), "r"(a[1]), "r"(a[2]), "r"(a[3]), "r"(b[0]), "r"(b[1]));
}

DEV_INLINE void ldsm4(unsigned* r, unsigned addr) {
    asm volatile("ldmatrix.sync.aligned.m8n8.x4.shared.b16 {%0,%1,%2,%3}, [%4];"
        : "=r"(r[0]), "=r"(r[1]), "=r"(r[2]), "=r"(r[3]) : "r"(addr));
}
DEV_INLINE void ldsm4t(unsigned* r, unsigned addr) {
    asm volatile("ldmatrix.sync.aligned.m8n8.x4.trans.shared.b16 {%0,%1,%2,%3}, [%4];"
        : "=r"(r[0]), "=r"(r[1]), "=r"(r[2]), "=r"(r[3]) : "r"(addr));
}

DEV_INLINE void cp16(unsigned dst, const void* src) {
    asm volatile("cp.async.cg.shared.global [%0], [%1], 16;" :: "r"(dst), "l"(src));
}
#define CP_COMMIT() asm volatile("cp.async.commit_group;" ::: "memory")
#define CP_WAIT1()  asm volatile("cp.async.wait_group 1;" ::: "memory")
#define CP_WAIT0()  asm volatile("cp.async.wait_group 0;" ::: "memory")

// ---------------------------------------------------------------------------
// bf16 tensor-core GEMM, BK=64, 3-stage cp.async + ldmatrix.
// C[M,N] = A[M,K] @ B[N,K]^T (+bias)(gelu)(+Res)
// BM=128, BN=128, 256 threads (8 warps: 2m x 4n), warp 64x32.
// SMEM rows of 36 u32 (32 data + 4 pad): 36r mod 32 = 4r -> 8-row ldmatrix
// tiles hit all 32 banks, conflict-free; cp.async dsts 16B-aligned.
// ---------------------------------------------------------------------------
template<bool BIAS, bool RES, bool GELU_, bool OBF>
__global__ void __launch_bounds__(256)
k_tgemm(const bf16* __restrict__ A, const bf16* __restrict__ B,
        const float* __restrict__ bias, const float* __restrict__ Res,
        void* __restrict__ Cv, int K, int sA, int sB, int sC)
{
    extern __shared__ __align__(16) unsigned dsm[];
    constexpr int ASZ = 128 * 36;
    constexpr int BSZ = 128 * 36;

    int tid = threadIdx.x;
    int wid = tid >> 5, lane = tid & 31;
    int wm = wid & 1, wn = wid >> 1;
    int lrow = lane & 7, q = lane >> 3;
    int lg = lane >> 2, lt = lane & 3;

    int bm = blockIdx.y * 128, bn = blockIdx.x * 128;
    unsigned smemU = (unsigned)__cvta_generic_to_shared(dsm);

    const int NC = K >> 6;
    float acc[4][4][4] = {};

    int pr = tid >> 3, pf = tid & 7;                 // prefetch row (0..31) / frag (0..7)
    const bf16* Apre = A + (size_t)(bm + pr) * sA + pf * 8;
    const bf16* Bpre = B + (size_t)(bn + pr) * sB + pf * 8;
    unsigned adst = smemU + (pr * 36 + pf * 4) * 4;
    unsigned bdst = smemU + (3 * ASZ + pr * 36 + pf * 4) * 4;

    // ldmatrix per-thread base addresses
    unsigned aBase = smemU + ((wm * 64 + (q & 1) * 8 + lrow) * 36 + (q >> 1) * 4) * 4;
    unsigned bBase = smemU + (3 * ASZ + (wn * 32 + (q >> 1) * 8 + lrow) * 36 + (q & 1) * 4) * 4;

#define PRE(s, c) do { int k0 = (c) << 6;                                          \
    _Pragma("unroll")                                                              \
    for (int i = 0; i < 4; i++)                                                    \
        cp16(adst + (s) * ASZ * 4 + i * 32 * 36 * 4, Apre + (size_t)i * 32 * sA + k0); \
    _Pragma("unroll")                                                              \
    for (int i = 0; i < 4; i++)                                                    \
        cp16(bdst + (s) * BSZ * 4 + i * 32 * 36 * 4, Bpre + (size_t)i * 32 * sB + k0); \
    CP_COMMIT(); } while (0)

    PRE(0, 0);
    PRE(1, 1);

    for (int c = 0; c < NC; c++) {
        if (c + 1 < NC) CP_WAIT1(); else CP_WAIT0();
        __syncthreads();
        if (c + 2 < NC) PRE((c + 2) % 3, c + 2);

        int st = c % 3;
        unsigned aS = aBase + st * ASZ * 4;
        unsigned bS = bBase + st * BSZ * 4;
        #pragma unroll
        for (int ks = 0; ks < 4; ks++) {
            unsigned af[4][4], bq[2][4];
            #pragma unroll
            for (int ma = 0; ma < 4; ma++) ldsm4(af[ma], aS + (ma * 576 + ks * 8) * 4);
            #pragma unroll
            for (int nb = 0; nb < 2; nb++) ldsm4(bq[nb], bS + (nb * 576 + ks * 8) * 4);
            #pragma unroll
            for (int ma = 0; ma < 4; ma++)
                #pragma unroll
                for (int na = 0; na < 4; na++)
                    mma_bf16(acc[ma][na], af[ma], &bq[na >> 1][(na & 1) * 2]);
        }
    }

    // Epilogue
    #pragma unroll
    for (int ma = 0; ma < 4; ma++) {
        #pragma unroll
        for (int na = 0; na < 4; na++) {
            int row = bm + wm * 64 + ma * 16 + lg;
            int col = bn + wn * 32 + na * 8 + 2 * lt;
            #pragma unroll
            for (int half = 0; half < 2; half++) {
                int r = row + half * 8;
                float v0 = acc[ma][na][half * 2 + 0];
                float v1 = acc[ma][na][half * 2 + 1];
                if (BIAS) { v0 += bias[col]; v1 += bias[col + 1]; }
                if (GELU_) { v0 = gelu_f(v0); v1 = gelu_f(v1); }
                if (RES) {
                    const float* rp = Res + (size_t)r * sC + col;
                    v0 += rp[0]; v1 += rp[1];
                }
                if (OBF) {
                    *(unsigned*)((bf16*)Cv + (size_t)r * sC + col) = pk2(v0, v1);
                } else {
                    *(float2*)((float*)Cv + (size_t)r * sC + col) = make_float2(v0, v1);
                }
            }
        }
    }
#undef PRE
}

// ---------------------------------------------------------------------------
// Flash attention: per (b,h), i-tile of 128 rows, online softmax over 16
// j-tiles of 64. 256 threads, 8 warps x 16 rows. 2-stage cp.async K/V,
// ldmatrix fragments, V via ldmatrix.trans.
// ---------------------------------------------------------------------------
__global__ void __launch_bounds__(256)
k_flash(const bf16* __restrict__ qkv, bf16* __restrict__ ao)
{
    extern __shared__ __align__(16) unsigned fsm[];
    // Qs [0,4608), Ks stage s at 4608 + s*2304, Vs stage s at 9216 + s*2304

    int tid = threadIdx.x;
    int wid = tid >> 5, lane = tid & 31;
    int lrow = lane & 7, q = lane >> 3;
    int lg = lane >> 2, lt = lane & 3;
    int bh = blockIdx.y, b = bh >> 3, h = bh & 7;
    int i0 = blockIdx.x * 128;

    unsigned fU = (unsigned)__cvta_generic_to_shared(fsm);

    const bf16* base = qkv + (size_t)b * cNW * 1536;
    const bf16* Qg = base + h * 64;
    const bf16* Kg = base + 512 + h * 64;
    const bf16* Vg = base + 1024 + h * 64;

    // Load Q tile (128 x 64 bf16)
    #pragma unroll
    for (int i = 0; i < 4; i++) {
        int idx = tid + i * 256;
        int r = idx >> 3, f = idx & 7;
        uint4 v = __ldg((const uint4*)(Qg + (size_t)(i0 + r) * 1536 + f * 8));
        *(uint4*)&fsm[r * 36 + f * 4] = v;
    }

    int pr2 = tid >> 3, pf2 = tid & 7;
    unsigned kdst = fU + (4608 + pr2 * 36 + pf2 * 4) * 4;
    unsigned vdst = fU + (9216 + pr2 * 36 + pf2 * 4) * 4;

#define PREKV(s, jt) do { int j0 = (jt) * 64;                                  \
    cp16(kdst + (s) * 2304 * 4,               Kg + (size_t)(j0 + pr2) * 1536 + pf2 * 8);      \
    cp16(kdst + (s) * 2304 * 4 + 32 * 36 * 4, Kg + (size_t)(j0 + pr2 + 32) * 1536 + pf2 * 8); \
    cp16(vdst + (s) * 2304 * 4,               Vg + (size_t)(j0 + pr2) * 1536 + pf2 * 8);      \
    cp16(vdst + (s) * 2304 * 4 + 32 * 36 * 4, Vg + (size_t)(j0 + pr2 + 32) * 1536 + pf2 * 8); \
    CP_COMMIT(); } while (0)

    PREKV(0, 0);

    unsigned qBase = fU + ((wid * 16 + (q & 1) * 8 + lrow) * 36 + (q >> 1) * 4) * 4;
    unsigned kBase = fU + (4608 + ((q >> 1) * 8 + lrow) * 36 + (q & 1) * 4) * 4;
    unsigned vBase = fU + (9216 + ((q & 1) * 8 + lrow) * 36 + (q >> 1) * 4) * 4;

    float m0 = -1e30f, m1 = -1e30f, l0 = 0.f, l1 = 0.f;
    float o[8][4] = {};
    int qrow = wid * 16 + lg;

    for (int jt = 0; jt < 16; jt++) {
        CP_WAIT0();
        __syncthreads();
        if (jt + 1 < 16) PREKV((jt + 1) & 1, jt + 1);

        int buf = jt & 1;
        unsigned kS = kBase + buf * 2304 * 4;
        unsigned vS = vBase + buf * 2304 * 4;

        // S = Q @ K^T
        float sacc[8][4] = {};
        #pragma unroll
        for (int ks = 0; ks < 4; ks++) {
            unsigned aq[4];
            ldsm4(aq, qBase + ks * 8 * 4);
            #pragma unroll
            for (int nb = 0; nb < 4; nb++) {
                unsigned kq[4];
                ldsm4(kq, kS + (nb * 576 + ks * 8) * 4);
                mma_bf16(sacc[2 * nb],     aq, &kq[0]);
                mma_bf16(sacc[2 * nb + 1], aq, &kq[2]);
            }
        }

        // scale + row stats
        float mx0 = -1e30f, mx1 = -1e30f;
        #pragma unroll
        for (int na = 0; na < 8; na++) {
            #pragma unroll
            for (int c2 = 0; c2 < 4; c2++) sacc[na][c2] *= cSCALE;
            mx0 = fmaxf(mx0, fmaxf(sacc[na][0], sacc[na][1]));
            mx1 = fmaxf(mx1, fmaxf(sacc[na][2], sacc[na][3]));
        }
        #pragma unroll
        for (int o2 = 1; o2 < 4; o2 <<= 1) {
            mx0 = fmaxf(mx0, __shfl_xor_sync(0xffffffffu, mx0, o2));
            mx1 = fmaxf(mx1, __shfl_xor_sync(0xffffffffu, mx1, o2));
        }
        float nm0 = fmaxf(m0, mx0), nm1 = fmaxf(m1, mx1);
        float cr0 = __expf(m0 - nm0), cr1 = __expf(m1 - nm1);
        m0 = nm0; m1 = nm1;

        float sum0 = 0.f, sum1 = 0.f;
        #pragma unroll
        for (int na = 0; na < 8; na++) {
            sacc[na][0] = __expf(sacc[na][0] - nm0);
            sacc[na][1] = __expf(sacc[na][1] - nm0);
            sacc[na][2] = __expf(sacc[na][2] - nm1);
            sacc[na][3] = __expf(sacc[na][3] - nm1);
            sum0 += sacc[na][0] + sacc[na][1];
            sum1 += sacc[na][2] + sacc[na][3];
        }
        #pragma unroll
        for (int o2 = 1; o2 < 4; o2 <<= 1) {
            sum0 += __shfl_xor_sync(0xffffffffu, sum0, o2);
            sum1 += __shfl_xor_sync(0xffffffffu, sum1, o2);
        }
        l0 = l0 * cr0 + sum0;
        l1 = l1 * cr1 + sum1;
        #pragma unroll
        for (int na = 0; na < 8; na++) {
            o[na][0] *= cr0; o[na][1] *= cr0;
            o[na][2] *= cr1; o[na][3] *= cr1;
        }

        // O += P @ V
        #pragma unroll
        for (int ks = 0; ks < 4; ks++) {
            unsigned pa[4];
            pa[0] = pk2(sacc[2*ks][0],   sacc[2*ks][1]);
            pa[1] = pk2(sacc[2*ks][2],   sacc[2*ks][3]);
            pa[2] = pk2(sacc[2*ks+1][0], sacc[2*ks+1][1]);
            pa[3] = pk2(sacc[2*ks+1][2], sacc[2*ks+1][3]);
            #pragma unroll
            for (int nb = 0; nb < 4; nb++) {
                unsigned vq[4];
                ldsm4t(vq, vS + (ks * 16 * 36 + nb * 8) * 4);
                mma_bf16(o[2 * nb],     pa, &vq[0]);
                mma_bf16(o[2 * nb + 1], pa, &vq[2]);
            }
        }
    }

    float inv0 = 1.f / l0, inv1 = 1.f / l1;
    bf16* aoG = ao + ((size_t)b * cNW + i0) * cD + h * 64;
    #pragma unroll
    for (int na = 0; na < 8; na++) {
        int col = na * 8 + 2 * lt;
        *(unsigned*)(aoG + (size_t)qrow * cD + col)       = pk2(o[na][0] * inv0, o[na][1] * inv0);
        *(unsigned*)(aoG + (size_t)(qrow + 8) * cD + col) = pk2(o[na][2] * inv1, o[na][3] * inv1);
    }
#undef PREKV
}

// ---------------------------------------------------------------------------
// Weight transpose fp32 -> bf16 [N][K], grid.z = layer
// ---------------------------------------------------------------------------
__global__ void k_wt(const float* __restrict__ in, bf16* __restrict__ out,
                     int R, int Cc, long long inL, long long outL) {
    __shared__ float t[32][33];
    in  += (size_t)blockIdx.z * inL;
    out += (size_t)blockIdx.z * outL;
    int c0 = blockIdx.x * 32, r0 = blockIdx.y * 32;
    #pragma unroll
    for (int i = 0; i < 4; i++)
        t[threadIdx.y + i * 8][threadIdx.x] = in[(size_t)(r0 + threadIdx.y + i * 8) * Cc + c0 + threadIdx.x];
    __syncthreads();
    #pragma unroll
    for (int i = 0; i < 4; i++)
        out[(size_t)(c0 + threadIdx.y + i * 8) * R + r0 + threadIdx.x] =
            __float2bfloat16(t[threadIdx.x][threadIdx.y + i * 8]);
}

// ---------------------------------------------------------------------------
// Reductions
// ---------------------------------------------------------------------------
template<int NWARPS>
DEV_INLINE void block_sum2(float& s, float& s2) {
    #pragma unroll
    for (int o = 16; o > 0; o >>= 1) {
        s  += __shfl_down_sync(0xffffffffu, s,  o);
        s2 += __shfl_down_sync(0xffffffffu, s2, o);
    }
    __shared__ float sh_a[NWARPS], sh_b[NWARPS];
    int w = threadIdx.x >> 5;
    if ((threadIdx.x & 31) == 0) { sh_a[w] = s; sh_b[w] = s2; }
    __syncthreads();
    if (threadIdx.x == 0) {
        float a = sh_a[0], b = sh_b[0];
        #pragma unroll
        for (int i = 1; i < NWARPS; i++) { a += sh_a[i]; b += sh_b[i]; }
        sh_a[0] = a; sh_b[0] = b;
    }
    __syncthreads();
    s = sh_a[0]; s2 = sh_b[0];
}

// ---------------------------------------------------------------------------
// Flags / embed / ln / output
// ---------------------------------------------------------------------------
__global__ void k_zeroflags() {
    int i = blockIdx.x * blockDim.x + threadIdx.x;
    if (i < cT) g_mflag[i] = 0;
}
__global__ void k_setflags(const int* __restrict__ mask_idx) {
    int i = blockIdx.x * blockDim.x + threadIdx.x;
    if (i < cB * cK) g_mflag[(i / cK) * cNW + mask_idx[i]] = 1;
}

__global__ void __launch_bounds__(128) k_embed(
    const float* __restrict__ seq, const float* __restrict__ pos_emb,
    const float* __restrict__ mtok,
    const float* __restrict__ p1g, const float* __restrict__ p1b,
    const float* __restrict__ W_emb, const float* __restrict__ b_emb,
    const float* __restrict__ p2g, const float* __restrict__ p2b)
{
    int tok = blockIdx.x;
    int w = tok & (cNW - 1);
    int t = threadIdx.x;
    const float* pos = pos_emb + (size_t)(w + 1) * cD;
    float* out = g_x + (size_t)tok * cD;

    if (g_mflag[tok]) {
        #pragma unroll
        for (int j = 0; j < 4; j++) { int d = t + j * 128; out[d] = mtok[d] + pos[d]; }
        return;
    }
    __shared__ float wsm[32];
    __shared__ float lnw[32];
    const float* wrow = seq + (size_t)tok * 32;
    if (t < 32) wsm[t] = wrow[t];
    __syncthreads();
    float m = 0.f;
    #pragma unroll
    for (int c = 0; c < 32; c++) m += wsm[c];
    m *= (1.f / 32.f);
    float v = 0.f;
    #pragma unroll
    for (int c = 0; c < 32; c++) { float d0 = wsm[c] - m; v += d0 * d0; }
    v *= (1.f / 32.f);
    float rs = rsqrtf(v + 1e-5f);
    if (t < 32) lnw[t] = (wsm[t] - m) * rs * p1g[t] + p1b[t];
    __syncthreads();
    float acc[4];
    #pragma unroll
    for (int j = 0; j < 4; j++) {
        int d = t + j * 128;
        float a = b_emb[d];
        #pragma unroll
        for (int c = 0; c < 32; c++) a += lnw[c] * W_emb[c * cD + d];
        acc[j] = a;
    }
    float s = 0.f, s2 = 0.f;
    #pragma unroll
    for (int j = 0; j < 4; j++) { s += acc[j]; s2 += acc[j] * acc[j]; }
    block_sum2<4>(s, s2);
    float mean = s * (1.f / cD);
    float var  = s2 * (1.f / cD) - mean * mean;
    float rstd = rsqrtf(var + 1e-5f);
    #pragma unroll
    for (int j = 0; j < 4; j++) {
        int d = t + j * 128;
        out[d] = (acc[j] - mean) * rstd * p2g[d] + p2b[d] + pos[d];
    }
}

// Warp-per-row LayerNorm: 8 rows per 256-thread block, shuffle-only reduce.
template<bool OBF>
__global__ void __launch_bounds__(256) k_ln(
    const float* __restrict__ x, const float* __restrict__ g,
    const float* __restrict__ bt, void* __restrict__ y)
{
    int row = blockIdx.x * 8 + (threadIdx.x >> 5);
    int lane = threadIdx.x & 31;
    const float4* xr = (const float4*)(x + (size_t)row * cD);
    float4 a[4];
    #pragma unroll
    for (int i = 0; i < 4; i++) a[i] = xr[lane + i * 32];
    float s = 0.f, s2 = 0.f;
    #pragma unroll
    for (int i = 0; i < 4; i++) {
        s  += a[i].x + a[i].y + a[i].z + a[i].w;
        s2 += a[i].x*a[i].x + a[i].y*a[i].y + a[i].z*a[i].z + a[i].w*a[i].w;
    }
    #pragma unroll
    for (int o = 16; o > 0; o >>= 1) {
        s  += __shfl_xor_sync(0xffffffffu, s,  o);
        s2 += __shfl_xor_sync(0xffffffffu, s2, o);
    }
    float mean = s * (1.f / cD);
    float var  = s2 * (1.f / cD) - mean * mean;
    float rstd = rsqrtf(var + 1e-5f);
    #pragma unroll
    for (int i = 0; i < 4; i++) {
        int c4 = lane + i * 32;
        float4 gg = ((const float4*)g)[c4];
        float4 bb = ((const float4*)bt)[c4];
        float o0 = (a[i].x - mean) * rstd * gg.x + bb.x;
        float o1 = (a[i].y - mean) * rstd * gg.y + bb.y;
        float o2 = (a[i].z - mean) * rstd * gg.z + bb.z;
        float o3 = (a[i].w - mean) * rstd * gg.w + bb.w;
        if (OBF) {
            uint2 u = make_uint2(pk2(o0, o1), pk2(o2, o3));
            *(uint2*)((bf16*)y + (size_t)row * cD + c4 * 4) = u;
        } else {
            ((float4*)((float*)y + (size_t)row * cD))[c4] = make_float4(o0, o1, o2, o3);
        }
    }
}

__global__ void __launch_bounds__(256) k_output(
    const float* __restrict__ seq, const int* __restrict__ mask_idx,
    const float* __restrict__ Ww, const float* __restrict__ bw,
    float* __restrict__ out, long long out_size)
{
    int b = blockIdx.y, k = blockIdx.x;
    int idx = mask_idx[b * cK + k];
    const float* enc = g_h + ((size_t)b * cNW + idx) * cD;
    __shared__ float es[cD];
    __shared__ float lgt[32];
    int t = threadIdx.x;
    ((float2*)es)[t] = ((const float2*)enc)[t];
    __syncthreads();
    int lg = t >> 3, sg = t & 7;
    float part = 0.f;
    #pragma unroll
    for (int c = 0; c < 64; c++) {
        int cc = sg * 64 + c;
        part += es[cc] * Ww[cc * 32 + lg];
    }
    part += __shfl_down_sync(0xffffffffu, part, 4);
    part += __shfl_down_sync(0xffffffffu, part, 2);
    part += __shfl_down_sync(0xffffffffu, part, 1);
    if (sg == 0) lgt[lg] = part + bw[lg];
    __syncthreads();
    size_t base = (size_t)b * cK + k;
    if (t < 8) {
        float l0 = lgt[t*4+0], l1 = lgt[t*4+1], l2 = lgt[t*4+2], l3 = lgt[t*4+3];
        float mx = fmaxf(fmaxf(l0, l1), fmaxf(l2, l3));
        float e0 = expf(l0 - mx), e1 = expf(l1 - mx), e2 = expf(l2 - mx), e3 = expf(l3 - mx);
        float inv = 1.f / (e0 + e1 + e2 + e3);
        size_t off = base * 32 + t * 4;
        if ((long long)(off + 3) < out_size) {
            out[off+0] = e0*inv; out[off+1] = e1*inv; out[off+2] = e2*inv; out[off+3] = e3*inv;
        }
    }
    if (t < 32) {
        size_t off = (size_t)cB * cK * 32 + base * 32 + t;
        if ((long long)off < out_size)
            out[off] = seq[((size_t)b * cNW + idx) * 32 + t];
    }
}

// ---------------------------------------------------------------------------
// Launch
// ---------------------------------------------------------------------------
extern "C" void kernel_launch(void* const* d_in, const int* in_sizes, int n_in,
                              void* d_out, int out_size)
{
    const float* seq      = (const float*)d_in[0];
    const int*   mask_idx = (const int*)  d_in[1];
    const float* pos_emb  = (const float*)d_in[2];
    const float* mtok     = (const float*)d_in[3];
    const float* p1g      = (const float*)d_in[4];
    const float* p1b      = (const float*)d_in[5];
    const float* W_emb    = (const float*)d_in[6];
    const float* b_emb    = (const float*)d_in[7];
    const float* p2g      = (const float*)d_in[8];
    const float* p2b      = (const float*)d_in[9];
    const float* alng     = (const float*)d_in[10];
    const float* alnb     = (const float*)d_in[11];
    const float* Wqkv     = (const float*)d_in[12];
    const float* Wo       = (const float*)d_in[13];
    const float* flng     = (const float*)d_in[14];
    const float* flnb     = (const float*)d_in[15];
    const float* W1       = (const float*)d_in[16];
    const float* b1       = (const float*)d_in[17];
    const float* W2       = (const float*)d_in[18];
    const float* b2       = (const float*)d_in[19];
    const float* olng     = (const float*)d_in[20];
    const float* olnb     = (const float*)d_in[21];
    const float* Ww       = (const float*)d_in[22];
    const float* bw       = (const float*)d_in[23];
    float* out = (float*)d_out;
    (void)in_sizes; (void)n_in;

    float *px, *ph;
    bf16 *phh, *pqkvh, *paoh, *pffh, *pwTh;
    cudaGetSymbolAddress((void**)&px,    g_x);
    cudaGetSymbolAddress((void**)&ph,    g_h);
    cudaGetSymbolAddress((void**)&phh,   g_hh);
    cudaGetSymbolAddress((void**)&pqkvh, g_qkvh);
    cudaGetSymbolAddress((void**)&paoh,  g_aoh);
    cudaGetSymbolAddress((void**)&pffh,  g_ffh);
    cudaGetSymbolAddress((void**)&pwTh,  g_wTh);

    const int GSM = 3 * (128 * 36 + 128 * 36) * 4;    // 110592
    const int FSM = (4608 + 2 * 2304 + 2 * 2304) * 4; // 55296
    cudaFuncSetAttribute(k_tgemm<false,false,false,true >, cudaFuncAttributeMaxDynamicSharedMemorySize, GSM);
    cudaFuncSetAttribute(k_tgemm<false,true, false,false>, cudaFuncAttributeMaxDynamicSharedMemorySize, GSM);
    cudaFuncSetAttribute(k_tgemm<true, false,true, true >, cudaFuncAttributeMaxDynamicSharedMemorySize, GSM);
    cudaFuncSetAttribute(k_tgemm<true, true, false,false>, cudaFuncAttributeMaxDynamicSharedMemorySize, GSM);
    cudaFuncSetAttribute(k_flash, cudaFuncAttributeMaxDynamicSharedMemorySize, FSM);

    k_zeroflags<<<cT / 256, 256>>>();
    k_setflags<<<(cB * cK) / 256, 256>>>(mask_idx);
    k_embed<<<cT, 128>>>(seq, pos_emb, mtok, p1g, p1b, W_emb, b_emb, p2g, p2b);

    // transpose all weights to bf16 [N][K], all layers at once (grid.z)
    const long long LSTR = 3145728;
    k_wt<<<dim3(1536/32, 512/32, cL), dim3(32,8)>>>(Wqkv, pwTh,            512, 1536, 786432,  LSTR);
    k_wt<<<dim3( 512/32, 512/32, cL), dim3(32,8)>>>(Wo,   pwTh + 786432,   512,  512, 262144,  LSTR);
    k_wt<<<dim3(2048/32, 512/32, cL), dim3(32,8)>>>(W1,   pwTh + 1048576,  512, 2048, 1048576, LSTR);
    k_wt<<<dim3( 512/32,2048/32, cL), dim3(32,8)>>>(W2,   pwTh + 2097152, 2048,  512, 1048576, LSTR);

    for (int l = 0; l < cL; l++) {
        bf16* baseT = pwTh + (size_t)l * LSTR;
        bf16* WqkvT = baseT;
        bf16* WoT   = baseT + 786432;
        bf16* W1T   = baseT + 1048576;
        bf16* W2T   = baseT + 2097152;

        // attention
        k_ln<true><<<cT / 8, 256>>>(px, alng + l*cD, alnb + l*cD, phh);
        k_tgemm<false,false,false,true><<<dim3(12, 64), 256, GSM>>>(
            phh, WqkvT, nullptr, nullptr, pqkvh, 512, 512, 512, 1536);
        k_flash<<<dim3(8, 64), 256, FSM>>>(pqkvh, paoh);
        k_tgemm<false,true,false,false><<<dim3(4, 64), 256, GSM>>>(
            paoh, WoT, nullptr, px, px, 512, 512, 512, 512);

        // ffn
        k_ln<true><<<cT / 8, 256>>>(px, flng + l*cD, flnb + l*cD, phh);
        k_tgemm<true,false,true,true><<<dim3(16, 64), 256, GSM>>>(
            phh, W1T, b1 + (size_t)l*cFF, nullptr, pffh, 512, 512, 512, 2048);
        k_tgemm<true,true,false,false><<<dim3(4, 64), 256, GSM>>>(
            pffh, W2T, b2 + (size_t)l*cD, px, px, 2048, 2048, 2048, 512);
    }

    k_ln<false><<<cT / 8, 256>>>(px, olng, olnb, ph);
    k_output<<<dim3(cK, cB), 256>>>(seq, mask_idx, Ww, bw, out, (long long)out_size);
}

// round 9
// speedup vs baseline: 6.5976x; 1.0190x over previous
#include <cuda_runtime.h>
#include <cuda_bf16.h>

#define DEV_INLINE __device__ __forceinline__

// Problem constants
constexpr int cB  = 8;
constexpr int cNW = 1024;
constexpr int cD  = 512;
constexpr int cH  = 8;
constexpr int cL  = 4;
constexpr int cFF = 2048;
constexpr int cK  = 512;
constexpr int cT  = cB * cNW;        // 8192 tokens
constexpr float cSCALE = 0.125f;

typedef __nv_bfloat16 bf16;

// ---------------------------------------------------------------------------
// Scratch
// ---------------------------------------------------------------------------
__device__ float g_x   [cT * cD];           // residual (fp32)
__device__ float g_h   [cT * cD];           // final LN out (fp32)
__device__ bf16  g_hh  [cT * cD];           // LN out bf16
__device__ bf16  g_qkvh[cT * 3 * cD];       // qkv bf16
__device__ bf16  g_aoh [cT * cD];           // attn out bf16
__device__ bf16  g_ffh [cT * cFF];          // ffn hidden bf16
__device__ bf16  g_wTh [12582912];          // transposed weights bf16
__device__ int   g_mflag[cT];

// ---------------------------------------------------------------------------
// Helpers
// ---------------------------------------------------------------------------
DEV_INLINE float gelu_f(float x) {
    float z = 0.7978845608028654f * (x + 0.044715f * x * x * x);
    float t = __expf(2.0f * z);
    float th = 1.0f - 2.0f / (t + 1.0f);
    return 0.5f * x * (1.0f + th);
}

DEV_INLINE unsigned pk2(float lo, float hi) {
    unsigned u;
    asm("cvt.rn.bf16x2.f32 %0, %1, %2;" : "=r"(u) : "f"(hi), "f"(lo));
    return u;
}

DEV_INLINE void mma_bf16(float* d, const unsigned* a, const unsigned* b) {
    asm volatile(
        "mma.sync.aligned.m16n8k16.row.col.f32.bf16.bf16.f32 "
        "{%0,%1,%2,%3}, {%4,%5,%6,%7}, {%8,%9}, {%0,%1,%2,%3};"
        : "+f"(d[0]), "+f"(d[1]), "+f"(d[2]), "+f"(d[3])
        : "r"(a[0]), "r"(a[1]), "r"(a[2]), "r"(a[3]), "r"(b[0]), "r"(b[1]));
}

DEV_INLINE void ldsm4(unsigned* r, unsigned addr) {
    asm volatile("ldmatrix.sync.aligned.m8n8.x4.shared.b16 {%0,%1,%2,%3}, [%4];"
        : "=r"(r[0]), "=r"(r[1]), "=r"(r[2]), "=r"(r[3]) : "r"(addr));
}
DEV_INLINE void ldsm4t(unsigned* r, unsigned addr) {
    asm volatile("ldmatrix.sync.aligned.m8n8.x4.trans.shared.b16 {%0,%1,%2,%3}, [%4];"
        : "=r"(r[0]), "=r"(r[1]), "=r"(r[2]), "=r"(r[3]) : "r"(addr));
}

DEV_INLINE void cp16(unsigned dst, const void* src) {
    asm volatile("cp.async.cg.shared.global [%0], [%1], 16;" :: "r"(dst), "l"(src));
}
#define CP_COMMIT() asm volatile("cp.async.commit_group;" ::: "memory")
#define CP_WAIT1()  asm volatile("cp.async.wait_group 1;" ::: "memory")
#define CP_WAIT0()  asm volatile("cp.async.wait_group 0;" ::: "memory")

// ---------------------------------------------------------------------------
// bf16 tensor-core GEMM, BK=64, 3-stage cp.async + ldmatrix, 2 CTAs/SM.
// C[M,N] = A[M,K] @ B[N,K]^T (+bias)(gelu)(+Res)
// BM=128, BN=128, 256 threads (8 warps: 2m x 4n), warp 64x32.
// SMEM rows of 36 u32 (32 data + 4 pad): conflict-free ldmatrix.
// ---------------------------------------------------------------------------
template<bool BIAS, bool RES, bool GELU_, bool OBF>
__global__ void __launch_bounds__(256, 2)
k_tgemm(const bf16* __restrict__ A, const bf16* __restrict__ B,
        const float* __restrict__ bias, const float* __restrict__ Res,
        void* __restrict__ Cv, int K, int sA, int sB, int sC)
{
    extern __shared__ __align__(16) unsigned dsm[];
    constexpr int ASZ = 128 * 36;
    constexpr int BSZ = 128 * 36;

    int tid = threadIdx.x;
    int wid = tid >> 5, lane = tid & 31;
    int wm = wid & 1, wn = wid >> 1;
    int lrow = lane & 7, q = lane >> 3;
    int lg = lane >> 2, lt = lane & 3;

    int bm = blockIdx.y * 128, bn = blockIdx.x * 128;
    unsigned smemU = (unsigned)__cvta_generic_to_shared(dsm);

    const int NC = K >> 6;
    float acc[4][4][4] = {};

    int pr = tid >> 3, pf = tid & 7;                 // prefetch row (0..31) / frag (0..7)
    const bf16* Apre = A + (size_t)(bm + pr) * sA + pf * 8;
    const bf16* Bpre = B + (size_t)(bn + pr) * sB + pf * 8;
    unsigned adst = smemU + (pr * 36 + pf * 4) * 4;
    unsigned bdst = smemU + (3 * ASZ + pr * 36 + pf * 4) * 4;

    unsigned aBase = smemU + ((wm * 64 + (q & 1) * 8 + lrow) * 36 + (q >> 1) * 4) * 4;
    unsigned bBase = smemU + (3 * ASZ + (wn * 32 + (q >> 1) * 8 + lrow) * 36 + (q & 1) * 4) * 4;

#define PRE(s, c) do { int k0 = (c) << 6;                                          \
    _Pragma("unroll")                                                              \
    for (int i = 0; i < 4; i++)                                                    \
        cp16(adst + (s) * ASZ * 4 + i * 32 * 36 * 4, Apre + (size_t)i * 32 * sA + k0); \
    _Pragma("unroll")                                                              \
    for (int i = 0; i < 4; i++)                                                    \
        cp16(bdst + (s) * BSZ * 4 + i * 32 * 36 * 4, Bpre + (size_t)i * 32 * sB + k0); \
    CP_COMMIT(); } while (0)

    PRE(0, 0);
    PRE(1, 1);

    for (int c = 0; c < NC; c++) {
        if (c + 1 < NC) CP_WAIT1(); else CP_WAIT0();
        __syncthreads();
        if (c + 2 < NC) PRE((c + 2) % 3, c + 2);

        int st = c % 3;
        unsigned aS = aBase + st * ASZ * 4;
        unsigned bS = bBase + st * BSZ * 4;
        #pragma unroll
        for (int ks = 0; ks < 4; ks++) {
            unsigned af[4][4], bq[2][4];
            #pragma unroll
            for (int ma = 0; ma < 4; ma++) ldsm4(af[ma], aS + (ma * 576 + ks * 8) * 4);
            #pragma unroll
            for (int nb = 0; nb < 2; nb++) ldsm4(bq[nb], bS + (nb * 576 + ks * 8) * 4);
            #pragma unroll
            for (int ma = 0; ma < 4; ma++)
                #pragma unroll
                for (int na = 0; na < 4; na++)
                    mma_bf16(acc[ma][na], af[ma], &bq[na >> 1][(na & 1) * 2]);
        }
    }

    // Epilogue
    #pragma unroll
    for (int ma = 0; ma < 4; ma++) {
        #pragma unroll
        for (int na = 0; na < 4; na++) {
            int row = bm + wm * 64 + ma * 16 + lg;
            int col = bn + wn * 32 + na * 8 + 2 * lt;
            #pragma unroll
            for (int half = 0; half < 2; half++) {
                int r = row + half * 8;
                float v0 = acc[ma][na][half * 2 + 0];
                float v1 = acc[ma][na][half * 2 + 1];
                if (BIAS) { v0 += bias[col]; v1 += bias[col + 1]; }
                if (GELU_) { v0 = gelu_f(v0); v1 = gelu_f(v1); }
                if (RES) {
                    const float* rp = Res + (size_t)r * sC + col;
                    v0 += rp[0]; v1 += rp[1];
                }
                if (OBF) {
                    *(unsigned*)((bf16*)Cv + (size_t)r * sC + col) = pk2(v0, v1);
                } else {
                    *(float2*)((float*)Cv + (size_t)r * sC + col) = make_float2(v0, v1);
                }
            }
        }
    }
#undef PRE
}

// ---------------------------------------------------------------------------
// Flash attention: per (b,h), i-tile of 128 rows, online softmax over 16
// j-tiles of 64. 256 threads, 8 warps x 16 rows. 2-stage cp.async K/V,
// ldmatrix fragments, V via ldmatrix.trans.
// ---------------------------------------------------------------------------
__global__ void __launch_bounds__(256, 2)
k_flash(const bf16* __restrict__ qkv, bf16* __restrict__ ao)
{
    extern __shared__ __align__(16) unsigned fsm[];
    // Qs [0,4608), Ks stage s at 4608 + s*2304, Vs stage s at 9216 + s*2304

    int tid = threadIdx.x;
    int wid = tid >> 5, lane = tid & 31;
    int lrow = lane & 7, q = lane >> 3;
    int lg = lane >> 2, lt = lane & 3;
    int bh = blockIdx.y, b = bh >> 3, h = bh & 7;
    int i0 = blockIdx.x * 128;

    unsigned fU = (unsigned)__cvta_generic_to_shared(fsm);

    const bf16* base = qkv + (size_t)b * cNW * 1536;
    const bf16* Qg = base + h * 64;
    const bf16* Kg = base + 512 + h * 64;
    const bf16* Vg = base + 1024 + h * 64;

    // Load Q tile (128 x 64 bf16)
    #pragma unroll
    for (int i = 0; i < 4; i++) {
        int idx = tid + i * 256;
        int r = idx >> 3, f = idx & 7;
        uint4 v = __ldg((const uint4*)(Qg + (size_t)(i0 + r) * 1536 + f * 8));
        *(uint4*)&fsm[r * 36 + f * 4] = v;
    }

    int pr2 = tid >> 3, pf2 = tid & 7;
    unsigned kdst = fU + (4608 + pr2 * 36 + pf2 * 4) * 4;
    unsigned vdst = fU + (9216 + pr2 * 36 + pf2 * 4) * 4;

#define PREKV(s, jt) do { int j0 = (jt) * 64;                                  \
    cp16(kdst + (s) * 2304 * 4,               Kg + (size_t)(j0 + pr2) * 1536 + pf2 * 8);      \
    cp16(kdst + (s) * 2304 * 4 + 32 * 36 * 4, Kg + (size_t)(j0 + pr2 + 32) * 1536 + pf2 * 8); \
    cp16(vdst + (s) * 2304 * 4,               Vg + (size_t)(j0 + pr2) * 1536 + pf2 * 8);      \
    cp16(vdst + (s) * 2304 * 4 + 32 * 36 * 4, Vg + (size_t)(j0 + pr2 + 32) * 1536 + pf2 * 8); \
    CP_COMMIT(); } while (0)

    PREKV(0, 0);

    unsigned qBase = fU + ((wid * 16 + (q & 1) * 8 + lrow) * 36 + (q >> 1) * 4) * 4;
    unsigned kBase = fU + (4608 + ((q >> 1) * 8 + lrow) * 36 + (q & 1) * 4) * 4;
    unsigned vBase = fU + (9216 + ((q & 1) * 8 + lrow) * 36 + (q >> 1) * 4) * 4;

    float m0 = -1e30f, m1 = -1e30f, l0 = 0.f, l1 = 0.f;
    float o[8][4] = {};
    int qrow = wid * 16 + lg;

    for (int jt = 0; jt < 16; jt++) {
        CP_WAIT0();
        __syncthreads();
        if (jt + 1 < 16) PREKV((jt + 1) & 1, jt + 1);

        int buf = jt & 1;
        unsigned kS = kBase + buf * 2304 * 4;
        unsigned vS = vBase + buf * 2304 * 4;

        // S = Q @ K^T
        float sacc[8][4] = {};
        #pragma unroll
        for (int ks = 0; ks < 4; ks++) {
            unsigned aq[4];
            ldsm4(aq, qBase + ks * 8 * 4);
            #pragma unroll
            for (int nb = 0; nb < 4; nb++) {
                unsigned kq[4];
                ldsm4(kq, kS + (nb * 576 + ks * 8) * 4);
                mma_bf16(sacc[2 * nb],     aq, &kq[0]);
                mma_bf16(sacc[2 * nb + 1], aq, &kq[2]);
            }
        }

        // scale + row stats
        float mx0 = -1e30f, mx1 = -1e30f;
        #pragma unroll
        for (int na = 0; na < 8; na++) {
            #pragma unroll
            for (int c2 = 0; c2 < 4; c2++) sacc[na][c2] *= cSCALE;
            mx0 = fmaxf(mx0, fmaxf(sacc[na][0], sacc[na][1]));
            mx1 = fmaxf(mx1, fmaxf(sacc[na][2], sacc[na][3]));
        }
        #pragma unroll
        for (int o2 = 1; o2 < 4; o2 <<= 1) {
            mx0 = fmaxf(mx0, __shfl_xor_sync(0xffffffffu, mx0, o2));
            mx1 = fmaxf(mx1, __shfl_xor_sync(0xffffffffu, mx1, o2));
        }
        float nm0 = fmaxf(m0, mx0), nm1 = fmaxf(m1, mx1);
        float cr0 = __expf(m0 - nm0), cr1 = __expf(m1 - nm1);
        m0 = nm0; m1 = nm1;

        float sum0 = 0.f, sum1 = 0.f;
        #pragma unroll
        for (int na = 0; na < 8; na++) {
            sacc[na][0] = __expf(sacc[na][0] - nm0);
            sacc[na][1] = __expf(sacc[na][1] - nm0);
            sacc[na][2] = __expf(sacc[na][2] - nm1);
            sacc[na][3] = __expf(sacc[na][3] - nm1);
            sum0 += sacc[na][0] + sacc[na][1];
            sum1 += sacc[na][2] + sacc[na][3];
        }
        #pragma unroll
        for (int o2 = 1; o2 < 4; o2 <<= 1) {
            sum0 += __shfl_xor_sync(0xffffffffu, sum0, o2);
            sum1 += __shfl_xor_sync(0xffffffffu, sum1, o2);
        }
        l0 = l0 * cr0 + sum0;
        l1 = l1 * cr1 + sum1;
        #pragma unroll
        for (int na = 0; na < 8; na++) {
            o[na][0] *= cr0; o[na][1] *= cr0;
            o[na][2] *= cr1; o[na][3] *= cr1;
        }

        // O += P @ V
        #pragma unroll
        for (int ks = 0; ks < 4; ks++) {
            unsigned pa[4];
            pa[0] = pk2(sacc[2*ks][0],   sacc[2*ks][1]);
            pa[1] = pk2(sacc[2*ks][2],   sacc[2*ks][3]);
            pa[2] = pk2(sacc[2*ks+1][0], sacc[2*ks+1][1]);
            pa[3] = pk2(sacc[2*ks+1][2], sacc[2*ks+1][3]);
            #pragma unroll
            for (int nb = 0; nb < 4; nb++) {
                unsigned vq[4];
                ldsm4t(vq, vS + (ks * 16 * 36 + nb * 8) * 4);
                mma_bf16(o[2 * nb],     pa, &vq[0]);
                mma_bf16(o[2 * nb + 1], pa, &vq[2]);
            }
        }
    }

    float inv0 = 1.f / l0, inv1 = 1.f / l1;
    bf16* aoG = ao + ((size_t)b * cNW + i0) * cD + h * 64;
    #pragma unroll
    for (int na = 0; na < 8; na++) {
        int col = na * 8 + 2 * lt;
        *(unsigned*)(aoG + (size_t)qrow * cD + col)       = pk2(o[na][0] * inv0, o[na][1] * inv0);
        *(unsigned*)(aoG + (size_t)(qrow + 8) * cD + col) = pk2(o[na][2] * inv1, o[na][3] * inv1);
    }
#undef PREKV
}

// ---------------------------------------------------------------------------
// Merged weight transpose fp32 -> bf16 [N][K]: one launch, all matrices,
// all layers. Flattened 1D grid; per-layer tile counts:
//   Wqkv 48x16=768, Wo 16x16=256, W1 64x16=1024, W2 16x64=1024 -> 3072/layer.
// ---------------------------------------------------------------------------
__global__ void k_wtall(const float* __restrict__ Wqkv, const float* __restrict__ Wo,
                        const float* __restrict__ W1, const float* __restrict__ W2,
                        bf16* __restrict__ outT) {
    __shared__ float t[32][33];
    int bid = blockIdx.x;
    int layer = bid / 3072;
    int r = bid % 3072;

    const float* in; bf16* out; int R, Cc, tx, ty;
    if (r < 768)        { in = Wqkv + (size_t)layer * 786432;  out = outT + (size_t)layer * 3145728;
                          R = 512; Cc = 1536; tx = r % 48; ty = r / 48; }
    else if (r < 1024)  { r -= 768;
                          in = Wo + (size_t)layer * 262144;    out = outT + (size_t)layer * 3145728 + 786432;
                          R = 512; Cc = 512;  tx = r % 16; ty = r / 16; }
    else if (r < 2048)  { r -= 1024;
                          in = W1 + (size_t)layer * 1048576;   out = outT + (size_t)layer * 3145728 + 1048576;
                          R = 512; Cc = 2048; tx = r % 64; ty = r / 64; }
    else                { r -= 2048;
                          in = W2 + (size_t)layer * 1048576;   out = outT + (size_t)layer * 3145728 + 2097152;
                          R = 2048; Cc = 512; tx = r % 16; ty = r / 16; }

    int c0 = tx * 32, r0 = ty * 32;
    #pragma unroll
    for (int i = 0; i < 4; i++)
        t[threadIdx.y + i * 8][threadIdx.x] = in[(size_t)(r0 + threadIdx.y + i * 8) * Cc + c0 + threadIdx.x];
    __syncthreads();
    #pragma unroll
    for (int i = 0; i < 4; i++)
        out[(size_t)(c0 + threadIdx.y + i * 8) * R + r0 + threadIdx.x] =
            __float2bfloat16(t[threadIdx.x][threadIdx.y + i * 8]);
}

// ---------------------------------------------------------------------------
// Reductions
// ---------------------------------------------------------------------------
template<int NWARPS>
DEV_INLINE void block_sum2(float& s, float& s2) {
    #pragma unroll
    for (int o = 16; o > 0; o >>= 1) {
        s  += __shfl_down_sync(0xffffffffu, s,  o);
        s2 += __shfl_down_sync(0xffffffffu, s2, o);
    }
    __shared__ float sh_a[NWARPS], sh_b[NWARPS];
    int w = threadIdx.x >> 5;
    if ((threadIdx.x & 31) == 0) { sh_a[w] = s; sh_b[w] = s2; }
    __syncthreads();
    if (threadIdx.x == 0) {
        float a = sh_a[0], b = sh_b[0];
        #pragma unroll
        for (int i = 1; i < NWARPS; i++) { a += sh_a[i]; b += sh_b[i]; }
        sh_a[0] = a; sh_b[0] = b;
    }
    __syncthreads();
    s = sh_a[0]; s2 = sh_b[0];
}

// ---------------------------------------------------------------------------
// Flags / embed / ln / output
// ---------------------------------------------------------------------------
__global__ void k_zeroflags() {
    int i = blockIdx.x * blockDim.x + threadIdx.x;
    if (i < cT) g_mflag[i] = 0;
}
__global__ void k_setflags(const int* __restrict__ mask_idx) {
    int i = blockIdx.x * blockDim.x + threadIdx.x;
    if (i < cB * cK) g_mflag[(i / cK) * cNW + mask_idx[i]] = 1;
}

__global__ void __launch_bounds__(128) k_embed(
    const float* __restrict__ seq, const float* __restrict__ pos_emb,
    const float* __restrict__ mtok,
    const float* __restrict__ p1g, const float* __restrict__ p1b,
    const float* __restrict__ W_emb, const float* __restrict__ b_emb,
    const float* __restrict__ p2g, const float* __restrict__ p2b)
{
    int tok = blockIdx.x;
    int w = tok & (cNW - 1);
    int t = threadIdx.x;
    const float* pos = pos_emb + (size_t)(w + 1) * cD;
    float* out = g_x + (size_t)tok * cD;

    if (g_mflag[tok]) {
        #pragma unroll
        for (int j = 0; j < 4; j++) { int d = t + j * 128; out[d] = mtok[d] + pos[d]; }
        return;
    }
    __shared__ float wsm[32];
    __shared__ float lnw[32];
    const float* wrow = seq + (size_t)tok * 32;
    if (t < 32) wsm[t] = wrow[t];
    __syncthreads();
    float m = 0.f;
    #pragma unroll
    for (int c = 0; c < 32; c++) m += wsm[c];
    m *= (1.f / 32.f);
    float v = 0.f;
    #pragma unroll
    for (int c = 0; c < 32; c++) { float d0 = wsm[c] - m; v += d0 * d0; }
    v *= (1.f / 32.f);
    float rs = rsqrtf(v + 1e-5f);
    if (t < 32) lnw[t] = (wsm[t] - m) * rs * p1g[t] + p1b[t];
    __syncthreads();
    float acc[4];
    #pragma unroll
    for (int j = 0; j < 4; j++) {
        int d = t + j * 128;
        float a = b_emb[d];
        #pragma unroll
        for (int c = 0; c < 32; c++) a += lnw[c] * W_emb[c * cD + d];
        acc[j] = a;
    }
    float s = 0.f, s2 = 0.f;
    #pragma unroll
    for (int j = 0; j < 4; j++) { s += acc[j]; s2 += acc[j] * acc[j]; }
    block_sum2<4>(s, s2);
    float mean = s * (1.f / cD);
    float var  = s2 * (1.f / cD) - mean * mean;
    float rstd = rsqrtf(var + 1e-5f);
    #pragma unroll
    for (int j = 0; j < 4; j++) {
        int d = t + j * 128;
        out[d] = (acc[j] - mean) * rstd * p2g[d] + p2b[d] + pos[d];
    }
}

// Warp-per-row LayerNorm: 8 rows per 256-thread block, shuffle-only reduce.
template<bool OBF>
__global__ void __launch_bounds__(256) k_ln(
    const float* __restrict__ x, const float* __restrict__ g,
    const float* __restrict__ bt, void* __restrict__ y)
{
    int row = blockIdx.x * 8 + (threadIdx.x >> 5);
    int lane = threadIdx.x & 31;
    const float4* xr = (const float4*)(x + (size_t)row * cD);
    float4 a[4];
    #pragma unroll
    for (int i = 0; i < 4; i++) a[i] = xr[lane + i * 32];
    float s = 0.f, s2 = 0.f;
    #pragma unroll
    for (int i = 0; i < 4; i++) {
        s  += a[i].x + a[i].y + a[i].z + a[i].w;
        s2 += a[i].x*a[i].x + a[i].y*a[i].y + a[i].z*a[i].z + a[i].w*a[i].w;
    }
    #pragma unroll
    for (int o = 16; o > 0; o >>= 1) {
        s  += __shfl_xor_sync(0xffffffffu, s,  o);
        s2 += __shfl_xor_sync(0xffffffffu, s2, o);
    }
    float mean = s * (1.f / cD);
    float var  = s2 * (1.f / cD) - mean * mean;
    float rstd = rsqrtf(var + 1e-5f);
    #pragma unroll
    for (int i = 0; i < 4; i++) {
        int c4 = lane + i * 32;
        float4 gg = ((const float4*)g)[c4];
        float4 bb = ((const float4*)bt)[c4];
        float o0 = (a[i].x - mean) * rstd * gg.x + bb.x;
        float o1 = (a[i].y - mean) * rstd * gg.y + bb.y;
        float o2 = (a[i].z - mean) * rstd * gg.z + bb.z;
        float o3 = (a[i].w - mean) * rstd * gg.w + bb.w;
        if (OBF) {
            uint2 u = make_uint2(pk2(o0, o1), pk2(o2, o3));
            *(uint2*)((bf16*)y + (size_t)row * cD + c4 * 4) = u;
        } else {
            ((float4*)((float*)y + (size_t)row * cD))[c4] = make_float4(o0, o1, o2, o3);
        }
    }
}

__global__ void __launch_bounds__(256) k_output(
    const float* __restrict__ seq, const int* __restrict__ mask_idx,
    const float* __restrict__ Ww, const float* __restrict__ bw,
    float* __restrict__ out, long long out_size)
{
    int b = blockIdx.y, k = blockIdx.x;
    int idx = mask_idx[b * cK + k];
    const float* enc = g_h + ((size_t)b * cNW + idx) * cD;
    __shared__ float es[cD];
    __shared__ float lgt[32];
    int t = threadIdx.x;
    ((float2*)es)[t] = ((const float2*)enc)[t];
    __syncthreads();
    int lg = t >> 3, sg = t & 7;
    float part = 0.f;
    #pragma unroll
    for (int c = 0; c < 64; c++) {
        int cc = sg * 64 + c;
        part += es[cc] * Ww[cc * 32 + lg];
    }
    part += __shfl_down_sync(0xffffffffu, part, 4);
    part += __shfl_down_sync(0xffffffffu, part, 2);
    part += __shfl_down_sync(0xffffffffu, part, 1);
    if (sg == 0) lgt[lg] = part + bw[lg];
    __syncthreads();
    size_t base = (size_t)b * cK + k;
    if (t < 8) {
        float l0 = lgt[t*4+0], l1 = lgt[t*4+1], l2 = lgt[t*4+2], l3 = lgt[t*4+3];
        float mx = fmaxf(fmaxf(l0, l1), fmaxf(l2, l3));
        float e0 = expf(l0 - mx), e1 = expf(l1 - mx), e2 = expf(l2 - mx), e3 = expf(l3 - mx);
        float inv = 1.f / (e0 + e1 + e2 + e3);
        size_t off = base * 32 + t * 4;
        if ((long long)(off + 3) < out_size) {
            out[off+0] = e0*inv; out[off+1] = e1*inv; out[off+2] = e2*inv; out[off+3] = e3*inv;
        }
    }
    if (t < 32) {
        size_t off = (size_t)cB * cK * 32 + base * 32 + t;
        if ((long long)off < out_size)
            out[off] = seq[((size_t)b * cNW + idx) * 32 + t];
    }
}

// ---------------------------------------------------------------------------
// Launch
// ---------------------------------------------------------------------------
extern "C" void kernel_launch(void* const* d_in, const int* in_sizes, int n_in,
                              void* d_out, int out_size)
{
    const float* seq      = (const float*)d_in[0];
    const int*   mask_idx = (const int*)  d_in[1];
    const float* pos_emb  = (const float*)d_in[2];
    const float* mtok     = (const float*)d_in[3];
    const float* p1g      = (const float*)d_in[4];
    const float* p1b      = (const float*)d_in[5];
    const float* W_emb    = (const float*)d_in[6];
    const float* b_emb    = (const float*)d_in[7];
    const float* p2g      = (const float*)d_in[8];
    const float* p2b      = (const float*)d_in[9];
    const float* alng     = (const float*)d_in[10];
    const float* alnb     = (const float*)d_in[11];
    const float* Wqkv     = (const float*)d_in[12];
    const float* Wo       = (const float*)d_in[13];
    const float* flng     = (const float*)d_in[14];
    const float* flnb     = (const float*)d_in[15];
    const float* W1       = (const float*)d_in[16];
    const float* b1       = (const float*)d_in[17];
    const float* W2       = (const float*)d_in[18];
    const float* b2       = (const float*)d_in[19];
    const float* olng     = (const float*)d_in[20];
    const float* olnb     = (const float*)d_in[21];
    const float* Ww       = (const float*)d_in[22];
    const float* bw       = (const float*)d_in[23];
    float* out = (float*)d_out;
    (void)in_sizes; (void)n_in;

    float *px, *ph;
    bf16 *phh, *pqkvh, *paoh, *pffh, *pwTh;
    cudaGetSymbolAddress((void**)&px,    g_x);
    cudaGetSymbolAddress((void**)&ph,    g_h);
    cudaGetSymbolAddress((void**)&phh,   g_hh);
    cudaGetSymbolAddress((void**)&pqkvh, g_qkvh);
    cudaGetSymbolAddress((void**)&paoh,  g_aoh);
    cudaGetSymbolAddress((void**)&pffh,  g_ffh);
    cudaGetSymbolAddress((void**)&pwTh,  g_wTh);

    const int GSM = 3 * (128 * 36 + 128 * 36) * 4;    // 110592
    const int FSM = (4608 + 2 * 2304 + 2 * 2304) * 4; // 55296
    cudaFuncSetAttribute(k_tgemm<false,false,false,true >, cudaFuncAttributeMaxDynamicSharedMemorySize, GSM);
    cudaFuncSetAttribute(k_tgemm<false,true, false,false>, cudaFuncAttributeMaxDynamicSharedMemorySize, GSM);
    cudaFuncSetAttribute(k_tgemm<true, false,true, true >, cudaFuncAttributeMaxDynamicSharedMemorySize, GSM);
    cudaFuncSetAttribute(k_tgemm<true, true, false,false>, cudaFuncAttributeMaxDynamicSharedMemorySize, GSM);
    cudaFuncSetAttribute(k_flash, cudaFuncAttributeMaxDynamicSharedMemorySize, FSM);

    k_zeroflags<<<cT / 256, 256>>>();
    k_setflags<<<(cB * cK) / 256, 256>>>(mask_idx);
    k_embed<<<cT, 128>>>(seq, pos_emb, mtok, p1g, p1b, W_emb, b_emb, p2g, p2b);

    // all weight transposes (fp32 -> bf16 [N][K]) in ONE launch
    k_wtall<<<3072 * cL, dim3(32, 8)>>>(Wqkv, Wo, W1, W2, pwTh);

    for (int l = 0; l < cL; l++) {
        bf16* baseT = pwTh + (size_t)l * 3145728;
        bf16* WqkvT = baseT;
        bf16* WoT   = baseT + 786432;
        bf16* W1T   = baseT + 1048576;
        bf16* W2T   = baseT + 2097152;

        // attention
        k_ln<true><<<cT / 8, 256>>>(px, alng + l*cD, alnb + l*cD, phh);
        k_tgemm<false,false,false,true><<<dim3(12, 64), 256, GSM>>>(
            phh, WqkvT, nullptr, nullptr, pqkvh, 512, 512, 512, 1536);
        k_flash<<<dim3(8, 64), 256, FSM>>>(pqkvh, paoh);
        k_tgemm<false,true,false,false><<<dim3(4, 64), 256, GSM>>>(
            paoh, WoT, nullptr, px, px, 512, 512, 512, 512);

        // ffn
        k_ln<true><<<cT / 8, 256>>>(px, flng + l*cD, flnb + l*cD, phh);
        k_tgemm<true,false,true,true><<<dim3(16, 64), 256, GSM>>>(
            phh, W1T, b1 + (size_t)l*cFF, nullptr, pffh, 512, 512, 512, 2048);
        k_tgemm<true,true,false,false><<<dim3(4, 64), 256, GSM>>>(
            pffh, W2T, b2 + (size_t)l*cD, px, px, 2048, 2048, 2048, 512);
    }

    k_ln<false><<<cT / 8, 256>>>(px, olng, olnb, ph);
    k_output<<<dim3(cK, cB), 256>>>(seq, mask_idx, Ww, bw, out, (long long)out_size);
}

// round 10
// speedup vs baseline: 6.7536x; 1.0236x over previous
#include <cuda_runtime.h>
#include <cuda_bf16.h>

#define DEV_INLINE __device__ __forceinline__

// Problem constants
constexpr int cB  = 8;
constexpr int cNW = 1024;
constexpr int cD  = 512;
constexpr int cH  = 8;
constexpr int cL  = 4;
constexpr int cFF = 2048;
constexpr int cK  = 512;
constexpr int cT  = cB * cNW;        // 8192 tokens
constexpr float cSCALE = 0.125f;
constexpr float cSC2   = 0.125f * 1.4426950408889634f;  // SCALE * log2(e)

typedef __nv_bfloat16 bf16;

// ---------------------------------------------------------------------------
// Scratch
// ---------------------------------------------------------------------------
__device__ float g_x   [cT * cD];           // residual (fp32)
__device__ float g_h   [cT * cD];           // final LN out (fp32)
__device__ bf16  g_hh  [cT * cD];           // LN out bf16
__device__ bf16  g_qkvh[cT * 3 * cD];       // qkv bf16
__device__ bf16  g_aoh [cT * cD];           // attn out bf16
__device__ bf16  g_ffh [cT * cFF];          // ffn hidden bf16
__device__ bf16  g_wTh [12582912];          // transposed weights bf16
__device__ int   g_mflag[cT];

// ---------------------------------------------------------------------------
// Helpers
// ---------------------------------------------------------------------------
DEV_INLINE float gelu_f(float x) {
    float z = 0.7978845608028654f * (x + 0.044715f * x * x * x);
    float t = __expf(2.0f * z);
    float th = 1.0f - 2.0f / (t + 1.0f);
    return 0.5f * x * (1.0f + th);
}

DEV_INLINE unsigned pk2(float lo, float hi) {
    unsigned u;
    asm("cvt.rn.bf16x2.f32 %0, %1, %2;" : "=r"(u) : "f"(hi), "f"(lo));
    return u;
}

DEV_INLINE void mma_bf16(float* d, const unsigned* a, const unsigned* b) {
    asm volatile(
        "mma.sync.aligned.m16n8k16.row.col.f32.bf16.bf16.f32 "
        "{%0,%1,%2,%3}, {%4,%5,%6,%7}, {%8,%9}, {%0,%1,%2,%3};"
        : "+f"(d[0]), "+f"(d[1]), "+f"(d[2]), "+f"(d[3])
        : "r"(a[0]), "r"(a[1]), "r"(a[2]), "r"(a[3]), "r"(b[0]), "r"(b[1]));
}

DEV_INLINE void ldsm4(unsigned* r, unsigned addr) {
    asm volatile("ldmatrix.sync.aligned.m8n8.x4.shared.b16 {%0,%1,%2,%3}, [%4];"
        : "=r"(r[0]), "=r"(r[1]), "=r"(r[2]), "=r"(r[3]) : "r"(addr));
}
DEV_INLINE void ldsm4t(unsigned* r, unsigned addr) {
    asm volatile("ldmatrix.sync.aligned.m8n8.x4.trans.shared.b16 {%0,%1,%2,%3}, [%4];"
        : "=r"(r[0]), "=r"(r[1]), "=r"(r[2]), "=r"(r[3]) : "r"(addr));
}

DEV_INLINE void cp16(unsigned dst, const void* src) {
    asm volatile("cp.async.cg.shared.global [%0], [%1], 16;" :: "r"(dst), "l"(src));
}
#define CP_COMMIT() asm volatile("cp.async.commit_group;" ::: "memory")
#define CP_WAIT1()  asm volatile("cp.async.wait_group 1;" ::: "memory")
#define CP_WAIT0()  asm volatile("cp.async.wait_group 0;" ::: "memory")

// ---------------------------------------------------------------------------
// bf16 tensor-core GEMM, BK=64, 3-stage cp.async + ldmatrix, 2 CTAs/SM.
// C[M,N] = A[M,K] @ B[N,K]^T (+bias)(gelu)(+Res)
// BM=128, BN=128, 256 threads (8 warps: 2m x 4n), warp 64x32.
// SMEM rows of 36 u32 (32 data + 4 pad): conflict-free ldmatrix.
// ---------------------------------------------------------------------------
template<bool BIAS, bool RES, bool GELU_, bool OBF>
__global__ void __launch_bounds__(256, 2)
k_tgemm(const bf16* __restrict__ A, const bf16* __restrict__ B,
        const float* __restrict__ bias, const float* __restrict__ Res,
        void* __restrict__ Cv, int K, int sA, int sB, int sC)
{
    extern __shared__ __align__(16) unsigned dsm[];
    constexpr int ASZ = 128 * 36;
    constexpr int BSZ = 128 * 36;

    int tid = threadIdx.x;
    int wid = tid >> 5, lane = tid & 31;
    int wm = wid & 1, wn = wid >> 1;
    int lrow = lane & 7, q = lane >> 3;
    int lg = lane >> 2, lt = lane & 3;

    int bm = blockIdx.y * 128, bn = blockIdx.x * 128;
    unsigned smemU = (unsigned)__cvta_generic_to_shared(dsm);

    const int NC = K >> 6;
    float acc[4][4][4] = {};

    int pr = tid >> 3, pf = tid & 7;
    const bf16* Apre = A + (size_t)(bm + pr) * sA + pf * 8;
    const bf16* Bpre = B + (size_t)(bn + pr) * sB + pf * 8;
    unsigned adst = smemU + (pr * 36 + pf * 4) * 4;
    unsigned bdst = smemU + (3 * ASZ + pr * 36 + pf * 4) * 4;

    unsigned aBase = smemU + ((wm * 64 + (q & 1) * 8 + lrow) * 36 + (q >> 1) * 4) * 4;
    unsigned bBase = smemU + (3 * ASZ + (wn * 32 + (q >> 1) * 8 + lrow) * 36 + (q & 1) * 4) * 4;

#define PRE(s, c) do { int k0 = (c) << 6;                                          \
    _Pragma("unroll")                                                              \
    for (int i = 0; i < 4; i++)                                                    \
        cp16(adst + (s) * ASZ * 4 + i * 32 * 36 * 4, Apre + (size_t)i * 32 * sA + k0); \
    _Pragma("unroll")                                                              \
    for (int i = 0; i < 4; i++)                                                    \
        cp16(bdst + (s) * BSZ * 4 + i * 32 * 36 * 4, Bpre + (size_t)i * 32 * sB + k0); \
    CP_COMMIT(); } while (0)

    PRE(0, 0);
    PRE(1, 1);

    for (int c = 0; c < NC; c++) {
        if (c + 1 < NC) CP_WAIT1(); else CP_WAIT0();
        __syncthreads();
        if (c + 2 < NC) PRE((c + 2) % 3, c + 2);

        int st = c % 3;
        unsigned aS = aBase + st * ASZ * 4;
        unsigned bS = bBase + st * BSZ * 4;
        #pragma unroll
        for (int ks = 0; ks < 4; ks++) {
            unsigned af[4][4], bq[2][4];
            #pragma unroll
            for (int ma = 0; ma < 4; ma++) ldsm4(af[ma], aS + (ma * 576 + ks * 8) * 4);
            #pragma unroll
            for (int nb = 0; nb < 2; nb++) ldsm4(bq[nb], bS + (nb * 576 + ks * 8) * 4);
            #pragma unroll
            for (int ma = 0; ma < 4; ma++)
                #pragma unroll
                for (int na = 0; na < 4; na++)
                    mma_bf16(acc[ma][na], af[ma], &bq[na >> 1][(na & 1) * 2]);
        }
    }

    // Epilogue
    #pragma unroll
    for (int ma = 0; ma < 4; ma++) {
        #pragma unroll
        for (int na = 0; na < 4; na++) {
            int row = bm + wm * 64 + ma * 16 + lg;
            int col = bn + wn * 32 + na * 8 + 2 * lt;
            #pragma unroll
            for (int half = 0; half < 2; half++) {
                int r = row + half * 8;
                float v0 = acc[ma][na][half * 2 + 0];
                float v1 = acc[ma][na][half * 2 + 1];
                if (BIAS) { v0 += bias[col]; v1 += bias[col + 1]; }
                if (GELU_) { v0 = gelu_f(v0); v1 = gelu_f(v1); }
                if (RES) {
                    const float* rp = Res + (size_t)r * sC + col;
                    v0 += rp[0]; v1 += rp[1];
                }
                if (OBF) {
                    *(unsigned*)((bf16*)Cv + (size_t)r * sC + col) = pk2(v0, v1);
                } else {
                    *(float2*)((float*)Cv + (size_t)r * sC + col) = make_float2(v0, v1);
                }
            }
        }
    }
#undef PRE
}

// ---------------------------------------------------------------------------
// Flash attention: per (b,h), i-tile of 128 rows, online softmax over 16
// j-tiles of 64. 256 threads, 8 warps x 16 rows. 2-stage cp.async K/V,
// Q fragments hoisted to registers, exp2-domain softmax.
// ---------------------------------------------------------------------------
__global__ void __launch_bounds__(256, 2)
k_flash(const bf16* __restrict__ qkv, bf16* __restrict__ ao)
{
    extern __shared__ __align__(16) unsigned fsm[];
    // Qs [0,4608), Ks stage s at 4608 + s*2304, Vs stage s at 9216 + s*2304

    int tid = threadIdx.x;
    int wid = tid >> 5, lane = tid & 31;
    int lrow = lane & 7, q = lane >> 3;
    int lg = lane >> 2, lt = lane & 3;
    int bh = blockIdx.y, b = bh >> 3, h = bh & 7;
    int i0 = blockIdx.x * 128;

    unsigned fU = (unsigned)__cvta_generic_to_shared(fsm);

    const bf16* base = qkv + (size_t)b * cNW * 1536;
    const bf16* Qg = base + h * 64;
    const bf16* Kg = base + 512 + h * 64;
    const bf16* Vg = base + 1024 + h * 64;

    // Load Q tile (128 x 64 bf16)
    #pragma unroll
    for (int i = 0; i < 4; i++) {
        int idx = tid + i * 256;
        int r = idx >> 3, f = idx & 7;
        uint4 v = __ldg((const uint4*)(Qg + (size_t)(i0 + r) * 1536 + f * 8));
        *(uint4*)&fsm[r * 36 + f * 4] = v;
    }

    int pr2 = tid >> 3, pf2 = tid & 7;
    unsigned kdst = fU + (4608 + pr2 * 36 + pf2 * 4) * 4;
    unsigned vdst = fU + (9216 + pr2 * 36 + pf2 * 4) * 4;

#define PREKV(s, jt) do { int j0 = (jt) * 64;                                  \
    cp16(kdst + (s) * 2304 * 4,               Kg + (size_t)(j0 + pr2) * 1536 + pf2 * 8);      \
    cp16(kdst + (s) * 2304 * 4 + 32 * 36 * 4, Kg + (size_t)(j0 + pr2 + 32) * 1536 + pf2 * 8); \
    cp16(vdst + (s) * 2304 * 4,               Vg + (size_t)(j0 + pr2) * 1536 + pf2 * 8);      \
    cp16(vdst + (s) * 2304 * 4 + 32 * 36 * 4, Vg + (size_t)(j0 + pr2 + 32) * 1536 + pf2 * 8); \
    CP_COMMIT(); } while (0)

    PREKV(0, 0);

    unsigned qBase = fU + ((wid * 16 + (q & 1) * 8 + lrow) * 36 + (q >> 1) * 4) * 4;
    unsigned kBase = fU + (4608 + ((q >> 1) * 8 + lrow) * 36 + (q & 1) * 4) * 4;
    unsigned vBase = fU + (9216 + ((q & 1) * 8 + lrow) * 36 + (q >> 1) * 4) * 4;

    // Hoist Q fragments to registers (loop-invariant)
    __syncthreads();
    unsigned qf[4][4];
    #pragma unroll
    for (int ks = 0; ks < 4; ks++) ldsm4(qf[ks], qBase + ks * 8 * 4);

    float m0 = -1e30f, m1 = -1e30f, l0 = 0.f, l1 = 0.f;
    float o[8][4] = {};
    int qrow = wid * 16 + lg;

    for (int jt = 0; jt < 16; jt++) {
        CP_WAIT0();
        __syncthreads();
        if (jt + 1 < 16) PREKV((jt + 1) & 1, jt + 1);

        int buf = jt & 1;
        unsigned kS = kBase + buf * 2304 * 4;
        unsigned vS = vBase + buf * 2304 * 4;

        // S = Q @ K^T
        float sacc[8][4] = {};
        #pragma unroll
        for (int ks = 0; ks < 4; ks++) {
            #pragma unroll
            for (int nb = 0; nb < 4; nb++) {
                unsigned kq[4];
                ldsm4(kq, kS + (nb * 576 + ks * 8) * 4);
                mma_bf16(sacc[2 * nb],     qf[ks], &kq[0]);
                mma_bf16(sacc[2 * nb + 1], qf[ks], &kq[2]);
            }
        }

        // scale into exp2 domain + row stats
        float mx0 = -1e30f, mx1 = -1e30f;
        #pragma unroll
        for (int na = 0; na < 8; na++) {
            #pragma unroll
            for (int c2 = 0; c2 < 4; c2++) sacc[na][c2] *= cSC2;
            mx0 = fmaxf(mx0, fmaxf(sacc[na][0], sacc[na][1]));
            mx1 = fmaxf(mx1, fmaxf(sacc[na][2], sacc[na][3]));
        }
        #pragma unroll
        for (int o2 = 1; o2 < 4; o2 <<= 1) {
            mx0 = fmaxf(mx0, __shfl_xor_sync(0xffffffffu, mx0, o2));
            mx1 = fmaxf(mx1, __shfl_xor_sync(0xffffffffu, mx1, o2));
        }
        float nm0 = fmaxf(m0, mx0), nm1 = fmaxf(m1, mx1);
        float cr0 = exp2f(m0 - nm0), cr1 = exp2f(m1 - nm1);
        m0 = nm0; m1 = nm1;

        float sum0 = 0.f, sum1 = 0.f;
        #pragma unroll
        for (int na = 0; na < 8; na++) {
            sacc[na][0] = exp2f(sacc[na][0] - nm0);
            sacc[na][1] = exp2f(sacc[na][1] - nm0);
            sacc[na][2] = exp2f(sacc[na][2] - nm1);
            sacc[na][3] = exp2f(sacc[na][3] - nm1);
            sum0 += sacc[na][0] + sacc[na][1];
            sum1 += sacc[na][2] + sacc[na][3];
        }
        #pragma unroll
        for (int o2 = 1; o2 < 4; o2 <<= 1) {
            sum0 += __shfl_xor_sync(0xffffffffu, sum0, o2);
            sum1 += __shfl_xor_sync(0xffffffffu, sum1, o2);
        }
        l0 = l0 * cr0 + sum0;
        l1 = l1 * cr1 + sum1;
        #pragma unroll
        for (int na = 0; na < 8; na++) {
            o[na][0] *= cr0; o[na][1] *= cr0;
            o[na][2] *= cr1; o[na][3] *= cr1;
        }

        // O += P @ V
        #pragma unroll
        for (int ks = 0; ks < 4; ks++) {
            unsigned pa[4];
            pa[0] = pk2(sacc[2*ks][0],   sacc[2*ks][1]);
            pa[1] = pk2(sacc[2*ks][2],   sacc[2*ks][3]);
            pa[2] = pk2(sacc[2*ks+1][0], sacc[2*ks+1][1]);
            pa[3] = pk2(sacc[2*ks+1][2], sacc[2*ks+1][3]);
            #pragma unroll
            for (int nb = 0; nb < 4; nb++) {
                unsigned vq[4];
                ldsm4t(vq, vS + (ks * 16 * 36 + nb * 8) * 4);
                mma_bf16(o[2 * nb],     pa, &vq[0]);
                mma_bf16(o[2 * nb + 1], pa, &vq[2]);
            }
        }
    }

    float inv0 = 1.f / l0, inv1 = 1.f / l1;
    bf16* aoG = ao + ((size_t)b * cNW + i0) * cD + h * 64;
    #pragma unroll
    for (int na = 0; na < 8; na++) {
        int col = na * 8 + 2 * lt;
        *(unsigned*)(aoG + (size_t)qrow * cD + col)       = pk2(o[na][0] * inv0, o[na][1] * inv0);
        *(unsigned*)(aoG + (size_t)(qrow + 8) * cD + col) = pk2(o[na][2] * inv1, o[na][3] * inv1);
    }
#undef PREKV
}

// ---------------------------------------------------------------------------
// Merged weight transpose fp32 -> bf16 [N][K]: one launch, all matrices,
// all layers.
// ---------------------------------------------------------------------------
__global__ void k_wtall(const float* __restrict__ Wqkv, const float* __restrict__ Wo,
                        const float* __restrict__ W1, const float* __restrict__ W2,
                        bf16* __restrict__ outT) {
    __shared__ float t[32][33];
    int bid = blockIdx.x;
    int layer = bid / 3072;
    int r = bid % 3072;

    const float* in; bf16* out; int R, Cc, tx, ty;
    if (r < 768)        { in = Wqkv + (size_t)layer * 786432;  out = outT + (size_t)layer * 3145728;
                          R = 512; Cc = 1536; tx = r % 48; ty = r / 48; }
    else if (r < 1024)  { r -= 768;
                          in = Wo + (size_t)layer * 262144;    out = outT + (size_t)layer * 3145728 + 786432;
                          R = 512; Cc = 512;  tx = r % 16; ty = r / 16; }
    else if (r < 2048)  { r -= 1024;
                          in = W1 + (size_t)layer * 1048576;   out = outT + (size_t)layer * 3145728 + 1048576;
                          R = 512; Cc = 2048; tx = r % 64; ty = r / 64; }
    else                { r -= 2048;
                          in = W2 + (size_t)layer * 1048576;   out = outT + (size_t)layer * 3145728 + 2097152;
                          R = 2048; Cc = 512; tx = r % 16; ty = r / 16; }

    int c0 = tx * 32, r0 = ty * 32;
    #pragma unroll
    for (int i = 0; i < 4; i++)
        t[threadIdx.y + i * 8][threadIdx.x] = in[(size_t)(r0 + threadIdx.y + i * 8) * Cc + c0 + threadIdx.x];
    __syncthreads();
    #pragma unroll
    for (int i = 0; i < 4; i++)
        out[(size_t)(c0 + threadIdx.y + i * 8) * R + r0 + threadIdx.x] =
            __float2bfloat16(t[threadIdx.x][threadIdx.y + i * 8]);
}

// ---------------------------------------------------------------------------
// Reductions
// ---------------------------------------------------------------------------
template<int NWARPS>
DEV_INLINE void block_sum2(float& s, float& s2) {
    #pragma unroll
    for (int o = 16; o > 0; o >>= 1) {
        s  += __shfl_down_sync(0xffffffffu, s,  o);
        s2 += __shfl_down_sync(0xffffffffu, s2, o);
    }
    __shared__ float sh_a[NWARPS], sh_b[NWARPS];
    int w = threadIdx.x >> 5;
    if ((threadIdx.x & 31) == 0) { sh_a[w] = s; sh_b[w] = s2; }
    __syncthreads();
    if (threadIdx.x == 0) {
        float a = sh_a[0], b = sh_b[0];
        #pragma unroll
        for (int i = 1; i < NWARPS; i++) { a += sh_a[i]; b += sh_b[i]; }
        sh_a[0] = a; sh_b[0] = b;
    }
    __syncthreads();
    s = sh_a[0]; s2 = sh_b[0];
}

// ---------------------------------------------------------------------------
// Flags / embed / ln / output
// ---------------------------------------------------------------------------
__global__ void k_zeroflags() {
    int i = blockIdx.x * blockDim.x + threadIdx.x;
    if (i < cT) g_mflag[i] = 0;
}
__global__ void k_setflags(const int* __restrict__ mask_idx) {
    int i = blockIdx.x * blockDim.x + threadIdx.x;
    if (i < cB * cK) g_mflag[(i / cK) * cNW + mask_idx[i]] = 1;
}

__global__ void __launch_bounds__(128) k_embed(
    const float* __restrict__ seq, const float* __restrict__ pos_emb,
    const float* __restrict__ mtok,
    const float* __restrict__ p1g, const float* __restrict__ p1b,
    const float* __restrict__ W_emb, const float* __restrict__ b_emb,
    const float* __restrict__ p2g, const float* __restrict__ p2b)
{
    int tok = blockIdx.x;
    int w = tok & (cNW - 1);
    int t = threadIdx.x;
    const float* pos = pos_emb + (size_t)(w + 1) * cD;
    float* out = g_x + (size_t)tok * cD;

    if (g_mflag[tok]) {
        #pragma unroll
        for (int j = 0; j < 4; j++) { int d = t + j * 128; out[d] = mtok[d] + pos[d]; }
        return;
    }
    __shared__ float wsm[32];
    __shared__ float lnw[32];
    const float* wrow = seq + (size_t)tok * 32;
    if (t < 32) wsm[t] = wrow[t];
    __syncthreads();
    float m = 0.f;
    #pragma unroll
    for (int c = 0; c < 32; c++) m += wsm[c];
    m *= (1.f / 32.f);
    float v = 0.f;
    #pragma unroll
    for (int c = 0; c < 32; c++) { float d0 = wsm[c] - m; v += d0 * d0; }
    v *= (1.f / 32.f);
    float rs = rsqrtf(v + 1e-5f);
    if (t < 32) lnw[t] = (wsm[t] - m) * rs * p1g[t] + p1b[t];
    __syncthreads();
    float acc[4];
    #pragma unroll
    for (int j = 0; j < 4; j++) {
        int d = t + j * 128;
        float a = b_emb[d];
        #pragma unroll
        for (int c = 0; c < 32; c++) a += lnw[c] * W_emb[c * cD + d];
        acc[j] = a;
    }
    float s = 0.f, s2 = 0.f;
    #pragma unroll
    for (int j = 0; j < 4; j++) { s += acc[j]; s2 += acc[j] * acc[j]; }
    block_sum2<4>(s, s2);
    float mean = s * (1.f / cD);
    float var  = s2 * (1.f / cD) - mean * mean;
    float rstd = rsqrtf(var + 1e-5f);
    #pragma unroll
    for (int j = 0; j < 4; j++) {
        int d = t + j * 128;
        out[d] = (acc[j] - mean) * rstd * p2g[d] + p2b[d] + pos[d];
    }
}

// Warp-per-row LayerNorm: 8 rows per 256-thread block, shuffle-only reduce.
template<bool OBF>
__global__ void __launch_bounds__(256) k_ln(
    const float* __restrict__ x, const float* __restrict__ g,
    const float* __restrict__ bt, void* __restrict__ y)
{
    int row = blockIdx.x * 8 + (threadIdx.x >> 5);
    int lane = threadIdx.x & 31;
    const float4* xr = (const float4*)(x + (size_t)row * cD);
    float4 a[4];
    #pragma unroll
    for (int i = 0; i < 4; i++) a[i] = xr[lane + i * 32];
    float s = 0.f, s2 = 0.f;
    #pragma unroll
    for (int i = 0; i < 4; i++) {
        s  += a[i].x + a[i].y + a[i].z + a[i].w;
        s2 += a[i].x*a[i].x + a[i].y*a[i].y + a[i].z*a[i].z + a[i].w*a[i].w;
    }
    #pragma unroll
    for (int o = 16; o > 0; o >>= 1) {
        s  += __shfl_xor_sync(0xffffffffu, s,  o);
        s2 += __shfl_xor_sync(0xffffffffu, s2, o);
    }
    float mean = s * (1.f / cD);
    float var  = s2 * (1.f / cD) - mean * mean;
    float rstd = rsqrtf(var + 1e-5f);
    #pragma unroll
    for (int i = 0; i < 4; i++) {
        int c4 = lane + i * 32;
        float4 gg = ((const float4*)g)[c4];
        float4 bb = ((const float4*)bt)[c4];
        float o0 = (a[i].x - mean) * rstd * gg.x + bb.x;
        float o1 = (a[i].y - mean) * rstd * gg.y + bb.y;
        float o2 = (a[i].z - mean) * rstd * gg.z + bb.z;
        float o3 = (a[i].w - mean) * rstd * gg.w + bb.w;
        if (OBF) {
            uint2 u = make_uint2(pk2(o0, o1), pk2(o2, o3));
            *(uint2*)((bf16*)y + (size_t)row * cD + c4 * 4) = u;
        } else {
            ((float4*)((float*)y + (size_t)row * cD))[c4] = make_float4(o0, o1, o2, o3);
        }
    }
}

__global__ void __launch_bounds__(256) k_output(
    const float* __restrict__ seq, const int* __restrict__ mask_idx,
    const float* __restrict__ Ww, const float* __restrict__ bw,
    float* __restrict__ out, long long out_size)
{
    int b = blockIdx.y, k = blockIdx.x;
    int idx = mask_idx[b * cK + k];
    const float* enc = g_h + ((size_t)b * cNW + idx) * cD;
    __shared__ float es[cD];
    __shared__ float lgt[32];
    int t = threadIdx.x;
    ((float2*)es)[t] = ((const float2*)enc)[t];
    __syncthreads();
    int lg = t >> 3, sg = t & 7;
    float part = 0.f;
    #pragma unroll
    for (int c = 0; c < 64; c++) {
        int cc = sg * 64 + c;
        part += es[cc] * Ww[cc * 32 + lg];
    }
    part += __shfl_down_sync(0xffffffffu, part, 4);
    part += __shfl_down_sync(0xffffffffu, part, 2);
    part += __shfl_down_sync(0xffffffffu, part, 1);
    if (sg == 0) lgt[lg] = part + bw[lg];
    __syncthreads();
    size_t base = (size_t)b * cK + k;
    if (t < 8) {
        float l0 = lgt[t*4+0], l1 = lgt[t*4+1], l2 = lgt[t*4+2], l3 = lgt[t*4+3];
        float mx = fmaxf(fmaxf(l0, l1), fmaxf(l2, l3));
        float e0 = expf(l0 - mx), e1 = expf(l1 - mx), e2 = expf(l2 - mx), e3 = expf(l3 - mx);
        float inv = 1.f / (e0 + e1 + e2 + e3);
        size_t off = base * 32 + t * 4;
        if ((long long)(off + 3) < out_size) {
            out[off+0] = e0*inv; out[off+1] = e1*inv; out[off+2] = e2*inv; out[off+3] = e3*inv;
        }
    }
    if (t < 32) {
        size_t off = (size_t)cB * cK * 32 + base * 32 + t;
        if ((long long)off < out_size)
            out[off] = seq[((size_t)b * cNW + idx) * 32 + t];
    }
}

// ---------------------------------------------------------------------------
// Launch
// ---------------------------------------------------------------------------
extern "C" void kernel_launch(void* const* d_in, const int* in_sizes, int n_in,
                              void* d_out, int out_size)
{
    const float* seq      = (const float*)d_in[0];
    const int*   mask_idx = (const int*)  d_in[1];
    const float* pos_emb  = (const float*)d_in[2];
    const float* mtok     = (const float*)d_in[3];
    const float* p1g      = (const float*)d_in[4];
    const float* p1b      = (const float*)d_in[5];
    const float* W_emb    = (const float*)d_in[6];
    const float* b_emb    = (const float*)d_in[7];
    const float* p2g      = (const float*)d_in[8];
    const float* p2b      = (const float*)d_in[9];
    const float* alng     = (const float*)d_in[10];
    const float* alnb     = (const float*)d_in[11];
    const float* Wqkv     = (const float*)d_in[12];
    const float* Wo       = (const float*)d_in[13];
    const float* flng     = (const float*)d_in[14];
    const float* flnb     = (const float*)d_in[15];
    const float* W1       = (const float*)d_in[16];
    const float* b1       = (const float*)d_in[17];
    const float* W2       = (const float*)d_in[18];
    const float* b2       = (const float*)d_in[19];
    const float* olng     = (const float*)d_in[20];
    const float* olnb     = (const float*)d_in[21];
    const float* Ww       = (const float*)d_in[22];
    const float* bw       = (const float*)d_in[23];
    float* out = (float*)d_out;
    (void)in_sizes; (void)n_in;

    float *px, *ph;
    bf16 *phh, *pqkvh, *paoh, *pffh, *pwTh;
    cudaGetSymbolAddress((void**)&px,    g_x);
    cudaGetSymbolAddress((void**)&ph,    g_h);
    cudaGetSymbolAddress((void**)&phh,   g_hh);
    cudaGetSymbolAddress((void**)&pqkvh, g_qkvh);
    cudaGetSymbolAddress((void**)&paoh,  g_aoh);
    cudaGetSymbolAddress((void**)&pffh,  g_ffh);
    cudaGetSymbolAddress((void**)&pwTh,  g_wTh);

    const int GSM = 3 * (128 * 36 + 128 * 36) * 4;    // 110592
    const int FSM = (4608 + 2 * 2304 + 2 * 2304) * 4; // 55296
    cudaFuncSetAttribute(k_tgemm<false,false,false,true >, cudaFuncAttributeMaxDynamicSharedMemorySize, GSM);
    cudaFuncSetAttribute(k_tgemm<false,true, false,false>, cudaFuncAttributeMaxDynamicSharedMemorySize, GSM);
    cudaFuncSetAttribute(k_tgemm<true, false,true, true >, cudaFuncAttributeMaxDynamicSharedMemorySize, GSM);
    cudaFuncSetAttribute(k_tgemm<true, true, false,false>, cudaFuncAttributeMaxDynamicSharedMemorySize, GSM);
    cudaFuncSetAttribute(k_flash, cudaFuncAttributeMaxDynamicSharedMemorySize, FSM);

    k_zeroflags<<<cT / 256, 256>>>();
    k_setflags<<<(cB * cK) / 256, 256>>>(mask_idx);
    k_embed<<<cT, 128>>>(seq, pos_emb, mtok, p1g, p1b, W_emb, b_emb, p2g, p2b);

    // all weight transposes (fp32 -> bf16 [N][K]) in ONE launch
    k_wtall<<<3072 * cL, dim3(32, 8)>>>(Wqkv, Wo, W1, W2, pwTh);

    for (int l = 0; l < cL; l++) {
        bf16* baseT = pwTh + (size_t)l * 3145728;
        bf16* WqkvT = baseT;
        bf16* WoT   = baseT + 786432;
        bf16* W1T   = baseT + 1048576;
        bf16* W2T   = baseT + 2097152;

        // attention
        k_ln<true><<<cT / 8, 256>>>(px, alng + l*cD, alnb + l*cD, phh);
        k_tgemm<false,false,false,true><<<dim3(12, 64), 256, GSM>>>(
            phh, WqkvT, nullptr, nullptr, pqkvh, 512, 512, 512, 1536);
        k_flash<<<dim3(8, 64), 256, FSM>>>(pqkvh, paoh);
        k_tgemm<false,true,false,false><<<dim3(4, 64), 256, GSM>>>(
            paoh, WoT, nullptr, px, px, 512, 512, 512, 512);

        // ffn
        k_ln<true><<<cT / 8, 256>>>(px, flng + l*cD, flnb + l*cD, phh);
        k_tgemm<true,false,true,true><<<dim3(16, 64), 256, GSM>>>(
            phh, W1T, b1 + (size_t)l*cFF, nullptr, pffh, 512, 512, 512, 2048);
        k_tgemm<true,true,false,false><<<dim3(4, 64), 256, GSM>>>(
            pffh, W2T, b2 + (size_t)l*cD, px, px, 2048, 2048, 2048, 512);
    }

    k_ln<false><<<cT / 8, 256>>>(px, olng, olnb, ph);
    k_output<<<dim3(cK, cB), 256>>>(seq, mask_idx, Ww, bw, out, (long long)out_size);
}